// round 12
// baseline (speedup 1.0000x reference)
#include <cuda_runtime.h>
#include <cuda_bf16.h>
#include <math.h>
#include <stdint.h>

#define B_ROWS 4096
#define D_INF  192
#define D_HID  512
#define D_OUTF 128
#define M2     8192      // 2*B
#define INV_T  2.0f      // 1/TEMPERATURE
#define BN_EPS 1e-5f
#define L2_EPS 1e-12f
// zh = z * sqrt(2*log2(e)): zh_i.zh_j = 2*log2e*(z_i.z_j); exp((z.z)/T) = exp2(zh.zh)
#define ZH_SCALE 1.69864361f

// ---------------- scratch (static device globals; no allocation) ------------
__device__ __align__(128) float g_Y[(size_t)M2 * D_HID];     // 16 MB
__device__ __align__(128) float g_Z[(size_t)M2 * D_OUTF];    // fallback only
__device__ __align__(128) __nv_bfloat16 g_Zh[(size_t)M2 * D_OUTF]; // scaled bf16 z
__device__ float g_colsum[2][D_HID];
__device__ float g_colsq[2][D_HID];
__device__ float g_sumexp[M2];
__device__ float g_loss[1];
__device__ unsigned g_done;

// ---------------- helpers ----------------------------------------------------
__device__ __forceinline__ uint32_t smem_u32(const void* p) {
    uint32_t a;
    asm("{ .reg .u64 t; cvta.to.shared.u64 t, %1; cvt.u32.u64 %0, t; }" : "=r"(a) : "l"(p));
    return a;
}
__device__ __forceinline__ void ldsm4(uint32_t* r, uint32_t addr) {
    asm volatile("ldmatrix.sync.aligned.m8n8.x4.shared.b16 {%0,%1,%2,%3}, [%4];"
                 : "=r"(r[0]), "=r"(r[1]), "=r"(r[2]), "=r"(r[3]) : "r"(addr));
}
__device__ __forceinline__ void mma16816(float* c, const uint32_t* a, const uint32_t* b) {
    asm volatile(
        "mma.sync.aligned.m16n8k16.row.col.f32.bf16.bf16.f32 "
        "{%0,%1,%2,%3}, {%4,%5,%6,%7}, {%8,%9}, {%0,%1,%2,%3};"
        : "+f"(c[0]), "+f"(c[1]), "+f"(c[2]), "+f"(c[3])
        : "r"(a[0]), "r"(a[1]), "r"(a[2]), "r"(a[3]), "r"(b[0]), "r"(b[1]));
}
__device__ __forceinline__ float ex2(float x) {
    float y;
    asm("ex2.approx.f32 %0, %1;" : "=f"(y) : "f"(x));
    return y;
}
__device__ __forceinline__ void cpa16(uint32_t saddr, const void* gaddr) {
    asm volatile("cp.async.cg.shared.global [%0], [%1], 16;"
                 :: "r"(saddr), "l"(gaddr) : "memory");
}
__device__ __forceinline__ void cpa_wait_all() {
    asm volatile("cp.async.commit_group;\n\tcp.async.wait_group 0;" ::: "memory");
}
// split fp32 pair into bf16x2 hi + bf16x2 lo (x = hi + lo, err ~2^-18)
__device__ __forceinline__ void split2(float f0, float f1, uint32_t& hi, uint32_t& lo) {
    __nv_bfloat162 h = __floats2bfloat162_rn(f0, f1);
    __nv_bfloat162 l = __floats2bfloat162_rn(f0 - __bfloat162float(h.x),
                                             f1 - __bfloat162float(h.y));
    hi = *reinterpret_cast<uint32_t*>(&h);
    lo = *reinterpret_cast<uint32_t*>(&l);
}

// smem tile geometry for GEMMs (pitch 36 words = 72 bf16 = 144 bytes)
#define PW   36
#define SAW  (64 * PW)    // A tile: 64 rows
#define SBW  (128 * PW)   // B tile: 128 rows
#define GSM1_BYTES (((2 * SAW + 2 * SBW) * 4) + 1024)            // 56320
#define GSM2_BYTES (((2 * SAW + 2 * SBW) * 4) + 4096 + 1280)     // 60672

// ---------------- init: zero accumulators ------------------------------------
__global__ void k_init() {
    int i = blockIdx.x * blockDim.x + threadIdx.x;
    if (i < M2) g_sumexp[i] = 0.f;
    if (i < 2 * D_HID) {
        g_colsum[i >> 9][i & 511] = 0.f;
        g_colsq [i >> 9][i & 511] = 0.f;
    }
    if (i == 0) { g_loss[0] = 0.f; g_done = 0u; }
}

// ---------------- GEMM1 (tensor, split-bf16): Y = H @ W1^T + b1 + BN partials
// BM=64, BN=128, K=192 in 3 chunks of 64. A and B staged from fp32 with
// in-register split (no pre-split pass).
__global__ __launch_bounds__(256) void k_gemm1t(const float* __restrict__ h1,
                                                const float* __restrict__ h2,
                                                const float* __restrict__ W1,
                                                const float* __restrict__ b1) {
    extern __shared__ __align__(16) uint32_t sw[];
    uint32_t* sAhi = sw;
    uint32_t* sAlo = sw + SAW;
    uint32_t* sBhi = sw + 2 * SAW;
    uint32_t* sBlo = sw + 2 * SAW + SBW;
    float* colS = (float*)(sw + 2 * SAW + 2 * SBW);
    float* colQ = colS + 128;

    const int t = threadIdx.x;
    const int wid = t >> 5, lane = t & 31;
    const int gr = lane >> 2, qq = lane & 3;
    const int sel = lane >> 3, li = lane & 7;
    const int warp_m = wid >> 2, warp_n = wid & 3;
    const int n0 = blockIdx.x * 128;
    const int m0 = blockIdx.y * 64;
    const int half = (m0 >= B_ROWS);
    const float* H = half ? (h2 + (size_t)(m0 - B_ROWS) * D_INF)
                          : (h1 + (size_t)m0 * D_INF);

    if (t < 128) { colS[t] = 0.f; colQ[t] = 0.f; }

    float acc[2][4][4];
#pragma unroll
    for (int mi = 0; mi < 2; mi++)
#pragma unroll
        for (int ni = 0; ni < 4; ni++)
#pragma unroll
            for (int r = 0; r < 4; r++) acc[mi][ni][r] = 0.f;

    const int arow = t >> 2, acq = (t & 3) * 16;    // 16 floats/thread
    const int brow = t >> 1, bcq = (t & 1) * 32;    // 32 floats/thread
    const float* pA = H  + (size_t)arow * D_INF + acq;
    const float* pB = W1 + (size_t)(n0 + brow) * D_INF + bcq;
    const int aw = arow * PW + (acq >> 1);
    const int bw = brow * PW + (bcq >> 1);

    const uint32_t sAhiU = smem_u32(sAhi), sAloU = smem_u32(sAlo);
    const uint32_t sBhiU = smem_u32(sBhi), sBloU = smem_u32(sBlo);
    uint32_t aoff[2], boff[2];
#pragma unroll
    for (int mi = 0; mi < 2; mi++)
        aoff[mi] = (uint32_t)(warp_m * 32 + mi * 16 + (sel & 1) * 8 + li) * 144u
                 + (uint32_t)(sel >> 1) * 16u;
#pragma unroll
    for (int nip = 0; nip < 2; nip++)
        boff[nip] = (uint32_t)(warp_n * 32 + nip * 16 + (sel >> 1) * 8 + li) * 144u
                  + (uint32_t)(sel & 1) * 16u;

    for (int kb = 0; kb < D_INF; kb += 64) {
        {
#pragma unroll
            for (int j = 0; j < 4; j++) {
                float4 v = *(const float4*)(pA + kb + j * 4);
                uint32_t h0, l0, h1v, l1;
                split2(v.x, v.y, h0, l0);
                split2(v.z, v.w, h1v, l1);
                uint2 hh = {h0, h1v}, ll = {l0, l1};
                *(uint2*)(sAhi + aw + j * 2) = hh;
                *(uint2*)(sAlo + aw + j * 2) = ll;
            }
#pragma unroll
            for (int j = 0; j < 8; j++) {
                float4 v = *(const float4*)(pB + kb + j * 4);
                uint32_t h0, l0, h1v, l1;
                split2(v.x, v.y, h0, l0);
                split2(v.z, v.w, h1v, l1);
                uint2 hh = {h0, h1v}, ll = {l0, l1};
                *(uint2*)(sBhi + bw + j * 2) = hh;
                *(uint2*)(sBlo + bw + j * 2) = ll;
            }
        }
        __syncthreads();
#pragma unroll
        for (int ks = 0; ks < 4; ks++) {
            uint32_t koff = (uint32_t)ks * 32u;
            uint32_t ah[2][4], al[2][4], bh[4][2], bl[4][2], tmp[4];
            ldsm4(ah[0], sAhiU + aoff[0] + koff);
            ldsm4(ah[1], sAhiU + aoff[1] + koff);
            ldsm4(al[0], sAloU + aoff[0] + koff);
            ldsm4(al[1], sAloU + aoff[1] + koff);
            ldsm4(tmp, sBhiU + boff[0] + koff);
            bh[0][0]=tmp[0]; bh[0][1]=tmp[1]; bh[1][0]=tmp[2]; bh[1][1]=tmp[3];
            ldsm4(tmp, sBhiU + boff[1] + koff);
            bh[2][0]=tmp[0]; bh[2][1]=tmp[1]; bh[3][0]=tmp[2]; bh[3][1]=tmp[3];
            ldsm4(tmp, sBloU + boff[0] + koff);
            bl[0][0]=tmp[0]; bl[0][1]=tmp[1]; bl[1][0]=tmp[2]; bl[1][1]=tmp[3];
            ldsm4(tmp, sBloU + boff[1] + koff);
            bl[2][0]=tmp[0]; bl[2][1]=tmp[1]; bl[3][0]=tmp[2]; bl[3][1]=tmp[3];
#pragma unroll
            for (int mi = 0; mi < 2; mi++)
#pragma unroll
                for (int ni = 0; ni < 4; ni++) {
                    mma16816(acc[mi][ni], ah[mi], bh[ni]);
                    mma16816(acc[mi][ni], ah[mi], bl[ni]);
                    mma16816(acc[mi][ni], al[mi], bh[ni]);
                }
        }
        __syncthreads();
    }

    float ps[4][2], pq[4][2];
#pragma unroll
    for (int ni = 0; ni < 4; ni++) { ps[ni][0]=ps[ni][1]=pq[ni][0]=pq[ni][1]=0.f; }
#pragma unroll
    for (int ni = 0; ni < 4; ni++) {
        int col = warp_n * 32 + ni * 8 + qq * 2;
        float2 bb = *(const float2*)&b1[n0 + col];
#pragma unroll
        for (int mi = 0; mi < 2; mi++) {
            int r = warp_m * 32 + mi * 16 + gr;
            float y0 = acc[mi][ni][0] + bb.x;
            float y1 = acc[mi][ni][1] + bb.y;
            float y2 = acc[mi][ni][2] + bb.x;
            float y3 = acc[mi][ni][3] + bb.y;
            float2 p0 = {y0, y1}, p1 = {y2, y3};
            *(float2*)&g_Y[(size_t)(m0 + r)     * D_HID + n0 + col] = p0;
            *(float2*)&g_Y[(size_t)(m0 + r + 8) * D_HID + n0 + col] = p1;
            ps[ni][0] += y0 + y2;              ps[ni][1] += y1 + y3;
            pq[ni][0] += y0 * y0 + y2 * y2;    pq[ni][1] += y1 * y1 + y3 * y3;
        }
    }
#pragma unroll
    for (int ni = 0; ni < 4; ni++)
#pragma unroll
        for (int c2 = 0; c2 < 2; c2++) {
            float s = ps[ni][c2], q = pq[ni][c2];
            s += __shfl_xor_sync(~0u, s, 4);  q += __shfl_xor_sync(~0u, q, 4);
            s += __shfl_xor_sync(~0u, s, 8);  q += __shfl_xor_sync(~0u, q, 8);
            s += __shfl_xor_sync(~0u, s, 16); q += __shfl_xor_sync(~0u, q, 16);
            ps[ni][c2] = s; pq[ni][c2] = q;
        }
    if (gr == 0) {
#pragma unroll
        for (int ni = 0; ni < 4; ni++) {
            int col = warp_n * 32 + ni * 8 + qq * 2;
            atomicAdd(&colS[col],     ps[ni][0]);
            atomicAdd(&colS[col + 1], ps[ni][1]);
            atomicAdd(&colQ[col],     pq[ni][0]);
            atomicAdd(&colQ[col + 1], pq[ni][1]);
        }
    }
    __syncthreads();
    if (t < 128) {
        atomicAdd(&g_colsum[half][n0 + t], colS[t]);
        atomicAdd(&g_colsq [half][n0 + t], colQ[t]);
    }
}

// ---------------- GEMM2 (tensor, split-bf16): Z = relu(BN(Y)) @ W2^T + b2 ----
// BM=64, BN=128, K=512 in 8 chunks of 64. BN finalize folded into prologue.
// z written straight into out+1 (scalar fp32 stores; out+1 is 4B-aligned only)
// and g_Zh (scaled bf16).
__global__ __launch_bounds__(256) void k_gemm2t(const float* __restrict__ W2,
                                                const float* __restrict__ b2,
                                                const float* __restrict__ gamma,
                                                const float* __restrict__ beta,
                                                float* __restrict__ out,
                                                int out_size) {
    extern __shared__ __align__(16) uint32_t sw[];
    uint32_t* sAhi = sw;
    uint32_t* sAlo = sw + SAW;
    uint32_t* sBhi = sw + 2 * SAW;
    uint32_t* sBlo = sw + 2 * SAW + SBW;
    float* ssc  = (float*)(sw + 2 * SAW + 2 * SBW);
    float* ssh  = ssc + D_HID;
    float* red  = ssh + D_HID;    // [64][4]
    float* sInv = red + 256;      // [64]

    const int t = threadIdx.x;
    const int wid = t >> 5, lane = t & 31;
    const int gr = lane >> 2, qq = lane & 3;
    const int sel = lane >> 3, li = lane & 7;
    const int warp_m = wid >> 2, warp_n = wid & 3;
    const int m0 = blockIdx.x * 64;
    const int half = (m0 >= B_ROWS);

    for (int c = t; c < D_HID; c += 256) {
        float mean = g_colsum[half][c] * (1.f / B_ROWS);
        float var  = g_colsq [half][c] * (1.f / B_ROWS) - mean * mean;
        float scv  = gamma[c] * rsqrtf(var + BN_EPS);
        ssc[c] = scv;
        ssh[c] = beta[c] - mean * scv;
    }
    __syncthreads();

    float acc[2][4][4];
#pragma unroll
    for (int mi = 0; mi < 2; mi++)
#pragma unroll
        for (int ni = 0; ni < 4; ni++)
#pragma unroll
            for (int r = 0; r < 4; r++) acc[mi][ni][r] = 0.f;

    const int arow = t >> 2, acq = (t & 3) * 16;
    const int brow = t >> 1, bcq = (t & 1) * 32;
    const float* pA = g_Y + (size_t)(m0 + arow) * D_HID + acq;
    const float* pB = W2 + (size_t)brow * D_HID + bcq;
    const int aw = arow * PW + (acq >> 1);
    const int bw = brow * PW + (bcq >> 1);

    const uint32_t sAhiU = smem_u32(sAhi), sAloU = smem_u32(sAlo);
    const uint32_t sBhiU = smem_u32(sBhi), sBloU = smem_u32(sBlo);
    uint32_t aoff[2], boff[2];
#pragma unroll
    for (int mi = 0; mi < 2; mi++)
        aoff[mi] = (uint32_t)(warp_m * 32 + mi * 16 + (sel & 1) * 8 + li) * 144u
                 + (uint32_t)(sel >> 1) * 16u;
#pragma unroll
    for (int nip = 0; nip < 2; nip++)
        boff[nip] = (uint32_t)(warp_n * 32 + nip * 16 + (sel >> 1) * 8 + li) * 144u
                  + (uint32_t)(sel & 1) * 16u;

    for (int kb = 0; kb < D_HID; kb += 64) {
        {
#pragma unroll
            for (int j = 0; j < 4; j++) {
                float4 v = *(const float4*)(pA + kb + j * 4);
                int k = kb + acq + j * 4;
                float f0 = fmaxf(fmaf(v.x, ssc[k],     ssh[k]),     0.f);
                float f1 = fmaxf(fmaf(v.y, ssc[k + 1], ssh[k + 1]), 0.f);
                float f2 = fmaxf(fmaf(v.z, ssc[k + 2], ssh[k + 2]), 0.f);
                float f3 = fmaxf(fmaf(v.w, ssc[k + 3], ssh[k + 3]), 0.f);
                uint32_t h0, l0, h1v, l1;
                split2(f0, f1, h0, l0);
                split2(f2, f3, h1v, l1);
                uint2 hh = {h0, h1v}, ll = {l0, l1};
                *(uint2*)(sAhi + aw + j * 2) = hh;
                *(uint2*)(sAlo + aw + j * 2) = ll;
            }
#pragma unroll
            for (int j = 0; j < 8; j++) {
                float4 v = *(const float4*)(pB + kb + j * 4);
                uint32_t h0, l0, h1v, l1;
                split2(v.x, v.y, h0, l0);
                split2(v.z, v.w, h1v, l1);
                uint2 hh = {h0, h1v}, ll = {l0, l1};
                *(uint2*)(sBhi + bw + j * 2) = hh;
                *(uint2*)(sBlo + bw + j * 2) = ll;
            }
        }
        __syncthreads();
#pragma unroll
        for (int ks = 0; ks < 4; ks++) {
            uint32_t koff = (uint32_t)ks * 32u;
            uint32_t ah[2][4], al[2][4], bh[4][2], bl[4][2], tmp[4];
            ldsm4(ah[0], sAhiU + aoff[0] + koff);
            ldsm4(ah[1], sAhiU + aoff[1] + koff);
            ldsm4(al[0], sAloU + aoff[0] + koff);
            ldsm4(al[1], sAloU + aoff[1] + koff);
            ldsm4(tmp, sBhiU + boff[0] + koff);
            bh[0][0]=tmp[0]; bh[0][1]=tmp[1]; bh[1][0]=tmp[2]; bh[1][1]=tmp[3];
            ldsm4(tmp, sBhiU + boff[1] + koff);
            bh[2][0]=tmp[0]; bh[2][1]=tmp[1]; bh[3][0]=tmp[2]; bh[3][1]=tmp[3];
            ldsm4(tmp, sBloU + boff[0] + koff);
            bl[0][0]=tmp[0]; bl[0][1]=tmp[1]; bl[1][0]=tmp[2]; bl[1][1]=tmp[3];
            ldsm4(tmp, sBloU + boff[1] + koff);
            bl[2][0]=tmp[0]; bl[2][1]=tmp[1]; bl[3][0]=tmp[2]; bl[3][1]=tmp[3];
#pragma unroll
            for (int mi = 0; mi < 2; mi++)
#pragma unroll
                for (int ni = 0; ni < 4; ni++) {
                    mma16816(acc[mi][ni], ah[mi], bh[ni]);
                    mma16816(acc[mi][ni], ah[mi], bl[ni]);
                    mma16816(acc[mi][ni], al[mi], bh[ni]);
                }
        }
        __syncthreads();
    }

    float rp[2][2] = {{0.f, 0.f}, {0.f, 0.f}};
#pragma unroll
    for (int ni = 0; ni < 4; ni++) {
        int col = warp_n * 32 + ni * 8 + qq * 2;
        float2 bb = *(const float2*)&b2[col];
#pragma unroll
        for (int mi = 0; mi < 2; mi++) {
            acc[mi][ni][0] += bb.x; acc[mi][ni][1] += bb.y;
            acc[mi][ni][2] += bb.x; acc[mi][ni][3] += bb.y;
            rp[mi][0] = fmaf(acc[mi][ni][0], acc[mi][ni][0],
                        fmaf(acc[mi][ni][1], acc[mi][ni][1], rp[mi][0]));
            rp[mi][1] = fmaf(acc[mi][ni][2], acc[mi][ni][2],
                        fmaf(acc[mi][ni][3], acc[mi][ni][3], rp[mi][1]));
        }
    }
#pragma unroll
    for (int mi = 0; mi < 2; mi++)
#pragma unroll
        for (int rh = 0; rh < 2; rh++) {
            float s = rp[mi][rh];
            s += __shfl_xor_sync(~0u, s, 1);
            s += __shfl_xor_sync(~0u, s, 2);
            rp[mi][rh] = s;
        }
    if (qq == 0) {
#pragma unroll
        for (int mi = 0; mi < 2; mi++) {
            red[(warp_m * 32 + mi * 16 + gr)     * 4 + warp_n] = rp[mi][0];
            red[(warp_m * 32 + mi * 16 + gr + 8) * 4 + warp_n] = rp[mi][1];
        }
    }
    __syncthreads();
    if (t < 64) {
        float s = red[t * 4] + red[t * 4 + 1] + red[t * 4 + 2] + red[t * 4 + 3];
        sInv[t] = 1.f / fmaxf(sqrtf(s), L2_EPS);
    }
    __syncthreads();
    bool full = (out_size > M2 * D_OUTF);
#pragma unroll
    for (int mi = 0; mi < 2; mi++)
#pragma unroll
        for (int rh = 0; rh < 2; rh++) {
            int r = warp_m * 32 + mi * 16 + gr + rh * 8;
            float inv = sInv[r];
            int m = m0 + r;
#pragma unroll
            for (int ni = 0; ni < 4; ni++) {
                int col = warp_n * 32 + ni * 8 + qq * 2;
                float z0 = acc[mi][ni][rh * 2]     * inv;
                float z1 = acc[mi][ni][rh * 2 + 1] * inv;
                if (full) {
                    // out+1 is only 4B-aligned: scalar stores
                    out[1 + (size_t)m * D_OUTF + col]     = z0;
                    out[1 + (size_t)m * D_OUTF + col + 1] = z1;
                } else {
                    float2 zz = {z0, z1};
                    *(float2*)&g_Z[(size_t)m * D_OUTF + col] = zz;
                }
                *(__nv_bfloat162*)&g_Zh[(size_t)m * D_OUTF + col] =
                    __floats2bfloat162_rn(z0 * ZH_SCALE, z1 * ZH_SCALE);
            }
        }
}

// ---------------- paired tensor-core sim: 128x256 tile per CTA --------------
#define SIM_PITCH_B 272                        // 128 cols bf16 + 16B pad
#define SIM_TILE_BYTES (128 * SIM_PITCH_B)     // 34816
#define SIM_SMEM_SIZE (3 * SIM_TILE_BYTES + 3 * 128 * 4)

__device__ __forceinline__ int pair_off(int bi) {
    int h = bi >> 1, r = bi & 1;
    return 32 * bi - h * (h - 1 + r);
}

__global__ __launch_bounds__(256, 2) void k_simp() {
    extern __shared__ __align__(16) char smem[];
    char* sA  = smem;
    char* sB0 = smem + SIM_TILE_BYTES;
    char* sB1 = smem + 2 * SIM_TILE_BYTES;
    float* srow  = (float*)(smem + 3 * SIM_TILE_BYTES);
    float* scol0 = srow + 128;
    float* scol1 = srow + 256;

    const int t = threadIdx.x;
    const int wid = t >> 5, lane = t & 31;
    const int gr = lane >> 2, qq = lane & 3;
    const int sel = lane >> 3, li = lane & 7;
    const int warp_m = wid >> 2, warp_n = wid & 3;

    int tb = blockIdx.x;
    float disc = fmaxf(4096.f - 4.f * (float)tb, 0.f);
    int bi = (int)(64.f - sqrtf(disc));
    if (bi < 0) bi = 0; if (bi > 63) bi = 63;
    while (bi < 63 && pair_off(bi + 1) <= tb) ++bi;
    while (bi > 0 && pair_off(bi) > tb) --bi;
    int c = (bi >> 1) + (tb - pair_off(bi));
    const size_t i0  = (size_t)bi * 128;
    const int bj0 = 2 * c, bj1 = 2 * c + 1;
    const size_t j00 = (size_t)bj0 * 128;
    const size_t j01 = (size_t)bj1 * 128;
    const bool sub0  = (bj0 >= bi);
    const bool col0  = (bj0 > bi);
    const bool col1  = (bj1 > bi);

    const uint32_t sAu  = smem_u32(sA);
    const uint32_t sB0u = smem_u32(sB0);
    const uint32_t sB1u = smem_u32(sB1);
    const char* gA  = (const char*)(g_Zh + i0  * D_OUTF);
    const char* gB0 = (const char*)(g_Zh + j00 * D_OUTF);
    const char* gB1 = (const char*)(g_Zh + j01 * D_OUTF);
#pragma unroll
    for (int it = 0; it < 8; it++) {
        int q = t + it * 256;
        uint32_t so = (uint32_t)(q >> 4) * SIM_PITCH_B + (uint32_t)(q & 15) * 16u;
        cpa16(sAu + so,  gA  + q * 16);
        cpa16(sB0u + so, gB0 + q * 16);
        cpa16(sB1u + so, gB1 + q * 16);
    }
    if (t < 128) { srow[t] = 0.f; scol0[t] = 0.f; scol1[t] = 0.f; }
    cpa_wait_all();
    __syncthreads();

    uint32_t aBase[4], bB0[2], bB1[2];
#pragma unroll
    for (int mi = 0; mi < 4; mi++)
        aBase[mi] = sAu + (uint32_t)(warp_m * 64 + mi * 16 + (sel & 1) * 8 + li) * SIM_PITCH_B
                  + (uint32_t)(sel >> 1) * 16u;
#pragma unroll
    for (int nip = 0; nip < 2; nip++) {
        uint32_t ro = (uint32_t)(warp_n * 32 + nip * 16 + (sel >> 1) * 8 + li) * SIM_PITCH_B
                    + (uint32_t)(sel & 1) * 16u;
        bB0[nip] = sB0u + ro;
        bB1[nip] = sB1u + ro;
    }

    float rsum[8];
#pragma unroll
    for (int i = 0; i < 8; i++) rsum[i] = 0.f;

    for (int sub = 0; sub < 2; sub++) {
        if (sub == 0 && !sub0) continue;
        const uint32_t* bBase = sub ? bB1 : bB0;
        const bool colAdd = sub ? col1 : col0;
        float* scol = sub ? scol1 : scol0;

        float cc[4][4][4];
#pragma unroll
        for (int mi = 0; mi < 4; mi++)
#pragma unroll
            for (int ni = 0; ni < 4; ni++)
#pragma unroll
                for (int r = 0; r < 4; r++) cc[mi][ni][r] = 0.f;

#pragma unroll
        for (int ks = 0; ks < 8; ks++) {
            uint32_t koff = (uint32_t)ks * 32u;
            uint32_t a[4][4], b[4][2], tmp[4];
#pragma unroll
            for (int mi = 0; mi < 4; mi++) ldsm4(a[mi], aBase[mi] + koff);
            ldsm4(tmp, bBase[0] + koff);
            b[0][0]=tmp[0]; b[0][1]=tmp[1]; b[1][0]=tmp[2]; b[1][1]=tmp[3];
            ldsm4(tmp, bBase[1] + koff);
            b[2][0]=tmp[0]; b[2][1]=tmp[1]; b[3][0]=tmp[2]; b[3][1]=tmp[3];
#pragma unroll
            for (int mi = 0; mi < 4; mi++)
#pragma unroll
                for (int ni = 0; ni < 4; ni++)
                    mma16816(cc[mi][ni], a[mi], b[ni]);
        }

        float csum[8];
#pragma unroll
        for (int i = 0; i < 8; i++) csum[i] = 0.f;
#pragma unroll
        for (int mi = 0; mi < 4; mi++)
#pragma unroll
            for (int ni = 0; ni < 4; ni++) {
                float e0 = ex2(cc[mi][ni][0]);
                float e1 = ex2(cc[mi][ni][1]);
                float e2 = ex2(cc[mi][ni][2]);
                float e3 = ex2(cc[mi][ni][3]);
                rsum[mi * 2 + 0] += e0 + e1;
                rsum[mi * 2 + 1] += e2 + e3;
                csum[ni * 2 + 0] += e0 + e2;
                csum[ni * 2 + 1] += e1 + e3;
            }
        if (colAdd) {
#pragma unroll
            for (int i = 0; i < 8; i++) {
                csum[i] += __shfl_xor_sync(0xffffffffu, csum[i], 4);
                csum[i] += __shfl_xor_sync(0xffffffffu, csum[i], 8);
                csum[i] += __shfl_xor_sync(0xffffffffu, csum[i], 16);
            }
            if (gr == 0) {
#pragma unroll
                for (int ni = 0; ni < 4; ni++) {
                    atomicAdd(&scol[warp_n * 32 + ni * 8 + qq * 2],     csum[ni * 2 + 0]);
                    atomicAdd(&scol[warp_n * 32 + ni * 8 + qq * 2 + 1], csum[ni * 2 + 1]);
                }
            }
        }
    }

#pragma unroll
    for (int i = 0; i < 8; i++) {
        rsum[i] += __shfl_xor_sync(0xffffffffu, rsum[i], 1);
        rsum[i] += __shfl_xor_sync(0xffffffffu, rsum[i], 2);
    }
    if (qq == 0) {
#pragma unroll
        for (int mi = 0; mi < 4; mi++) {
            atomicAdd(&srow[warp_m * 64 + mi * 16 + gr],     rsum[mi * 2 + 0]);
            atomicAdd(&srow[warp_m * 64 + mi * 16 + gr + 8], rsum[mi * 2 + 1]);
        }
    }
    __syncthreads();
    if (t < 128) {
        atomicAdd(&g_sumexp[i0 + t], srow[t]);
        if (col0) atomicAdd(&g_sumexp[j00 + t], scol0[t]);
        if (col1) atomicAdd(&g_sumexp[j01 + t], scol1[t]);
    }
}

// ---------------- finish: loss = mean(lse_i - pos_i); emits out[0] ----------
__global__ void k_finish(float* __restrict__ out, int out_size) {
    int w    = (blockIdx.x * blockDim.x + threadIdx.x) >> 5;
    int lane = threadIdx.x & 31;
    if (w >= B_ROWS) return;
    bool full = (out_size > M2 * D_OUTF);
    const float* zsrc = full ? (out + 1) : g_Z;
    // zsrc may be only 4B-aligned (out+1): scalar loads
    const float* p1 = zsrc + (size_t)w * D_OUTF + lane * 4;
    const float* p2 = zsrc + (size_t)(w + B_ROWS) * D_OUTF + lane * 4;
    float dp = 0.f;
#pragma unroll
    for (int j = 0; j < 4; j++) dp = fmaf(p1[j], p2[j], dp);
    const __nv_bfloat16* z1 = g_Zh + (size_t)w * D_OUTF + lane * 4;
    const __nv_bfloat16* z2 = g_Zh + (size_t)(w + B_ROWS) * D_OUTF + lane * 4;
    float d1 = 0.f, d2 = 0.f;
#pragma unroll
    for (int j = 0; j < 4; j++) {
        float v1 = __bfloat162float(z1[j]);
        float v2 = __bfloat162float(z2[j]);
        d1 = fmaf(v1, v1, d1);
        d2 = fmaf(v2, v2, d2);
    }
#pragma unroll
    for (int o = 16; o; o >>= 1) {
        dp += __shfl_down_sync(0xffffffffu, dp, o);
        d1 += __shfl_down_sync(0xffffffffu, d1, o);
        d2 += __shfl_down_sync(0xffffffffu, d2, o);
    }
    if (lane == 0) {
        float pos  = dp * INV_T;
        float lse1 = logf(g_sumexp[w]          - ex2(d1));
        float lse2 = logf(g_sumexp[w + B_ROWS] - ex2(d2));
        atomicAdd(&g_loss[0], (lse1 + lse2 - 2.f * pos) * (1.f / M2));
        __threadfence();
        unsigned prev = atomicAdd(&g_done, 1u);
        if (prev == B_ROWS - 1) {
            if (out_size > 0) out[0] = g_loss[0];
            g_done = 0u;   // reset for next graph replay
        }
    }
}

// ---------------- launch -----------------------------------------------------
extern "C" void kernel_launch(void* const* d_in, const int* in_sizes, int n_in,
                              void* d_out, int out_size) {
    const float* h1    = (const float*)d_in[0];
    const float* h2    = (const float*)d_in[1];
    const float* W1    = (const float*)d_in[2];
    const float* b1    = (const float*)d_in[3];
    const float* gamma = (const float*)d_in[4];
    const float* beta  = (const float*)d_in[5];
    const float* W2    = (const float*)d_in[6];
    const float* b2    = (const float*)d_in[7];
    float* out = (float*)d_out;

    cudaFuncSetAttribute(k_gemm1t, cudaFuncAttributeMaxDynamicSharedMemorySize, GSM1_BYTES);
    cudaFuncSetAttribute(k_gemm2t, cudaFuncAttributeMaxDynamicSharedMemorySize, GSM2_BYTES);
    cudaFuncSetAttribute(k_simp,   cudaFuncAttributeMaxDynamicSharedMemorySize, SIM_SMEM_SIZE);

    k_init   <<<33, 256>>>();
    k_gemm1t <<<dim3(4, 128), 256, GSM1_BYTES>>>(h1, h2, W1, b1);
    k_gemm2t <<<128, 256, GSM2_BYTES>>>(W2, b2, gamma, beta, out, out_size);
    k_simp   <<<1056, 256, SIM_SMEM_SIZE>>>();
    k_finish <<<512, 256>>>(out, out_size);
}

// round 13
// speedup vs baseline: 1.1393x; 1.1393x over previous
#include <cuda_runtime.h>
#include <cuda_bf16.h>
#include <math.h>
#include <stdint.h>

#define B_ROWS 4096
#define D_INF  192
#define D_HID  512
#define D_OUTF 128
#define M2     8192      // 2*B
#define INV_T  2.0f      // 1/TEMPERATURE
#define BN_EPS 1e-5f
#define L2_EPS 1e-12f
// zh = z * sqrt(2*log2(e)): zh_i.zh_j = 2*log2e*(z_i.z_j); exp((z.z)/T) = exp2(zh.zh)
#define ZH_SCALE 1.69864361f

// ---------------- scratch (static device globals; no allocation) ------------
__device__ __align__(128) float g_Y[(size_t)M2 * D_HID];     // 16 MB
__device__ __align__(128) float g_Z[(size_t)M2 * D_OUTF];    // fallback only
__device__ __align__(128) __nv_bfloat16 g_Zh[(size_t)M2 * D_OUTF]; // scaled bf16 z
__device__ __align__(128) __nv_bfloat16 g_Hh[(size_t)M2 * D_INF];
__device__ __align__(128) __nv_bfloat16 g_Hl[(size_t)M2 * D_INF];
__device__ __align__(128) __nv_bfloat16 g_W1h[D_HID * D_INF];
__device__ __align__(128) __nv_bfloat16 g_W1l[D_HID * D_INF];
__device__ __align__(128) __nv_bfloat16 g_W2h[D_OUTF * D_HID];
__device__ __align__(128) __nv_bfloat16 g_W2l[D_OUTF * D_HID];
__device__ float g_colsum[2][D_HID];
__device__ float g_colsq[2][D_HID];
__device__ float g_sumexp[M2];
__device__ float g_loss[1];
__device__ unsigned g_done;

// ---------------- helpers ----------------------------------------------------
__device__ __forceinline__ uint32_t smem_u32(const void* p) {
    uint32_t a;
    asm("{ .reg .u64 t; cvta.to.shared.u64 t, %1; cvt.u32.u64 %0, t; }" : "=r"(a) : "l"(p));
    return a;
}
__device__ __forceinline__ void ldsm4(uint32_t* r, uint32_t addr) {
    asm volatile("ldmatrix.sync.aligned.m8n8.x4.shared.b16 {%0,%1,%2,%3}, [%4];"
                 : "=r"(r[0]), "=r"(r[1]), "=r"(r[2]), "=r"(r[3]) : "r"(addr));
}
__device__ __forceinline__ void mma16816(float* c, const uint32_t* a, const uint32_t* b) {
    asm volatile(
        "mma.sync.aligned.m16n8k16.row.col.f32.bf16.bf16.f32 "
        "{%0,%1,%2,%3}, {%4,%5,%6,%7}, {%8,%9}, {%0,%1,%2,%3};"
        : "+f"(c[0]), "+f"(c[1]), "+f"(c[2]), "+f"(c[3])
        : "r"(a[0]), "r"(a[1]), "r"(a[2]), "r"(a[3]), "r"(b[0]), "r"(b[1]));
}
__device__ __forceinline__ float ex2(float x) {
    float y;
    asm("ex2.approx.f32 %0, %1;" : "=f"(y) : "f"(x));
    return y;
}
__device__ __forceinline__ void cpa16(uint32_t saddr, const void* gaddr) {
    asm volatile("cp.async.cg.shared.global [%0], [%1], 16;"
                 :: "r"(saddr), "l"(gaddr) : "memory");
}
__device__ __forceinline__ void cpa_wait_all() {
    asm volatile("cp.async.commit_group;\n\tcp.async.wait_group 0;" ::: "memory");
}
// split fp32 pair into bf16x2 hi + bf16x2 lo (x = hi + lo, err ~2^-18)
__device__ __forceinline__ void split2(float f0, float f1, uint32_t& hi, uint32_t& lo) {
    __nv_bfloat162 h = __floats2bfloat162_rn(f0, f1);
    __nv_bfloat162 l = __floats2bfloat162_rn(f0 - __bfloat162float(h.x),
                                             f1 - __bfloat162float(h.y));
    hi = *reinterpret_cast<uint32_t*>(&h);
    lo = *reinterpret_cast<uint32_t*>(&l);
}

// smem tile geometry for GEMMs (pitch 36 words = 72 bf16 = 144 bytes)
#define PW   36
#define SAW  (64 * PW)    // A tile: 64 rows
#define SBW  (128 * PW)   // B tile: 128 rows
#define GSM1_BYTES (((2 * SAW + 2 * SBW) * 4) + 1024)            // 56320
#define GSM2_BYTES (((2 * SAW + 2 * SBW) * 4) + 4096 + 1280)     // 60672

// ---------------- prep: init + split inputs to hi/lo bf16 (ONCE) ------------
__global__ __launch_bounds__(256) void k_prep(const float* __restrict__ h1,
                                              const float* __restrict__ h2,
                                              const float* __restrict__ W1,
                                              const float* __restrict__ W2) {
    int i = blockIdx.x * blockDim.x + threadIdx.x;
    if (i < M2) g_sumexp[i] = 0.f;
    if (i < 2 * D_HID) {
        g_colsum[i >> 9][i & 511] = 0.f;
        g_colsq [i >> 9][i & 511] = 0.f;
    }
    if (i == 0) { g_loss[0] = 0.f; g_done = 0u; }

    const int NH4  = (B_ROWS * D_INF) / 4;
    const int NW14 = (D_HID * D_INF) / 4;
    const int NW24 = (D_OUTF * D_HID) / 4;
    const float* src;
    __nv_bfloat16 *dh, *dl;
    int off;
    if (i < NH4)                        { src = h1; dh = g_Hh; dl = g_Hl; off = i; }
    else if (i < 2 * NH4)               { src = h2; dh = g_Hh + B_ROWS * D_INF;
                                          dl = g_Hl + B_ROWS * D_INF; off = i - NH4; }
    else if (i < 2 * NH4 + NW14)        { src = W1; dh = g_W1h; dl = g_W1l; off = i - 2 * NH4; }
    else if (i < 2 * NH4 + NW14 + NW24) { src = W2; dh = g_W2h; dl = g_W2l;
                                          off = i - 2 * NH4 - NW14; }
    else return;
    float4 v = *(const float4*)(src + (size_t)off * 4);
    uint32_t a0, b0, a1, b1v;
    split2(v.x, v.y, a0, b0);
    split2(v.z, v.w, a1, b1v);
    uint2 hh = {a0, a1}, ll = {b0, b1v};
    *(uint2*)(dh + (size_t)off * 4) = hh;
    *(uint2*)(dl + (size_t)off * 4) = ll;
}

// ---------------- GEMM1 (tensor, split-bf16): Y = H @ W1^T + b1 + BN partials
__global__ __launch_bounds__(256) void k_gemm1t(const float* __restrict__ b1) {
    extern __shared__ __align__(16) uint32_t sw[];
    uint32_t* sAhi = sw;
    uint32_t* sAlo = sw + SAW;
    uint32_t* sBhi = sw + 2 * SAW;
    uint32_t* sBlo = sw + 2 * SAW + SBW;
    float* colS = (float*)(sw + 2 * SAW + 2 * SBW);
    float* colQ = colS + 128;

    const int t = threadIdx.x;
    const int wid = t >> 5, lane = t & 31;
    const int gr = lane >> 2, qq = lane & 3;
    const int sel = lane >> 3, li = lane & 7;
    const int warp_m = wid >> 2, warp_n = wid & 3;
    const int n0 = blockIdx.x * 128;
    const int m0 = blockIdx.y * 64;
    const int half = (m0 >= B_ROWS);

    if (t < 128) { colS[t] = 0.f; colQ[t] = 0.f; }

    float acc[2][4][4];
#pragma unroll
    for (int mi = 0; mi < 2; mi++)
#pragma unroll
        for (int ni = 0; ni < 4; ni++)
#pragma unroll
            for (int r = 0; r < 4; r++) acc[mi][ni][r] = 0.f;

    const int arow = t >> 2, acq = (t & 3) * 16;
    const int brow = t >> 1, bcq = (t & 1) * 32;
    const __nv_bfloat16* pAh = g_Hh + (size_t)(m0 + arow) * D_INF + acq;
    const __nv_bfloat16* pAl = g_Hl + (size_t)(m0 + arow) * D_INF + acq;
    const __nv_bfloat16* pBh = g_W1h + (size_t)(n0 + brow) * D_INF + bcq;
    const __nv_bfloat16* pBl = g_W1l + (size_t)(n0 + brow) * D_INF + bcq;
    const int aw = arow * PW + (acq >> 1);
    const int bw = brow * PW + (bcq >> 1);

    const uint32_t sAhiU = smem_u32(sAhi), sAloU = smem_u32(sAlo);
    const uint32_t sBhiU = smem_u32(sBhi), sBloU = smem_u32(sBlo);
    uint32_t aoff[2], boff[2];
#pragma unroll
    for (int mi = 0; mi < 2; mi++)
        aoff[mi] = (uint32_t)(warp_m * 32 + mi * 16 + (sel & 1) * 8 + li) * 144u
                 + (uint32_t)(sel >> 1) * 16u;
#pragma unroll
    for (int nip = 0; nip < 2; nip++)
        boff[nip] = (uint32_t)(warp_n * 32 + nip * 16 + (sel >> 1) * 8 + li) * 144u
                  + (uint32_t)(sel & 1) * 16u;

    for (int kb = 0; kb < D_INF; kb += 64) {
        {
            uint4 v0 = *(const uint4*)(pAh + kb);
            uint4 v1 = *(const uint4*)(pAh + kb + 8);
            *(uint4*)(sAhi + aw) = v0; *(uint4*)(sAhi + aw + 4) = v1;
            v0 = *(const uint4*)(pAl + kb);
            v1 = *(const uint4*)(pAl + kb + 8);
            *(uint4*)(sAlo + aw) = v0; *(uint4*)(sAlo + aw + 4) = v1;
#pragma unroll
            for (int j = 0; j < 4; j++) {
                uint4 vh = *(const uint4*)(pBh + kb + j * 8);
                uint4 vl = *(const uint4*)(pBl + kb + j * 8);
                *(uint4*)(sBhi + bw + j * 4) = vh;
                *(uint4*)(sBlo + bw + j * 4) = vl;
            }
        }
        __syncthreads();
#pragma unroll
        for (int ks = 0; ks < 4; ks++) {
            uint32_t koff = (uint32_t)ks * 32u;
            uint32_t ah[2][4], al[2][4], bh[4][2], bl[4][2], tmp[4];
            ldsm4(ah[0], sAhiU + aoff[0] + koff);
            ldsm4(ah[1], sAhiU + aoff[1] + koff);
            ldsm4(al[0], sAloU + aoff[0] + koff);
            ldsm4(al[1], sAloU + aoff[1] + koff);
            ldsm4(tmp, sBhiU + boff[0] + koff);
            bh[0][0]=tmp[0]; bh[0][1]=tmp[1]; bh[1][0]=tmp[2]; bh[1][1]=tmp[3];
            ldsm4(tmp, sBhiU + boff[1] + koff);
            bh[2][0]=tmp[0]; bh[2][1]=tmp[1]; bh[3][0]=tmp[2]; bh[3][1]=tmp[3];
            ldsm4(tmp, sBloU + boff[0] + koff);
            bl[0][0]=tmp[0]; bl[0][1]=tmp[1]; bl[1][0]=tmp[2]; bl[1][1]=tmp[3];
            ldsm4(tmp, sBloU + boff[1] + koff);
            bl[2][0]=tmp[0]; bl[2][1]=tmp[1]; bl[3][0]=tmp[2]; bl[3][1]=tmp[3];
#pragma unroll
            for (int mi = 0; mi < 2; mi++)
#pragma unroll
                for (int ni = 0; ni < 4; ni++) {
                    mma16816(acc[mi][ni], ah[mi], bh[ni]);
                    mma16816(acc[mi][ni], ah[mi], bl[ni]);
                    mma16816(acc[mi][ni], al[mi], bh[ni]);
                }
        }
        __syncthreads();
    }

    float ps[4][2], pq[4][2];
#pragma unroll
    for (int ni = 0; ni < 4; ni++) { ps[ni][0]=ps[ni][1]=pq[ni][0]=pq[ni][1]=0.f; }
#pragma unroll
    for (int ni = 0; ni < 4; ni++) {
        int col = warp_n * 32 + ni * 8 + qq * 2;
        float2 bb = *(const float2*)&b1[n0 + col];
#pragma unroll
        for (int mi = 0; mi < 2; mi++) {
            int r = warp_m * 32 + mi * 16 + gr;
            float y0 = acc[mi][ni][0] + bb.x;
            float y1 = acc[mi][ni][1] + bb.y;
            float y2 = acc[mi][ni][2] + bb.x;
            float y3 = acc[mi][ni][3] + bb.y;
            float2 p0 = {y0, y1}, p1 = {y2, y3};
            *(float2*)&g_Y[(size_t)(m0 + r)     * D_HID + n0 + col] = p0;
            *(float2*)&g_Y[(size_t)(m0 + r + 8) * D_HID + n0 + col] = p1;
            ps[ni][0] += y0 + y2;              ps[ni][1] += y1 + y3;
            pq[ni][0] += y0 * y0 + y2 * y2;    pq[ni][1] += y1 * y1 + y3 * y3;
        }
    }
#pragma unroll
    for (int ni = 0; ni < 4; ni++)
#pragma unroll
        for (int c2 = 0; c2 < 2; c2++) {
            float s = ps[ni][c2], q = pq[ni][c2];
            s += __shfl_xor_sync(~0u, s, 4);  q += __shfl_xor_sync(~0u, q, 4);
            s += __shfl_xor_sync(~0u, s, 8);  q += __shfl_xor_sync(~0u, q, 8);
            s += __shfl_xor_sync(~0u, s, 16); q += __shfl_xor_sync(~0u, q, 16);
            ps[ni][c2] = s; pq[ni][c2] = q;
        }
    if (gr == 0) {
#pragma unroll
        for (int ni = 0; ni < 4; ni++) {
            int col = warp_n * 32 + ni * 8 + qq * 2;
            atomicAdd(&colS[col],     ps[ni][0]);
            atomicAdd(&colS[col + 1], ps[ni][1]);
            atomicAdd(&colQ[col],     pq[ni][0]);
            atomicAdd(&colQ[col + 1], pq[ni][1]);
        }
    }
    __syncthreads();
    if (t < 128) {
        atomicAdd(&g_colsum[half][n0 + t], colS[t]);
        atomicAdd(&g_colsq [half][n0 + t], colQ[t]);
    }
}

// ---------------- GEMM2 (tensor, split-bf16): Z = relu(BN(Y)) @ W2^T + b2 ----
// BM=64, BN=128, K=512 in 8 chunks of 64. BN finalize folded into prologue.
// z written straight into out+1 (scalar stores; 4B-aligned) + g_Zh.
__global__ __launch_bounds__(256) void k_gemm2t(const float* __restrict__ b2,
                                                const float* __restrict__ gamma,
                                                const float* __restrict__ beta,
                                                float* __restrict__ out,
                                                int out_size) {
    extern __shared__ __align__(16) uint32_t sw[];
    uint32_t* sAhi = sw;
    uint32_t* sAlo = sw + SAW;
    uint32_t* sBhi = sw + 2 * SAW;
    uint32_t* sBlo = sw + 2 * SAW + SBW;
    float* ssc  = (float*)(sw + 2 * SAW + 2 * SBW);
    float* ssh  = ssc + D_HID;
    float* red  = ssh + D_HID;    // [64][4]
    float* sInv = red + 256;      // [64]

    const int t = threadIdx.x;
    const int wid = t >> 5, lane = t & 31;
    const int gr = lane >> 2, qq = lane & 3;
    const int sel = lane >> 3, li = lane & 7;
    const int warp_m = wid >> 2, warp_n = wid & 3;
    const int m0 = blockIdx.x * 64;
    const int half = (m0 >= B_ROWS);

    for (int c = t; c < D_HID; c += 256) {
        float mean = g_colsum[half][c] * (1.f / B_ROWS);
        float var  = g_colsq [half][c] * (1.f / B_ROWS) - mean * mean;
        float scv  = gamma[c] * rsqrtf(var + BN_EPS);
        ssc[c] = scv;
        ssh[c] = beta[c] - mean * scv;
    }
    __syncthreads();

    float acc[2][4][4];
#pragma unroll
    for (int mi = 0; mi < 2; mi++)
#pragma unroll
        for (int ni = 0; ni < 4; ni++)
#pragma unroll
            for (int r = 0; r < 4; r++) acc[mi][ni][r] = 0.f;

    const int arow = t >> 2, acq = (t & 3) * 16;
    const int brow = t >> 1, bcq = (t & 1) * 32;
    const float* pA = g_Y + (size_t)(m0 + arow) * D_HID + acq;
    const __nv_bfloat16* pBh = g_W2h + (size_t)brow * D_HID + bcq;
    const __nv_bfloat16* pBl = g_W2l + (size_t)brow * D_HID + bcq;
    const int aw = arow * PW + (acq >> 1);
    const int bw = brow * PW + (bcq >> 1);

    const uint32_t sAhiU = smem_u32(sAhi), sAloU = smem_u32(sAlo);
    const uint32_t sBhiU = smem_u32(sBhi), sBloU = smem_u32(sBlo);
    uint32_t aoff[2], boff[2];
#pragma unroll
    for (int mi = 0; mi < 2; mi++)
        aoff[mi] = (uint32_t)(warp_m * 32 + mi * 16 + (sel & 1) * 8 + li) * 144u
                 + (uint32_t)(sel >> 1) * 16u;
#pragma unroll
    for (int nip = 0; nip < 2; nip++)
        boff[nip] = (uint32_t)(warp_n * 32 + nip * 16 + (sel >> 1) * 8 + li) * 144u
                  + (uint32_t)(sel & 1) * 16u;

    for (int kb = 0; kb < D_HID; kb += 64) {
        {
#pragma unroll
            for (int j = 0; j < 4; j++) {
                float4 v = *(const float4*)(pA + kb + j * 4);
                int k = kb + acq + j * 4;
                float f0 = fmaxf(fmaf(v.x, ssc[k],     ssh[k]),     0.f);
                float f1 = fmaxf(fmaf(v.y, ssc[k + 1], ssh[k + 1]), 0.f);
                float f2 = fmaxf(fmaf(v.z, ssc[k + 2], ssh[k + 2]), 0.f);
                float f3 = fmaxf(fmaf(v.w, ssc[k + 3], ssh[k + 3]), 0.f);
                uint32_t h0, l0, h1v, l1;
                split2(f0, f1, h0, l0);
                split2(f2, f3, h1v, l1);
                uint2 hh = {h0, h1v}, ll = {l0, l1};
                *(uint2*)(sAhi + aw + j * 2) = hh;
                *(uint2*)(sAlo + aw + j * 2) = ll;
            }
#pragma unroll
            for (int j = 0; j < 4; j++) {
                uint4 vh = *(const uint4*)(pBh + kb + j * 8);
                uint4 vl = *(const uint4*)(pBl + kb + j * 8);
                *(uint4*)(sBhi + bw + j * 4) = vh;
                *(uint4*)(sBlo + bw + j * 4) = vl;
            }
        }
        __syncthreads();
#pragma unroll
        for (int ks = 0; ks < 4; ks++) {
            uint32_t koff = (uint32_t)ks * 32u;
            uint32_t ah[2][4], al[2][4], bh[4][2], bl[4][2], tmp[4];
            ldsm4(ah[0], sAhiU + aoff[0] + koff);
            ldsm4(ah[1], sAhiU + aoff[1] + koff);
            ldsm4(al[0], sAloU + aoff[0] + koff);
            ldsm4(al[1], sAloU + aoff[1] + koff);
            ldsm4(tmp, sBhiU + boff[0] + koff);
            bh[0][0]=tmp[0]; bh[0][1]=tmp[1]; bh[1][0]=tmp[2]; bh[1][1]=tmp[3];
            ldsm4(tmp, sBhiU + boff[1] + koff);
            bh[2][0]=tmp[0]; bh[2][1]=tmp[1]; bh[3][0]=tmp[2]; bh[3][1]=tmp[3];
            ldsm4(tmp, sBloU + boff[0] + koff);
            bl[0][0]=tmp[0]; bl[0][1]=tmp[1]; bl[1][0]=tmp[2]; bl[1][1]=tmp[3];
            ldsm4(tmp, sBloU + boff[1] + koff);
            bl[2][0]=tmp[0]; bl[2][1]=tmp[1]; bl[3][0]=tmp[2]; bl[3][1]=tmp[3];
#pragma unroll
            for (int mi = 0; mi < 2; mi++)
#pragma unroll
                for (int ni = 0; ni < 4; ni++) {
                    mma16816(acc[mi][ni], ah[mi], bh[ni]);
                    mma16816(acc[mi][ni], ah[mi], bl[ni]);
                    mma16816(acc[mi][ni], al[mi], bh[ni]);
                }
        }
        __syncthreads();
    }

    float rp[2][2] = {{0.f, 0.f}, {0.f, 0.f}};
#pragma unroll
    for (int ni = 0; ni < 4; ni++) {
        int col = warp_n * 32 + ni * 8 + qq * 2;
        float2 bb = *(const float2*)&b2[col];
#pragma unroll
        for (int mi = 0; mi < 2; mi++) {
            acc[mi][ni][0] += bb.x; acc[mi][ni][1] += bb.y;
            acc[mi][ni][2] += bb.x; acc[mi][ni][3] += bb.y;
            rp[mi][0] = fmaf(acc[mi][ni][0], acc[mi][ni][0],
                        fmaf(acc[mi][ni][1], acc[mi][ni][1], rp[mi][0]));
            rp[mi][1] = fmaf(acc[mi][ni][2], acc[mi][ni][2],
                        fmaf(acc[mi][ni][3], acc[mi][ni][3], rp[mi][1]));
        }
    }
#pragma unroll
    for (int mi = 0; mi < 2; mi++)
#pragma unroll
        for (int rh = 0; rh < 2; rh++) {
            float s = rp[mi][rh];
            s += __shfl_xor_sync(~0u, s, 1);
            s += __shfl_xor_sync(~0u, s, 2);
            rp[mi][rh] = s;
        }
    if (qq == 0) {
#pragma unroll
        for (int mi = 0; mi < 2; mi++) {
            red[(warp_m * 32 + mi * 16 + gr)     * 4 + warp_n] = rp[mi][0];
            red[(warp_m * 32 + mi * 16 + gr + 8) * 4 + warp_n] = rp[mi][1];
        }
    }
    __syncthreads();
    if (t < 64) {
        float s = red[t * 4] + red[t * 4 + 1] + red[t * 4 + 2] + red[t * 4 + 3];
        sInv[t] = 1.f / fmaxf(sqrtf(s), L2_EPS);
    }
    __syncthreads();
    bool full = (out_size > M2 * D_OUTF);
#pragma unroll
    for (int mi = 0; mi < 2; mi++)
#pragma unroll
        for (int rh = 0; rh < 2; rh++) {
            int r = warp_m * 32 + mi * 16 + gr + rh * 8;
            float inv = sInv[r];
            int m = m0 + r;
#pragma unroll
            for (int ni = 0; ni < 4; ni++) {
                int col = warp_n * 32 + ni * 8 + qq * 2;
                float z0 = acc[mi][ni][rh * 2]     * inv;
                float z1 = acc[mi][ni][rh * 2 + 1] * inv;
                if (full) {
                    // out+1 is only 4B-aligned: scalar stores
                    out[1 + (size_t)m * D_OUTF + col]     = z0;
                    out[1 + (size_t)m * D_OUTF + col + 1] = z1;
                } else {
                    float2 zz = {z0, z1};
                    *(float2*)&g_Z[(size_t)m * D_OUTF + col] = zz;
                }
                *(__nv_bfloat162*)&g_Zh[(size_t)m * D_OUTF + col] =
                    __floats2bfloat162_rn(z0 * ZH_SCALE, z1 * ZH_SCALE);
            }
        }
}

// ---------------- paired tensor-core sim: 128x256 tile per CTA --------------
#define SIM_PITCH_B 272                        // 128 cols bf16 + 16B pad
#define SIM_TILE_BYTES (128 * SIM_PITCH_B)     // 34816
#define SIM_SMEM_SIZE (3 * SIM_TILE_BYTES + 3 * 128 * 4)

__device__ __forceinline__ int pair_off(int bi) {
    int h = bi >> 1, r = bi & 1;
    return 32 * bi - h * (h - 1 + r);
}

__global__ __launch_bounds__(256, 2) void k_simp() {
    extern __shared__ __align__(16) char smem[];
    char* sA  = smem;
    char* sB0 = smem + SIM_TILE_BYTES;
    char* sB1 = smem + 2 * SIM_TILE_BYTES;
    float* srow  = (float*)(smem + 3 * SIM_TILE_BYTES);
    float* scol0 = srow + 128;
    float* scol1 = srow + 256;

    const int t = threadIdx.x;
    const int wid = t >> 5, lane = t & 31;
    const int gr = lane >> 2, qq = lane & 3;
    const int sel = lane >> 3, li = lane & 7;
    const int warp_m = wid >> 2, warp_n = wid & 3;

    int tb = blockIdx.x;
    float disc = fmaxf(4096.f - 4.f * (float)tb, 0.f);
    int bi = (int)(64.f - sqrtf(disc));
    if (bi < 0) bi = 0; if (bi > 63) bi = 63;
    while (bi < 63 && pair_off(bi + 1) <= tb) ++bi;
    while (bi > 0 && pair_off(bi) > tb) --bi;
    int c = (bi >> 1) + (tb - pair_off(bi));
    const size_t i0  = (size_t)bi * 128;
    const int bj0 = 2 * c, bj1 = 2 * c + 1;
    const size_t j00 = (size_t)bj0 * 128;
    const size_t j01 = (size_t)bj1 * 128;
    const bool sub0  = (bj0 >= bi);
    const bool col0  = (bj0 > bi);
    const bool col1  = (bj1 > bi);

    const uint32_t sAu  = smem_u32(sA);
    const uint32_t sB0u = smem_u32(sB0);
    const uint32_t sB1u = smem_u32(sB1);
    const char* gA  = (const char*)(g_Zh + i0  * D_OUTF);
    const char* gB0 = (const char*)(g_Zh + j00 * D_OUTF);
    const char* gB1 = (const char*)(g_Zh + j01 * D_OUTF);
#pragma unroll
    for (int it = 0; it < 8; it++) {
        int q = t + it * 256;
        uint32_t so = (uint32_t)(q >> 4) * SIM_PITCH_B + (uint32_t)(q & 15) * 16u;
        cpa16(sAu + so,  gA  + q * 16);
        cpa16(sB0u + so, gB0 + q * 16);
        cpa16(sB1u + so, gB1 + q * 16);
    }
    if (t < 128) { srow[t] = 0.f; scol0[t] = 0.f; scol1[t] = 0.f; }
    cpa_wait_all();
    __syncthreads();

    uint32_t aBase[4], bB0[2], bB1[2];
#pragma unroll
    for (int mi = 0; mi < 4; mi++)
        aBase[mi] = sAu + (uint32_t)(warp_m * 64 + mi * 16 + (sel & 1) * 8 + li) * SIM_PITCH_B
                  + (uint32_t)(sel >> 1) * 16u;
#pragma unroll
    for (int nip = 0; nip < 2; nip++) {
        uint32_t ro = (uint32_t)(warp_n * 32 + nip * 16 + (sel >> 1) * 8 + li) * SIM_PITCH_B
                    + (uint32_t)(sel & 1) * 16u;
        bB0[nip] = sB0u + ro;
        bB1[nip] = sB1u + ro;
    }

    float rsum[8];
#pragma unroll
    for (int i = 0; i < 8; i++) rsum[i] = 0.f;

    for (int sub = 0; sub < 2; sub++) {
        if (sub == 0 && !sub0) continue;
        const uint32_t* bBase = sub ? bB1 : bB0;
        const bool colAdd = sub ? col1 : col0;
        float* scol = sub ? scol1 : scol0;

        float cc[4][4][4];
#pragma unroll
        for (int mi = 0; mi < 4; mi++)
#pragma unroll
            for (int ni = 0; ni < 4; ni++)
#pragma unroll
                for (int r = 0; r < 4; r++) cc[mi][ni][r] = 0.f;

#pragma unroll
        for (int ks = 0; ks < 8; ks++) {
            uint32_t koff = (uint32_t)ks * 32u;
            uint32_t a[4][4], b[4][2], tmp[4];
#pragma unroll
            for (int mi = 0; mi < 4; mi++) ldsm4(a[mi], aBase[mi] + koff);
            ldsm4(tmp, bBase[0] + koff);
            b[0][0]=tmp[0]; b[0][1]=tmp[1]; b[1][0]=tmp[2]; b[1][1]=tmp[3];
            ldsm4(tmp, bBase[1] + koff);
            b[2][0]=tmp[0]; b[2][1]=tmp[1]; b[3][0]=tmp[2]; b[3][1]=tmp[3];
#pragma unroll
            for (int mi = 0; mi < 4; mi++)
#pragma unroll
                for (int ni = 0; ni < 4; ni++)
                    mma16816(cc[mi][ni], a[mi], b[ni]);
        }

        float csum[8];
#pragma unroll
        for (int i = 0; i < 8; i++) csum[i] = 0.f;
#pragma unroll
        for (int mi = 0; mi < 4; mi++)
#pragma unroll
            for (int ni = 0; ni < 4; ni++) {
                float e0 = ex2(cc[mi][ni][0]);
                float e1 = ex2(cc[mi][ni][1]);
                float e2 = ex2(cc[mi][ni][2]);
                float e3 = ex2(cc[mi][ni][3]);
                rsum[mi * 2 + 0] += e0 + e1;
                rsum[mi * 2 + 1] += e2 + e3;
                csum[ni * 2 + 0] += e0 + e2;
                csum[ni * 2 + 1] += e1 + e3;
            }
        if (colAdd) {
#pragma unroll
            for (int i = 0; i < 8; i++) {
                csum[i] += __shfl_xor_sync(0xffffffffu, csum[i], 4);
                csum[i] += __shfl_xor_sync(0xffffffffu, csum[i], 8);
                csum[i] += __shfl_xor_sync(0xffffffffu, csum[i], 16);
            }
            if (gr == 0) {
#pragma unroll
                for (int ni = 0; ni < 4; ni++) {
                    atomicAdd(&scol[warp_n * 32 + ni * 8 + qq * 2],     csum[ni * 2 + 0]);
                    atomicAdd(&scol[warp_n * 32 + ni * 8 + qq * 2 + 1], csum[ni * 2 + 1]);
                }
            }
        }
    }

#pragma unroll
    for (int i = 0; i < 8; i++) {
        rsum[i] += __shfl_xor_sync(0xffffffffu, rsum[i], 1);
        rsum[i] += __shfl_xor_sync(0xffffffffu, rsum[i], 2);
    }
    if (qq == 0) {
#pragma unroll
        for (int mi = 0; mi < 4; mi++) {
            atomicAdd(&srow[warp_m * 64 + mi * 16 + gr],     rsum[mi * 2 + 0]);
            atomicAdd(&srow[warp_m * 64 + mi * 16 + gr + 8], rsum[mi * 2 + 1]);
        }
    }
    __syncthreads();
    if (t < 128) {
        atomicAdd(&g_sumexp[i0 + t], srow[t]);
        if (col0) atomicAdd(&g_sumexp[j00 + t], scol0[t]);
        if (col1) atomicAdd(&g_sumexp[j01 + t], scol1[t]);
    }
}

// ---------------- finish: loss = mean(lse_i - pos_i); emits out[0] ----------
__global__ void k_finish(float* __restrict__ out, int out_size) {
    int w    = (blockIdx.x * blockDim.x + threadIdx.x) >> 5;
    int lane = threadIdx.x & 31;
    if (w >= B_ROWS) return;
    bool full = (out_size > M2 * D_OUTF);
    const float* zsrc = full ? (out + 1) : g_Z;
    // zsrc may be only 4B-aligned (out+1): scalar loads
    const float* p1 = zsrc + (size_t)w * D_OUTF + lane * 4;
    const float* p2 = zsrc + (size_t)(w + B_ROWS) * D_OUTF + lane * 4;
    float dp = 0.f;
#pragma unroll
    for (int j = 0; j < 4; j++) dp = fmaf(p1[j], p2[j], dp);
    const __nv_bfloat16* z1 = g_Zh + (size_t)w * D_OUTF + lane * 4;
    const __nv_bfloat16* z2 = g_Zh + (size_t)(w + B_ROWS) * D_OUTF + lane * 4;
    float d1 = 0.f, d2 = 0.f;
#pragma unroll
    for (int j = 0; j < 4; j++) {
        float v1 = __bfloat162float(z1[j]);
        float v2 = __bfloat162float(z2[j]);
        d1 = fmaf(v1, v1, d1);
        d2 = fmaf(v2, v2, d2);
    }
#pragma unroll
    for (int o = 16; o; o >>= 1) {
        dp += __shfl_down_sync(0xffffffffu, dp, o);
        d1 += __shfl_down_sync(0xffffffffu, d1, o);
        d2 += __shfl_down_sync(0xffffffffu, d2, o);
    }
    if (lane == 0) {
        float pos  = dp * INV_T;
        float lse1 = logf(g_sumexp[w]          - ex2(d1));
        float lse2 = logf(g_sumexp[w + B_ROWS] - ex2(d2));
        atomicAdd(&g_loss[0], (lse1 + lse2 - 2.f * pos) * (1.f / M2));
        __threadfence();
        unsigned prev = atomicAdd(&g_done, 1u);
        if (prev == B_ROWS - 1) {
            if (out_size > 0) out[0] = g_loss[0];
            g_done = 0u;   // reset for next graph replay
        }
    }
}

// ---------------- launch -----------------------------------------------------
extern "C" void kernel_launch(void* const* d_in, const int* in_sizes, int n_in,
                              void* d_out, int out_size) {
    const float* h1    = (const float*)d_in[0];
    const float* h2    = (const float*)d_in[1];
    const float* W1    = (const float*)d_in[2];
    const float* b1    = (const float*)d_in[3];
    const float* gamma = (const float*)d_in[4];
    const float* beta  = (const float*)d_in[5];
    const float* W2    = (const float*)d_in[6];
    const float* b2    = (const float*)d_in[7];
    float* out = (float*)d_out;

    cudaFuncSetAttribute(k_gemm1t, cudaFuncAttributeMaxDynamicSharedMemorySize, GSM1_BYTES);
    cudaFuncSetAttribute(k_gemm2t, cudaFuncAttributeMaxDynamicSharedMemorySize, GSM2_BYTES);
    cudaFuncSetAttribute(k_simp,   cudaFuncAttributeMaxDynamicSharedMemorySize, SIM_SMEM_SIZE);

    k_prep   <<<1696, 256>>>(h1, h2, W1, W2);
    k_gemm1t <<<dim3(4, 128), 256, GSM1_BYTES>>>(b1);
    k_gemm2t <<<128, 256, GSM2_BYTES>>>(b2, gamma, beta, out, out_size);
    k_simp   <<<1056, 256, SIM_SMEM_SIZE>>>();
    k_finish <<<512, 256>>>(out, out_size);
}

// round 14
// speedup vs baseline: 1.1659x; 1.0233x over previous
#include <cuda_runtime.h>
#include <cuda_bf16.h>
#include <math.h>
#include <stdint.h>

#define B_ROWS 4096
#define D_INF  192
#define D_HID  512
#define D_OUTF 128
#define M2     8192      // 2*B
#define INV_T  2.0f      // 1/TEMPERATURE
#define BN_EPS 1e-5f
#define L2_EPS 1e-12f
// zh = z * sqrt(2*log2(e)): zh_i.zh_j = 2*log2e*(z_i.z_j); exp((z.z)/T) = exp2(zh.zh)
#define ZH_SCALE 1.69864361f

// ---------------- scratch (static device globals; no allocation) ------------
__device__ __align__(128) float g_Y[(size_t)M2 * D_HID];     // 16 MB
__device__ __align__(128) float g_Z[(size_t)M2 * D_OUTF];    // fallback only
__device__ __align__(128) __nv_bfloat16 g_Zh[(size_t)M2 * D_OUTF]; // scaled bf16 z
__device__ __align__(128) __nv_bfloat16 g_W1h[D_HID * D_INF];
__device__ __align__(128) __nv_bfloat16 g_W1l[D_HID * D_INF];
__device__ __align__(128) __nv_bfloat16 g_W2h[D_OUTF * D_HID];
__device__ __align__(128) __nv_bfloat16 g_W2l[D_OUTF * D_HID];
__device__ float g_colsum[2][D_HID];
__device__ float g_colsq[2][D_HID];
__device__ float g_sumexp[M2];
__device__ float g_loss[1];
__device__ unsigned g_done;

// ---------------- helpers ----------------------------------------------------
__device__ __forceinline__ uint32_t smem_u32(const void* p) {
    uint32_t a;
    asm("{ .reg .u64 t; cvta.to.shared.u64 t, %1; cvt.u32.u64 %0, t; }" : "=r"(a) : "l"(p));
    return a;
}
__device__ __forceinline__ void ldsm4(uint32_t* r, uint32_t addr) {
    asm volatile("ldmatrix.sync.aligned.m8n8.x4.shared.b16 {%0,%1,%2,%3}, [%4];"
                 : "=r"(r[0]), "=r"(r[1]), "=r"(r[2]), "=r"(r[3]) : "r"(addr));
}
__device__ __forceinline__ void mma16816(float* c, const uint32_t* a, const uint32_t* b) {
    asm volatile(
        "mma.sync.aligned.m16n8k16.row.col.f32.bf16.bf16.f32 "
        "{%0,%1,%2,%3}, {%4,%5,%6,%7}, {%8,%9}, {%0,%1,%2,%3};"
        : "+f"(c[0]), "+f"(c[1]), "+f"(c[2]), "+f"(c[3])
        : "r"(a[0]), "r"(a[1]), "r"(a[2]), "r"(a[3]), "r"(b[0]), "r"(b[1]));
}
__device__ __forceinline__ float ex2(float x) {
    float y;
    asm("ex2.approx.f32 %0, %1;" : "=f"(y) : "f"(x));
    return y;
}
__device__ __forceinline__ void cpa16(uint32_t saddr, const void* gaddr) {
    asm volatile("cp.async.cg.shared.global [%0], [%1], 16;"
                 :: "r"(saddr), "l"(gaddr) : "memory");
}
__device__ __forceinline__ void cpa_wait_all() {
    asm volatile("cp.async.commit_group;\n\tcp.async.wait_group 0;" ::: "memory");
}
// split fp32 pair into bf16x2 hi + bf16x2 lo (x = hi + lo, err ~2^-18)
__device__ __forceinline__ void split2(float f0, float f1, uint32_t& hi, uint32_t& lo) {
    __nv_bfloat162 h = __floats2bfloat162_rn(f0, f1);
    __nv_bfloat162 l = __floats2bfloat162_rn(f0 - __bfloat162float(h.x),
                                             f1 - __bfloat162float(h.y));
    hi = *reinterpret_cast<uint32_t*>(&h);
    lo = *reinterpret_cast<uint32_t*>(&l);
}

// smem tile geometry for GEMMs (pitch 36 words = 72 bf16 = 144 bytes)
#define PW   36
#define SAW  (64 * PW)    // A tile: 64 rows
#define SBW  (128 * PW)   // B tile: 128 rows
#define GSM1_BYTES (((2 * SAW + 2 * SBW) * 4) + 1024)            // 56320
#define GSM2_BYTES (((2 * SAW + 2 * SBW) * 4) + 4096 + 1280)     // 60672

// ---------------- prep: init + split WEIGHTS to hi/lo bf16 (once) -----------
__global__ __launch_bounds__(256) void k_prep(const float* __restrict__ W1,
                                              const float* __restrict__ W2) {
    int i = blockIdx.x * blockDim.x + threadIdx.x;
    if (i < M2) g_sumexp[i] = 0.f;
    if (i < 2 * D_HID) {
        g_colsum[i >> 9][i & 511] = 0.f;
        g_colsq [i >> 9][i & 511] = 0.f;
    }
    if (i == 0) { g_loss[0] = 0.f; g_done = 0u; }

    const int NW14 = (D_HID * D_INF) / 4;    // 24576
    const int NW24 = (D_OUTF * D_HID) / 4;   // 16384
    const float* src;
    __nv_bfloat16 *dh, *dl;
    int off;
    if (i < NW14)             { src = W1; dh = g_W1h; dl = g_W1l; off = i; }
    else if (i < NW14 + NW24) { src = W2; dh = g_W2h; dl = g_W2l; off = i - NW14; }
    else return;
    float4 v = *(const float4*)(src + (size_t)off * 4);
    uint32_t a0, b0, a1, b1v;
    split2(v.x, v.y, a0, b0);
    split2(v.z, v.w, a1, b1v);
    uint2 hh = {a0, a1}, ll = {b0, b1v};
    *(uint2*)(dh + (size_t)off * 4) = hh;
    *(uint2*)(dl + (size_t)off * 4) = ll;
}

// ---------------- GEMM1 (tensor, split-bf16): Y = H @ W1^T + b1 + BN partials
// BM=64, BN=128, K=192 in 3 chunks of 64. A split in-register from fp32 H
// (4x redundancy only); B from pre-split W1.
__global__ __launch_bounds__(256) void k_gemm1t(const float* __restrict__ h1,
                                                const float* __restrict__ h2,
                                                const float* __restrict__ b1) {
    extern __shared__ __align__(16) uint32_t sw[];
    uint32_t* sAhi = sw;
    uint32_t* sAlo = sw + SAW;
    uint32_t* sBhi = sw + 2 * SAW;
    uint32_t* sBlo = sw + 2 * SAW + SBW;
    float* colS = (float*)(sw + 2 * SAW + 2 * SBW);
    float* colQ = colS + 128;

    const int t = threadIdx.x;
    const int wid = t >> 5, lane = t & 31;
    const int gr = lane >> 2, qq = lane & 3;
    const int sel = lane >> 3, li = lane & 7;
    const int warp_m = wid >> 2, warp_n = wid & 3;
    const int n0 = blockIdx.x * 128;
    const int m0 = blockIdx.y * 64;
    const int half = (m0 >= B_ROWS);
    const float* H = half ? (h2 + (size_t)(m0 - B_ROWS) * D_INF)
                          : (h1 + (size_t)m0 * D_INF);

    if (t < 128) { colS[t] = 0.f; colQ[t] = 0.f; }

    float acc[2][4][4];
#pragma unroll
    for (int mi = 0; mi < 2; mi++)
#pragma unroll
        for (int ni = 0; ni < 4; ni++)
#pragma unroll
            for (int r = 0; r < 4; r++) acc[mi][ni][r] = 0.f;

    const int arow = t >> 2, acq = (t & 3) * 16;
    const int brow = t >> 1, bcq = (t & 1) * 32;
    const float* pAf = H + (size_t)arow * D_INF + acq;
    const __nv_bfloat16* pBh = g_W1h + (size_t)(n0 + brow) * D_INF + bcq;
    const __nv_bfloat16* pBl = g_W1l + (size_t)(n0 + brow) * D_INF + bcq;
    const int aw = arow * PW + (acq >> 1);
    const int bw = brow * PW + (bcq >> 1);

    const uint32_t sAhiU = smem_u32(sAhi), sAloU = smem_u32(sAlo);
    const uint32_t sBhiU = smem_u32(sBhi), sBloU = smem_u32(sBlo);
    uint32_t aoff[2], boff[2];
#pragma unroll
    for (int mi = 0; mi < 2; mi++)
        aoff[mi] = (uint32_t)(warp_m * 32 + mi * 16 + (sel & 1) * 8 + li) * 144u
                 + (uint32_t)(sel >> 1) * 16u;
#pragma unroll
    for (int nip = 0; nip < 2; nip++)
        boff[nip] = (uint32_t)(warp_n * 32 + nip * 16 + (sel >> 1) * 8 + li) * 144u
                  + (uint32_t)(sel & 1) * 16u;

    for (int kb = 0; kb < D_INF; kb += 64) {
        {
#pragma unroll
            for (int j = 0; j < 4; j++) {
                float4 v = *(const float4*)(pAf + kb + j * 4);
                uint32_t h0, l0, h1v, l1;
                split2(v.x, v.y, h0, l0);
                split2(v.z, v.w, h1v, l1);
                uint2 hh = {h0, h1v}, ll = {l0, l1};
                *(uint2*)(sAhi + aw + j * 2) = hh;
                *(uint2*)(sAlo + aw + j * 2) = ll;
            }
#pragma unroll
            for (int j = 0; j < 4; j++) {
                uint4 vh = *(const uint4*)(pBh + kb + j * 8);
                uint4 vl = *(const uint4*)(pBl + kb + j * 8);
                *(uint4*)(sBhi + bw + j * 4) = vh;
                *(uint4*)(sBlo + bw + j * 4) = vl;
            }
        }
        __syncthreads();
#pragma unroll
        for (int ks = 0; ks < 4; ks++) {
            uint32_t koff = (uint32_t)ks * 32u;
            uint32_t ah[2][4], al[2][4], bh[4][2], bl[4][2], tmp[4];
            ldsm4(ah[0], sAhiU + aoff[0] + koff);
            ldsm4(ah[1], sAhiU + aoff[1] + koff);
            ldsm4(al[0], sAloU + aoff[0] + koff);
            ldsm4(al[1], sAloU + aoff[1] + koff);
            ldsm4(tmp, sBhiU + boff[0] + koff);
            bh[0][0]=tmp[0]; bh[0][1]=tmp[1]; bh[1][0]=tmp[2]; bh[1][1]=tmp[3];
            ldsm4(tmp, sBhiU + boff[1] + koff);
            bh[2][0]=tmp[0]; bh[2][1]=tmp[1]; bh[3][0]=tmp[2]; bh[3][1]=tmp[3];
            ldsm4(tmp, sBloU + boff[0] + koff);
            bl[0][0]=tmp[0]; bl[0][1]=tmp[1]; bl[1][0]=tmp[2]; bl[1][1]=tmp[3];
            ldsm4(tmp, sBloU + boff[1] + koff);
            bl[2][0]=tmp[0]; bl[2][1]=tmp[1]; bl[3][0]=tmp[2]; bl[3][1]=tmp[3];
#pragma unroll
            for (int mi = 0; mi < 2; mi++)
#pragma unroll
                for (int ni = 0; ni < 4; ni++) {
                    mma16816(acc[mi][ni], ah[mi], bh[ni]);
                    mma16816(acc[mi][ni], ah[mi], bl[ni]);
                    mma16816(acc[mi][ni], al[mi], bh[ni]);
                }
        }
        __syncthreads();
    }

    float ps[4][2], pq[4][2];
#pragma unroll
    for (int ni = 0; ni < 4; ni++) { ps[ni][0]=ps[ni][1]=pq[ni][0]=pq[ni][1]=0.f; }
#pragma unroll
    for (int ni = 0; ni < 4; ni++) {
        int col = warp_n * 32 + ni * 8 + qq * 2;
        float2 bb = *(const float2*)&b1[n0 + col];
#pragma unroll
        for (int mi = 0; mi < 2; mi++) {
            int r = warp_m * 32 + mi * 16 + gr;
            float y0 = acc[mi][ni][0] + bb.x;
            float y1 = acc[mi][ni][1] + bb.y;
            float y2 = acc[mi][ni][2] + bb.x;
            float y3 = acc[mi][ni][3] + bb.y;
            float2 p0 = {y0, y1}, p1 = {y2, y3};
            *(float2*)&g_Y[(size_t)(m0 + r)     * D_HID + n0 + col] = p0;
            *(float2*)&g_Y[(size_t)(m0 + r + 8) * D_HID + n0 + col] = p1;
            ps[ni][0] += y0 + y2;              ps[ni][1] += y1 + y3;
            pq[ni][0] += y0 * y0 + y2 * y2;    pq[ni][1] += y1 * y1 + y3 * y3;
        }
    }
#pragma unroll
    for (int ni = 0; ni < 4; ni++)
#pragma unroll
        for (int c2 = 0; c2 < 2; c2++) {
            float s = ps[ni][c2], q = pq[ni][c2];
            s += __shfl_xor_sync(~0u, s, 4);  q += __shfl_xor_sync(~0u, q, 4);
            s += __shfl_xor_sync(~0u, s, 8);  q += __shfl_xor_sync(~0u, q, 8);
            s += __shfl_xor_sync(~0u, s, 16); q += __shfl_xor_sync(~0u, q, 16);
            ps[ni][c2] = s; pq[ni][c2] = q;
        }
    if (gr == 0) {
#pragma unroll
        for (int ni = 0; ni < 4; ni++) {
            int col = warp_n * 32 + ni * 8 + qq * 2;
            atomicAdd(&colS[col],     ps[ni][0]);
            atomicAdd(&colS[col + 1], ps[ni][1]);
            atomicAdd(&colQ[col],     pq[ni][0]);
            atomicAdd(&colQ[col + 1], pq[ni][1]);
        }
    }
    __syncthreads();
    if (t < 128) {
        atomicAdd(&g_colsum[half][n0 + t], colS[t]);
        atomicAdd(&g_colsq [half][n0 + t], colQ[t]);
    }
}

// ---------------- GEMM2 (tensor, split-bf16): Z = relu(BN(Y)) @ W2^T + b2 ----
// BM=64, BN=128, K=512 in 8 chunks of 64, register-prefetch pipelined
// (grid=128 -> 1 CTA/SM: prefetch hides global latency). BN finalize folded.
__global__ __launch_bounds__(256) void k_gemm2t(const float* __restrict__ b2,
                                                const float* __restrict__ gamma,
                                                const float* __restrict__ beta,
                                                float* __restrict__ out,
                                                int out_size) {
    extern __shared__ __align__(16) uint32_t sw[];
    uint32_t* sAhi = sw;
    uint32_t* sAlo = sw + SAW;
    uint32_t* sBhi = sw + 2 * SAW;
    uint32_t* sBlo = sw + 2 * SAW + SBW;
    float* ssc  = (float*)(sw + 2 * SAW + 2 * SBW);
    float* ssh  = ssc + D_HID;
    float* red  = ssh + D_HID;    // [64][4]
    float* sInv = red + 256;      // [64]

    const int t = threadIdx.x;
    const int wid = t >> 5, lane = t & 31;
    const int gr = lane >> 2, qq = lane & 3;
    const int sel = lane >> 3, li = lane & 7;
    const int warp_m = wid >> 2, warp_n = wid & 3;
    const int m0 = blockIdx.x * 64;
    const int half = (m0 >= B_ROWS);

    for (int c = t; c < D_HID; c += 256) {
        float mean = g_colsum[half][c] * (1.f / B_ROWS);
        float var  = g_colsq [half][c] * (1.f / B_ROWS) - mean * mean;
        float scv  = gamma[c] * rsqrtf(var + BN_EPS);
        ssc[c] = scv;
        ssh[c] = beta[c] - mean * scv;
    }
    __syncthreads();

    float acc[2][4][4];
#pragma unroll
    for (int mi = 0; mi < 2; mi++)
#pragma unroll
        for (int ni = 0; ni < 4; ni++)
#pragma unroll
            for (int r = 0; r < 4; r++) acc[mi][ni][r] = 0.f;

    const int arow = t >> 2, acq = (t & 3) * 16;
    const int brow = t >> 1, bcq = (t & 1) * 32;
    const float* pA = g_Y + (size_t)(m0 + arow) * D_HID + acq;
    const __nv_bfloat16* pBh = g_W2h + (size_t)brow * D_HID + bcq;
    const __nv_bfloat16* pBl = g_W2l + (size_t)brow * D_HID + bcq;
    const int aw = arow * PW + (acq >> 1);
    const int bw = brow * PW + (bcq >> 1);

    const uint32_t sAhiU = smem_u32(sAhi), sAloU = smem_u32(sAlo);
    const uint32_t sBhiU = smem_u32(sBhi), sBloU = smem_u32(sBlo);
    uint32_t aoff[2], boff[2];
#pragma unroll
    for (int mi = 0; mi < 2; mi++)
        aoff[mi] = (uint32_t)(warp_m * 32 + mi * 16 + (sel & 1) * 8 + li) * 144u
                 + (uint32_t)(sel >> 1) * 16u;
#pragma unroll
    for (int nip = 0; nip < 2; nip++)
        boff[nip] = (uint32_t)(warp_n * 32 + nip * 16 + (sel >> 1) * 8 + li) * 144u
                  + (uint32_t)(sel & 1) * 16u;

    // register-prefetch pipeline
    float4 rA[4];
    uint4 rBh[4], rBl[4];
#pragma unroll
    for (int j = 0; j < 4; j++) {
        rA[j]  = *(const float4*)(pA + j * 4);
        rBh[j] = *(const uint4*)(pBh + j * 8);
        rBl[j] = *(const uint4*)(pBl + j * 8);
    }

    for (int it = 0; it < 8; it++) {
        const int kb = it * 64;
        // store current regs to smem (A: BN + relu + split)
        {
#pragma unroll
            for (int j = 0; j < 4; j++) {
                int k = kb + acq + j * 4;
                float f0 = fmaxf(fmaf(rA[j].x, ssc[k],     ssh[k]),     0.f);
                float f1 = fmaxf(fmaf(rA[j].y, ssc[k + 1], ssh[k + 1]), 0.f);
                float f2 = fmaxf(fmaf(rA[j].z, ssc[k + 2], ssh[k + 2]), 0.f);
                float f3 = fmaxf(fmaf(rA[j].w, ssc[k + 3], ssh[k + 3]), 0.f);
                uint32_t h0, l0, h1v, l1;
                split2(f0, f1, h0, l0);
                split2(f2, f3, h1v, l1);
                uint2 hh = {h0, h1v}, ll = {l0, l1};
                *(uint2*)(sAhi + aw + j * 2) = hh;
                *(uint2*)(sAlo + aw + j * 2) = ll;
                *(uint4*)(sBhi + bw + j * 4) = rBh[j];
                *(uint4*)(sBlo + bw + j * 4) = rBl[j];
            }
        }
        __syncthreads();
        // prefetch next chunk while MMAs run
        if (it < 7) {
            int kn = kb + 64;
#pragma unroll
            for (int j = 0; j < 4; j++) {
                rA[j]  = *(const float4*)(pA + kn + j * 4);
                rBh[j] = *(const uint4*)(pBh + kn + j * 8);
                rBl[j] = *(const uint4*)(pBl + kn + j * 8);
            }
        }
#pragma unroll
        for (int ks = 0; ks < 4; ks++) {
            uint32_t koff = (uint32_t)ks * 32u;
            uint32_t ah[2][4], al[2][4], bh[4][2], bl[4][2], tmp[4];
            ldsm4(ah[0], sAhiU + aoff[0] + koff);
            ldsm4(ah[1], sAhiU + aoff[1] + koff);
            ldsm4(al[0], sAloU + aoff[0] + koff);
            ldsm4(al[1], sAloU + aoff[1] + koff);
            ldsm4(tmp, sBhiU + boff[0] + koff);
            bh[0][0]=tmp[0]; bh[0][1]=tmp[1]; bh[1][0]=tmp[2]; bh[1][1]=tmp[3];
            ldsm4(tmp, sBhiU + boff[1] + koff);
            bh[2][0]=tmp[0]; bh[2][1]=tmp[1]; bh[3][0]=tmp[2]; bh[3][1]=tmp[3];
            ldsm4(tmp, sBloU + boff[0] + koff);
            bl[0][0]=tmp[0]; bl[0][1]=tmp[1]; bl[1][0]=tmp[2]; bl[1][1]=tmp[3];
            ldsm4(tmp, sBloU + boff[1] + koff);
            bl[2][0]=tmp[0]; bl[2][1]=tmp[1]; bl[3][0]=tmp[2]; bl[3][1]=tmp[3];
#pragma unroll
            for (int mi = 0; mi < 2; mi++)
#pragma unroll
                for (int ni = 0; ni < 4; ni++) {
                    mma16816(acc[mi][ni], ah[mi], bh[ni]);
                    mma16816(acc[mi][ni], ah[mi], bl[ni]);
                    mma16816(acc[mi][ni], al[mi], bh[ni]);
                }
        }
        __syncthreads();
    }

    float rp[2][2] = {{0.f, 0.f}, {0.f, 0.f}};
#pragma unroll
    for (int ni = 0; ni < 4; ni++) {
        int col = warp_n * 32 + ni * 8 + qq * 2;
        float2 bb = *(const float2*)&b2[col];
#pragma unroll
        for (int mi = 0; mi < 2; mi++) {
            acc[mi][ni][0] += bb.x; acc[mi][ni][1] += bb.y;
            acc[mi][ni][2] += bb.x; acc[mi][ni][3] += bb.y;
            rp[mi][0] = fmaf(acc[mi][ni][0], acc[mi][ni][0],
                        fmaf(acc[mi][ni][1], acc[mi][ni][1], rp[mi][0]));
            rp[mi][1] = fmaf(acc[mi][ni][2], acc[mi][ni][2],
                        fmaf(acc[mi][ni][3], acc[mi][ni][3], rp[mi][1]));
        }
    }
#pragma unroll
    for (int mi = 0; mi < 2; mi++)
#pragma unroll
        for (int rh = 0; rh < 2; rh++) {
            float s = rp[mi][rh];
            s += __shfl_xor_sync(~0u, s, 1);
            s += __shfl_xor_sync(~0u, s, 2);
            rp[mi][rh] = s;
        }
    if (qq == 0) {
#pragma unroll
        for (int mi = 0; mi < 2; mi++) {
            red[(warp_m * 32 + mi * 16 + gr)     * 4 + warp_n] = rp[mi][0];
            red[(warp_m * 32 + mi * 16 + gr + 8) * 4 + warp_n] = rp[mi][1];
        }
    }
    __syncthreads();
    if (t < 64) {
        float s = red[t * 4] + red[t * 4 + 1] + red[t * 4 + 2] + red[t * 4 + 3];
        sInv[t] = 1.f / fmaxf(sqrtf(s), L2_EPS);
    }
    __syncthreads();
    bool full = (out_size > M2 * D_OUTF);
#pragma unroll
    for (int mi = 0; mi < 2; mi++)
#pragma unroll
        for (int rh = 0; rh < 2; rh++) {
            int r = warp_m * 32 + mi * 16 + gr + rh * 8;
            float inv = sInv[r];
            int m = m0 + r;
#pragma unroll
            for (int ni = 0; ni < 4; ni++) {
                int col = warp_n * 32 + ni * 8 + qq * 2;
                float z0 = acc[mi][ni][rh * 2]     * inv;
                float z1 = acc[mi][ni][rh * 2 + 1] * inv;
                if (full) {
                    // out+1 is only 4B-aligned: scalar stores
                    out[1 + (size_t)m * D_OUTF + col]     = z0;
                    out[1 + (size_t)m * D_OUTF + col + 1] = z1;
                } else {
                    float2 zz = {z0, z1};
                    *(float2*)&g_Z[(size_t)m * D_OUTF + col] = zz;
                }
                *(__nv_bfloat162*)&g_Zh[(size_t)m * D_OUTF + col] =
                    __floats2bfloat162_rn(z0 * ZH_SCALE, z1 * ZH_SCALE);
            }
        }
}

// ---------------- paired tensor-core sim: 128x256 tile per CTA --------------
#define SIM_PITCH_B 272                        // 128 cols bf16 + 16B pad
#define SIM_TILE_BYTES (128 * SIM_PITCH_B)     // 34816
#define SIM_SMEM_SIZE (3 * SIM_TILE_BYTES + 3 * 128 * 4)

__device__ __forceinline__ int pair_off(int bi) {
    int h = bi >> 1, r = bi & 1;
    return 32 * bi - h * (h - 1 + r);
}

__global__ __launch_bounds__(256, 2) void k_simp() {
    extern __shared__ __align__(16) char smem[];
    char* sA  = smem;
    char* sB0 = smem + SIM_TILE_BYTES;
    char* sB1 = smem + 2 * SIM_TILE_BYTES;
    float* srow  = (float*)(smem + 3 * SIM_TILE_BYTES);
    float* scol0 = srow + 128;
    float* scol1 = srow + 256;

    const int t = threadIdx.x;
    const int wid = t >> 5, lane = t & 31;
    const int gr = lane >> 2, qq = lane & 3;
    const int sel = lane >> 3, li = lane & 7;
    const int warp_m = wid >> 2, warp_n = wid & 3;

    int tb = blockIdx.x;
    float disc = fmaxf(4096.f - 4.f * (float)tb, 0.f);
    int bi = (int)(64.f - sqrtf(disc));
    if (bi < 0) bi = 0; if (bi > 63) bi = 63;
    while (bi < 63 && pair_off(bi + 1) <= tb) ++bi;
    while (bi > 0 && pair_off(bi) > tb) --bi;
    int c = (bi >> 1) + (tb - pair_off(bi));
    const size_t i0  = (size_t)bi * 128;
    const int bj0 = 2 * c, bj1 = 2 * c + 1;
    const size_t j00 = (size_t)bj0 * 128;
    const size_t j01 = (size_t)bj1 * 128;
    const bool sub0  = (bj0 >= bi);
    const bool col0  = (bj0 > bi);
    const bool col1  = (bj1 > bi);

    const uint32_t sAu  = smem_u32(sA);
    const uint32_t sB0u = smem_u32(sB0);
    const uint32_t sB1u = smem_u32(sB1);
    const char* gA  = (const char*)(g_Zh + i0  * D_OUTF);
    const char* gB0 = (const char*)(g_Zh + j00 * D_OUTF);
    const char* gB1 = (const char*)(g_Zh + j01 * D_OUTF);
#pragma unroll
    for (int it = 0; it < 8; it++) {
        int q = t + it * 256;
        uint32_t so = (uint32_t)(q >> 4) * SIM_PITCH_B + (uint32_t)(q & 15) * 16u;
        cpa16(sAu + so,  gA  + q * 16);
        cpa16(sB0u + so, gB0 + q * 16);
        cpa16(sB1u + so, gB1 + q * 16);
    }
    if (t < 128) { srow[t] = 0.f; scol0[t] = 0.f; scol1[t] = 0.f; }
    cpa_wait_all();
    __syncthreads();

    uint32_t aBase[4], bB0[2], bB1[2];
#pragma unroll
    for (int mi = 0; mi < 4; mi++)
        aBase[mi] = sAu + (uint32_t)(warp_m * 64 + mi * 16 + (sel & 1) * 8 + li) * SIM_PITCH_B
                  + (uint32_t)(sel >> 1) * 16u;
#pragma unroll
    for (int nip = 0; nip < 2; nip++) {
        uint32_t ro = (uint32_t)(warp_n * 32 + nip * 16 + (sel >> 1) * 8 + li) * SIM_PITCH_B
                    + (uint32_t)(sel & 1) * 16u;
        bB0[nip] = sB0u + ro;
        bB1[nip] = sB1u + ro;
    }

    float rsum[8];
#pragma unroll
    for (int i = 0; i < 8; i++) rsum[i] = 0.f;

    for (int sub = 0; sub < 2; sub++) {
        if (sub == 0 && !sub0) continue;
        const uint32_t* bBase = sub ? bB1 : bB0;
        const bool colAdd = sub ? col1 : col0;
        float* scol = sub ? scol1 : scol0;

        float cc[4][4][4];
#pragma unroll
        for (int mi = 0; mi < 4; mi++)
#pragma unroll
            for (int ni = 0; ni < 4; ni++)
#pragma unroll
                for (int r = 0; r < 4; r++) cc[mi][ni][r] = 0.f;

#pragma unroll
        for (int ks = 0; ks < 8; ks++) {
            uint32_t koff = (uint32_t)ks * 32u;
            uint32_t a[4][4], b[4][2], tmp[4];
#pragma unroll
            for (int mi = 0; mi < 4; mi++) ldsm4(a[mi], aBase[mi] + koff);
            ldsm4(tmp, bBase[0] + koff);
            b[0][0]=tmp[0]; b[0][1]=tmp[1]; b[1][0]=tmp[2]; b[1][1]=tmp[3];
            ldsm4(tmp, bBase[1] + koff);
            b[2][0]=tmp[0]; b[2][1]=tmp[1]; b[3][0]=tmp[2]; b[3][1]=tmp[3];
#pragma unroll
            for (int mi = 0; mi < 4; mi++)
#pragma unroll
                for (int ni = 0; ni < 4; ni++)
                    mma16816(cc[mi][ni], a[mi], b[ni]);
        }

        float csum[8];
#pragma unroll
        for (int i = 0; i < 8; i++) csum[i] = 0.f;
#pragma unroll
        for (int mi = 0; mi < 4; mi++)
#pragma unroll
            for (int ni = 0; ni < 4; ni++) {
                float e0 = ex2(cc[mi][ni][0]);
                float e1 = ex2(cc[mi][ni][1]);
                float e2 = ex2(cc[mi][ni][2]);
                float e3 = ex2(cc[mi][ni][3]);
                rsum[mi * 2 + 0] += e0 + e1;
                rsum[mi * 2 + 1] += e2 + e3;
                csum[ni * 2 + 0] += e0 + e2;
                csum[ni * 2 + 1] += e1 + e3;
            }
        if (colAdd) {
#pragma unroll
            for (int i = 0; i < 8; i++) {
                csum[i] += __shfl_xor_sync(0xffffffffu, csum[i], 4);
                csum[i] += __shfl_xor_sync(0xffffffffu, csum[i], 8);
                csum[i] += __shfl_xor_sync(0xffffffffu, csum[i], 16);
            }
            if (gr == 0) {
#pragma unroll
                for (int ni = 0; ni < 4; ni++) {
                    atomicAdd(&scol[warp_n * 32 + ni * 8 + qq * 2],     csum[ni * 2 + 0]);
                    atomicAdd(&scol[warp_n * 32 + ni * 8 + qq * 2 + 1], csum[ni * 2 + 1]);
                }
            }
        }
    }

#pragma unroll
    for (int i = 0; i < 8; i++) {
        rsum[i] += __shfl_xor_sync(0xffffffffu, rsum[i], 1);
        rsum[i] += __shfl_xor_sync(0xffffffffu, rsum[i], 2);
    }
    if (qq == 0) {
#pragma unroll
        for (int mi = 0; mi < 4; mi++) {
            atomicAdd(&srow[warp_m * 64 + mi * 16 + gr],     rsum[mi * 2 + 0]);
            atomicAdd(&srow[warp_m * 64 + mi * 16 + gr + 8], rsum[mi * 2 + 1]);
        }
    }
    __syncthreads();
    if (t < 128) {
        atomicAdd(&g_sumexp[i0 + t], srow[t]);
        if (col0) atomicAdd(&g_sumexp[j00 + t], scol0[t]);
        if (col1) atomicAdd(&g_sumexp[j01 + t], scol1[t]);
    }
}

// ---------------- finish: loss = mean(lse_i - pos_i); emits out[0] ----------
__global__ void k_finish(float* __restrict__ out, int out_size) {
    int w    = (blockIdx.x * blockDim.x + threadIdx.x) >> 5;
    int lane = threadIdx.x & 31;
    if (w >= B_ROWS) return;
    bool full = (out_size > M2 * D_OUTF);
    const float* zsrc = full ? (out + 1) : g_Z;
    // zsrc may be only 4B-aligned (out+1): scalar loads
    const float* p1 = zsrc + (size_t)w * D_OUTF + lane * 4;
    const float* p2 = zsrc + (size_t)(w + B_ROWS) * D_OUTF + lane * 4;
    float dp = 0.f;
#pragma unroll
    for (int j = 0; j < 4; j++) dp = fmaf(p1[j], p2[j], dp);
    const __nv_bfloat16* z1 = g_Zh + (size_t)w * D_OUTF + lane * 4;
    const __nv_bfloat16* z2 = g_Zh + (size_t)(w + B_ROWS) * D_OUTF + lane * 4;
    float d1 = 0.f, d2 = 0.f;
#pragma unroll
    for (int j = 0; j < 4; j++) {
        float v1 = __bfloat162float(z1[j]);
        float v2 = __bfloat162float(z2[j]);
        d1 = fmaf(v1, v1, d1);
        d2 = fmaf(v2, v2, d2);
    }
#pragma unroll
    for (int o = 16; o; o >>= 1) {
        dp += __shfl_down_sync(0xffffffffu, dp, o);
        d1 += __shfl_down_sync(0xffffffffu, d1, o);
        d2 += __shfl_down_sync(0xffffffffu, d2, o);
    }
    if (lane == 0) {
        float pos  = dp * INV_T;
        float lse1 = logf(g_sumexp[w]          - ex2(d1));
        float lse2 = logf(g_sumexp[w + B_ROWS] - ex2(d2));
        atomicAdd(&g_loss[0], (lse1 + lse2 - 2.f * pos) * (1.f / M2));
        __threadfence();
        unsigned prev = atomicAdd(&g_done, 1u);
        if (prev == B_ROWS - 1) {
            if (out_size > 0) out[0] = g_loss[0];
            g_done = 0u;   // reset for next graph replay
        }
    }
}

// ---------------- launch -----------------------------------------------------
extern "C" void kernel_launch(void* const* d_in, const int* in_sizes, int n_in,
                              void* d_out, int out_size) {
    const float* h1    = (const float*)d_in[0];
    const float* h2    = (const float*)d_in[1];
    const float* W1    = (const float*)d_in[2];
    const float* b1    = (const float*)d_in[3];
    const float* gamma = (const float*)d_in[4];
    const float* beta  = (const float*)d_in[5];
    const float* W2    = (const float*)d_in[6];
    const float* b2    = (const float*)d_in[7];
    float* out = (float*)d_out;

    cudaFuncSetAttribute(k_gemm1t, cudaFuncAttributeMaxDynamicSharedMemorySize, GSM1_BYTES);
    cudaFuncSetAttribute(k_gemm2t, cudaFuncAttributeMaxDynamicSharedMemorySize, GSM2_BYTES);
    cudaFuncSetAttribute(k_simp,   cudaFuncAttributeMaxDynamicSharedMemorySize, SIM_SMEM_SIZE);

    k_prep   <<<160, 256>>>(W1, W2);
    k_gemm1t <<<dim3(4, 128), 256, GSM1_BYTES>>>(h1, h2, b1);
    k_gemm2t <<<128, 256, GSM2_BYTES>>>(b2, gamma, beta, out, out_size);
    k_simp   <<<1056, 256, SIM_SMEM_SIZE>>>();
    k_finish <<<512, 256>>>(out, out_size);
}

// round 15
// speedup vs baseline: 1.1689x; 1.0026x over previous
#include <cuda_runtime.h>
#include <cuda_bf16.h>
#include <math.h>
#include <stdint.h>

#define B_ROWS 4096
#define D_INF  192
#define D_HID  512
#define D_OUTF 128
#define M2     8192      // 2*B
#define INV_T  2.0f      // 1/TEMPERATURE
#define BN_EPS 1e-5f
#define L2_EPS 1e-12f
// zh = z * sqrt(2*log2(e)): zh_i.zh_j = 2*log2e*(z_i.z_j); exp((z.z)/T) = exp2(zh.zh)
#define ZH_SCALE 1.69864361f

// ---------------- scratch (static device globals; no allocation) ------------
__device__ __align__(128) float g_Y[(size_t)M2 * D_HID];     // 16 MB
__device__ __align__(128) float g_Z[(size_t)M2 * D_OUTF];    // fallback only
__device__ __align__(128) __nv_bfloat16 g_Zh[(size_t)M2 * D_OUTF]; // scaled bf16 z
__device__ __align__(128) __nv_bfloat16 g_W1h[D_HID * D_INF];
__device__ __align__(128) __nv_bfloat16 g_W1l[D_HID * D_INF];
__device__ __align__(128) __nv_bfloat16 g_W2h[D_OUTF * D_HID];
__device__ __align__(128) __nv_bfloat16 g_W2l[D_OUTF * D_HID];
__device__ float g_colsum[2][D_HID];
__device__ float g_colsq[2][D_HID];
__device__ float g_sumexp[M2];
__device__ float g_loss[1];
__device__ unsigned g_done;

// ---------------- helpers ----------------------------------------------------
__device__ __forceinline__ uint32_t smem_u32(const void* p) {
    uint32_t a;
    asm("{ .reg .u64 t; cvta.to.shared.u64 t, %1; cvt.u32.u64 %0, t; }" : "=r"(a) : "l"(p));
    return a;
}
__device__ __forceinline__ void ldsm4(uint32_t* r, uint32_t addr) {
    asm volatile("ldmatrix.sync.aligned.m8n8.x4.shared.b16 {%0,%1,%2,%3}, [%4];"
                 : "=r"(r[0]), "=r"(r[1]), "=r"(r[2]), "=r"(r[3]) : "r"(addr));
}
__device__ __forceinline__ void mma16816(float* c, const uint32_t* a, const uint32_t* b) {
    asm volatile(
        "mma.sync.aligned.m16n8k16.row.col.f32.bf16.bf16.f32 "
        "{%0,%1,%2,%3}, {%4,%5,%6,%7}, {%8,%9}, {%0,%1,%2,%3};"
        : "+f"(c[0]), "+f"(c[1]), "+f"(c[2]), "+f"(c[3])
        : "r"(a[0]), "r"(a[1]), "r"(a[2]), "r"(a[3]), "r"(b[0]), "r"(b[1]));
}
__device__ __forceinline__ float ex2(float x) {
    float y;
    asm("ex2.approx.f32 %0, %1;" : "=f"(y) : "f"(x));
    return y;
}
__device__ __forceinline__ void cpa16(uint32_t saddr, const void* gaddr) {
    asm volatile("cp.async.cg.shared.global [%0], [%1], 16;"
                 :: "r"(saddr), "l"(gaddr) : "memory");
}
__device__ __forceinline__ void cpa_wait_all() {
    asm volatile("cp.async.commit_group;\n\tcp.async.wait_group 0;" ::: "memory");
}
// split fp32 pair into bf16x2 hi + bf16x2 lo (x = hi + lo, err ~2^-18)
__device__ __forceinline__ void split2(float f0, float f1, uint32_t& hi, uint32_t& lo) {
    __nv_bfloat162 h = __floats2bfloat162_rn(f0, f1);
    __nv_bfloat162 l = __floats2bfloat162_rn(f0 - __bfloat162float(h.x),
                                             f1 - __bfloat162float(h.y));
    hi = *reinterpret_cast<uint32_t*>(&h);
    lo = *reinterpret_cast<uint32_t*>(&l);
}

// smem tile geometry (pitch 36 words = 72 bf16 = 144 bytes)
#define PW   36
#define SAW  (64 * PW)     // gemm2 A tile: 64 rows
#define SA1W (128 * PW)    // gemm1 A tile: 128 rows
#define SBW  (128 * PW)    // B tile: 128 rows
#define GSM1_BYTES (((2 * SA1W + 2 * SBW) * 4) + 1024)           // 74752
#define GSM2_BYTES (((2 * SAW + 2 * SBW) * 4) + 4096 + 1280)     // 60672

// ---------------- prep: init + split WEIGHTS to hi/lo bf16 (once) -----------
__global__ __launch_bounds__(256) void k_prep(const float* __restrict__ W1,
                                              const float* __restrict__ W2) {
    int i = blockIdx.x * blockDim.x + threadIdx.x;
    if (i < M2) g_sumexp[i] = 0.f;
    if (i < 2 * D_HID) {
        g_colsum[i >> 9][i & 511] = 0.f;
        g_colsq [i >> 9][i & 511] = 0.f;
    }
    if (i == 0) { g_loss[0] = 0.f; g_done = 0u; }

    const int NW14 = (D_HID * D_INF) / 4;    // 24576
    const int NW24 = (D_OUTF * D_HID) / 4;   // 16384
    const float* src;
    __nv_bfloat16 *dh, *dl;
    int off;
    if (i < NW14)             { src = W1; dh = g_W1h; dl = g_W1l; off = i; }
    else if (i < NW14 + NW24) { src = W2; dh = g_W2h; dl = g_W2l; off = i - NW14; }
    else return;
    float4 v = *(const float4*)(src + (size_t)off * 4);
    uint32_t a0, b0, a1, b1v;
    split2(v.x, v.y, a0, b0);
    split2(v.z, v.w, a1, b1v);
    uint2 hh = {a0, a1}, ll = {b0, b1v};
    *(uint2*)(dh + (size_t)off * 4) = hh;
    *(uint2*)(dl + (size_t)off * 4) = ll;
}

// ---------------- GEMM1 (tensor, split-bf16): Y = H @ W1^T + b1 + BN partials
// BM=128, BN=128, K=192 in 3 chunks of 64. 8 warps (2m x 4n), warp tile 64x32
// (same fragment geometry as k_simp). A split in-register from fp32 H.
__global__ __launch_bounds__(256) void k_gemm1t(const float* __restrict__ h1,
                                                const float* __restrict__ h2,
                                                const float* __restrict__ b1) {
    extern __shared__ __align__(16) uint32_t sw[];
    uint32_t* sAhi = sw;
    uint32_t* sAlo = sw + SA1W;
    uint32_t* sBhi = sw + 2 * SA1W;
    uint32_t* sBlo = sw + 2 * SA1W + SBW;
    float* colS = (float*)(sw + 2 * SA1W + 2 * SBW);
    float* colQ = colS + 128;

    const int t = threadIdx.x;
    const int wid = t >> 5, lane = t & 31;
    const int gr = lane >> 2, qq = lane & 3;
    const int sel = lane >> 3, li = lane & 7;
    const int warp_m = wid >> 2, warp_n = wid & 3;
    const int n0 = blockIdx.x * 128;
    const int m0 = blockIdx.y * 128;
    const int half = (m0 >= B_ROWS);
    const float* H = half ? (h2 + (size_t)(m0 - B_ROWS) * D_INF)
                          : (h1 + (size_t)m0 * D_INF);

    if (t < 128) { colS[t] = 0.f; colQ[t] = 0.f; }

    float acc[4][4][4];
#pragma unroll
    for (int mi = 0; mi < 4; mi++)
#pragma unroll
        for (int ni = 0; ni < 4; ni++)
#pragma unroll
            for (int r = 0; r < 4; r++) acc[mi][ni][r] = 0.f;

    const int arow = t >> 1, acq = (t & 1) * 32;    // 128 rows, 32 floats/thread
    const int brow = t >> 1, bcq = (t & 1) * 32;
    const float* pAf = H + (size_t)arow * D_INF + acq;
    const __nv_bfloat16* pBh = g_W1h + (size_t)(n0 + brow) * D_INF + bcq;
    const __nv_bfloat16* pBl = g_W1l + (size_t)(n0 + brow) * D_INF + bcq;
    const int aw = arow * PW + (acq >> 1);
    const int bw = brow * PW + (bcq >> 1);

    const uint32_t sAhiU = smem_u32(sAhi), sAloU = smem_u32(sAlo);
    const uint32_t sBhiU = smem_u32(sBhi), sBloU = smem_u32(sBlo);
    uint32_t aoff[4], boff[2];
#pragma unroll
    for (int mi = 0; mi < 4; mi++)
        aoff[mi] = (uint32_t)(warp_m * 64 + mi * 16 + (sel & 1) * 8 + li) * 144u
                 + (uint32_t)(sel >> 1) * 16u;
#pragma unroll
    for (int nip = 0; nip < 2; nip++)
        boff[nip] = (uint32_t)(warp_n * 32 + nip * 16 + (sel >> 1) * 8 + li) * 144u
                  + (uint32_t)(sel & 1) * 16u;

    for (int kb = 0; kb < D_INF; kb += 64) {
        {
#pragma unroll
            for (int j = 0; j < 8; j++) {
                float4 v = *(const float4*)(pAf + kb + j * 4);
                uint32_t h0, l0, h1v, l1;
                split2(v.x, v.y, h0, l0);
                split2(v.z, v.w, h1v, l1);
                uint2 hh = {h0, h1v}, ll = {l0, l1};
                *(uint2*)(sAhi + aw + j * 2) = hh;
                *(uint2*)(sAlo + aw + j * 2) = ll;
            }
#pragma unroll
            for (int j = 0; j < 4; j++) {
                uint4 vh = *(const uint4*)(pBh + kb + j * 8);
                uint4 vl = *(const uint4*)(pBl + kb + j * 8);
                *(uint4*)(sBhi + bw + j * 4) = vh;
                *(uint4*)(sBlo + bw + j * 4) = vl;
            }
        }
        __syncthreads();
#pragma unroll
        for (int ks = 0; ks < 4; ks++) {
            uint32_t koff = (uint32_t)ks * 32u;
            uint32_t ah[4][4], al[4][4], bh[4][2], bl[4][2], tmp[4];
#pragma unroll
            for (int mi = 0; mi < 4; mi++) {
                ldsm4(ah[mi], sAhiU + aoff[mi] + koff);
                ldsm4(al[mi], sAloU + aoff[mi] + koff);
            }
            ldsm4(tmp, sBhiU + boff[0] + koff);
            bh[0][0]=tmp[0]; bh[0][1]=tmp[1]; bh[1][0]=tmp[2]; bh[1][1]=tmp[3];
            ldsm4(tmp, sBhiU + boff[1] + koff);
            bh[2][0]=tmp[0]; bh[2][1]=tmp[1]; bh[3][0]=tmp[2]; bh[3][1]=tmp[3];
            ldsm4(tmp, sBloU + boff[0] + koff);
            bl[0][0]=tmp[0]; bl[0][1]=tmp[1]; bl[1][0]=tmp[2]; bl[1][1]=tmp[3];
            ldsm4(tmp, sBloU + boff[1] + koff);
            bl[2][0]=tmp[0]; bl[2][1]=tmp[1]; bl[3][0]=tmp[2]; bl[3][1]=tmp[3];
#pragma unroll
            for (int mi = 0; mi < 4; mi++)
#pragma unroll
                for (int ni = 0; ni < 4; ni++) {
                    mma16816(acc[mi][ni], ah[mi], bh[ni]);
                    mma16816(acc[mi][ni], ah[mi], bl[ni]);
                    mma16816(acc[mi][ni], al[mi], bh[ni]);
                }
        }
        __syncthreads();
    }

    // epilogue: bias, store Y, per-column sum/sumsq partials
    float ps[4][2], pq[4][2];
#pragma unroll
    for (int ni = 0; ni < 4; ni++) { ps[ni][0]=ps[ni][1]=pq[ni][0]=pq[ni][1]=0.f; }
#pragma unroll
    for (int ni = 0; ni < 4; ni++) {
        int col = warp_n * 32 + ni * 8 + qq * 2;
        float2 bb = *(const float2*)&b1[n0 + col];
#pragma unroll
        for (int mi = 0; mi < 4; mi++) {
            int r = warp_m * 64 + mi * 16 + gr;
            float y0 = acc[mi][ni][0] + bb.x;
            float y1 = acc[mi][ni][1] + bb.y;
            float y2 = acc[mi][ni][2] + bb.x;
            float y3 = acc[mi][ni][3] + bb.y;
            float2 p0 = {y0, y1}, p1 = {y2, y3};
            *(float2*)&g_Y[(size_t)(m0 + r)     * D_HID + n0 + col] = p0;
            *(float2*)&g_Y[(size_t)(m0 + r + 8) * D_HID + n0 + col] = p1;
            ps[ni][0] += y0 + y2;              ps[ni][1] += y1 + y3;
            pq[ni][0] += y0 * y0 + y2 * y2;    pq[ni][1] += y1 * y1 + y3 * y3;
        }
    }
#pragma unroll
    for (int ni = 0; ni < 4; ni++)
#pragma unroll
        for (int c2 = 0; c2 < 2; c2++) {
            float s = ps[ni][c2], q = pq[ni][c2];
            s += __shfl_xor_sync(~0u, s, 4);  q += __shfl_xor_sync(~0u, q, 4);
            s += __shfl_xor_sync(~0u, s, 8);  q += __shfl_xor_sync(~0u, q, 8);
            s += __shfl_xor_sync(~0u, s, 16); q += __shfl_xor_sync(~0u, q, 16);
            ps[ni][c2] = s; pq[ni][c2] = q;
        }
    if (gr == 0) {
#pragma unroll
        for (int ni = 0; ni < 4; ni++) {
            int col = warp_n * 32 + ni * 8 + qq * 2;
            atomicAdd(&colS[col],     ps[ni][0]);
            atomicAdd(&colS[col + 1], ps[ni][1]);
            atomicAdd(&colQ[col],     pq[ni][0]);
            atomicAdd(&colQ[col + 1], pq[ni][1]);
        }
    }
    __syncthreads();
    if (t < 128) {
        atomicAdd(&g_colsum[half][n0 + t], colS[t]);
        atomicAdd(&g_colsq [half][n0 + t], colQ[t]);
    }
}

// ---------------- GEMM2 (tensor, split-bf16): Z = relu(BN(Y)) @ W2^T + b2 ----
// BM=64, BN=128, K=512 in 8 chunks of 64, register-prefetch pipelined.
__global__ __launch_bounds__(256) void k_gemm2t(const float* __restrict__ b2,
                                                const float* __restrict__ gamma,
                                                const float* __restrict__ beta,
                                                float* __restrict__ out,
                                                int out_size) {
    extern __shared__ __align__(16) uint32_t sw[];
    uint32_t* sAhi = sw;
    uint32_t* sAlo = sw + SAW;
    uint32_t* sBhi = sw + 2 * SAW;
    uint32_t* sBlo = sw + 2 * SAW + SBW;
    float* ssc  = (float*)(sw + 2 * SAW + 2 * SBW);
    float* ssh  = ssc + D_HID;
    float* red  = ssh + D_HID;    // [64][4]
    float* sInv = red + 256;      // [64]

    const int t = threadIdx.x;
    const int wid = t >> 5, lane = t & 31;
    const int gr = lane >> 2, qq = lane & 3;
    const int sel = lane >> 3, li = lane & 7;
    const int warp_m = wid >> 2, warp_n = wid & 3;
    const int m0 = blockIdx.x * 64;
    const int half = (m0 >= B_ROWS);

    for (int c = t; c < D_HID; c += 256) {
        float mean = g_colsum[half][c] * (1.f / B_ROWS);
        float var  = g_colsq [half][c] * (1.f / B_ROWS) - mean * mean;
        float scv  = gamma[c] * rsqrtf(var + BN_EPS);
        ssc[c] = scv;
        ssh[c] = beta[c] - mean * scv;
    }
    __syncthreads();

    float acc[2][4][4];
#pragma unroll
    for (int mi = 0; mi < 2; mi++)
#pragma unroll
        for (int ni = 0; ni < 4; ni++)
#pragma unroll
            for (int r = 0; r < 4; r++) acc[mi][ni][r] = 0.f;

    const int arow = t >> 2, acq = (t & 3) * 16;
    const int brow = t >> 1, bcq = (t & 1) * 32;
    const float* pA = g_Y + (size_t)(m0 + arow) * D_HID + acq;
    const __nv_bfloat16* pBh = g_W2h + (size_t)brow * D_HID + bcq;
    const __nv_bfloat16* pBl = g_W2l + (size_t)brow * D_HID + bcq;
    const int aw = arow * PW + (acq >> 1);
    const int bw = brow * PW + (bcq >> 1);

    const uint32_t sAhiU = smem_u32(sAhi), sAloU = smem_u32(sAlo);
    const uint32_t sBhiU = smem_u32(sBhi), sBloU = smem_u32(sBlo);
    uint32_t aoff[2], boff[2];
#pragma unroll
    for (int mi = 0; mi < 2; mi++)
        aoff[mi] = (uint32_t)(warp_m * 32 + mi * 16 + (sel & 1) * 8 + li) * 144u
                 + (uint32_t)(sel >> 1) * 16u;
#pragma unroll
    for (int nip = 0; nip < 2; nip++)
        boff[nip] = (uint32_t)(warp_n * 32 + nip * 16 + (sel >> 1) * 8 + li) * 144u
                  + (uint32_t)(sel & 1) * 16u;

    // register-prefetch pipeline
    float4 rA[4];
    uint4 rBh[4], rBl[4];
#pragma unroll
    for (int j = 0; j < 4; j++) {
        rA[j]  = *(const float4*)(pA + j * 4);
        rBh[j] = *(const uint4*)(pBh + j * 8);
        rBl[j] = *(const uint4*)(pBl + j * 8);
    }

    for (int it = 0; it < 8; it++) {
        const int kb = it * 64;
        {
#pragma unroll
            for (int j = 0; j < 4; j++) {
                int k = kb + acq + j * 4;
                float f0 = fmaxf(fmaf(rA[j].x, ssc[k],     ssh[k]),     0.f);
                float f1 = fmaxf(fmaf(rA[j].y, ssc[k + 1], ssh[k + 1]), 0.f);
                float f2 = fmaxf(fmaf(rA[j].z, ssc[k + 2], ssh[k + 2]), 0.f);
                float f3 = fmaxf(fmaf(rA[j].w, ssc[k + 3], ssh[k + 3]), 0.f);
                uint32_t h0, l0, h1v, l1;
                split2(f0, f1, h0, l0);
                split2(f2, f3, h1v, l1);
                uint2 hh = {h0, h1v}, ll = {l0, l1};
                *(uint2*)(sAhi + aw + j * 2) = hh;
                *(uint2*)(sAlo + aw + j * 2) = ll;
                *(uint4*)(sBhi + bw + j * 4) = rBh[j];
                *(uint4*)(sBlo + bw + j * 4) = rBl[j];
            }
        }
        __syncthreads();
        if (it < 7) {
            int kn = kb + 64;
#pragma unroll
            for (int j = 0; j < 4; j++) {
                rA[j]  = *(const float4*)(pA + kn + j * 4);
                rBh[j] = *(const uint4*)(pBh + kn + j * 8);
                rBl[j] = *(const uint4*)(pBl + kn + j * 8);
            }
        }
#pragma unroll
        for (int ks = 0; ks < 4; ks++) {
            uint32_t koff = (uint32_t)ks * 32u;
            uint32_t ah[2][4], al[2][4], bh[4][2], bl[4][2], tmp[4];
            ldsm4(ah[0], sAhiU + aoff[0] + koff);
            ldsm4(ah[1], sAhiU + aoff[1] + koff);
            ldsm4(al[0], sAloU + aoff[0] + koff);
            ldsm4(al[1], sAloU + aoff[1] + koff);
            ldsm4(tmp, sBhiU + boff[0] + koff);
            bh[0][0]=tmp[0]; bh[0][1]=tmp[1]; bh[1][0]=tmp[2]; bh[1][1]=tmp[3];
            ldsm4(tmp, sBhiU + boff[1] + koff);
            bh[2][0]=tmp[0]; bh[2][1]=tmp[1]; bh[3][0]=tmp[2]; bh[3][1]=tmp[3];
            ldsm4(tmp, sBloU + boff[0] + koff);
            bl[0][0]=tmp[0]; bl[0][1]=tmp[1]; bl[1][0]=tmp[2]; bl[1][1]=tmp[3];
            ldsm4(tmp, sBloU + boff[1] + koff);
            bl[2][0]=tmp[0]; bl[2][1]=tmp[1]; bl[3][0]=tmp[2]; bl[3][1]=tmp[3];
#pragma unroll
            for (int mi = 0; mi < 2; mi++)
#pragma unroll
                for (int ni = 0; ni < 4; ni++) {
                    mma16816(acc[mi][ni], ah[mi], bh[ni]);
                    mma16816(acc[mi][ni], ah[mi], bl[ni]);
                    mma16816(acc[mi][ni], al[mi], bh[ni]);
                }
        }
        __syncthreads();
    }

    float rp[2][2] = {{0.f, 0.f}, {0.f, 0.f}};
#pragma unroll
    for (int ni = 0; ni < 4; ni++) {
        int col = warp_n * 32 + ni * 8 + qq * 2;
        float2 bb = *(const float2*)&b2[col];
#pragma unroll
        for (int mi = 0; mi < 2; mi++) {
            acc[mi][ni][0] += bb.x; acc[mi][ni][1] += bb.y;
            acc[mi][ni][2] += bb.x; acc[mi][ni][3] += bb.y;
            rp[mi][0] = fmaf(acc[mi][ni][0], acc[mi][ni][0],
                        fmaf(acc[mi][ni][1], acc[mi][ni][1], rp[mi][0]));
            rp[mi][1] = fmaf(acc[mi][ni][2], acc[mi][ni][2],
                        fmaf(acc[mi][ni][3], acc[mi][ni][3], rp[mi][1]));
        }
    }
#pragma unroll
    for (int mi = 0; mi < 2; mi++)
#pragma unroll
        for (int rh = 0; rh < 2; rh++) {
            float s = rp[mi][rh];
            s += __shfl_xor_sync(~0u, s, 1);
            s += __shfl_xor_sync(~0u, s, 2);
            rp[mi][rh] = s;
        }
    if (qq == 0) {
#pragma unroll
        for (int mi = 0; mi < 2; mi++) {
            red[(warp_m * 32 + mi * 16 + gr)     * 4 + warp_n] = rp[mi][0];
            red[(warp_m * 32 + mi * 16 + gr + 8) * 4 + warp_n] = rp[mi][1];
        }
    }
    __syncthreads();
    if (t < 64) {
        float s = red[t * 4] + red[t * 4 + 1] + red[t * 4 + 2] + red[t * 4 + 3];
        sInv[t] = 1.f / fmaxf(sqrtf(s), L2_EPS);
    }
    __syncthreads();
    bool full = (out_size > M2 * D_OUTF);
#pragma unroll
    for (int mi = 0; mi < 2; mi++)
#pragma unroll
        for (int rh = 0; rh < 2; rh++) {
            int r = warp_m * 32 + mi * 16 + gr + rh * 8;
            float inv = sInv[r];
            int m = m0 + r;
#pragma unroll
            for (int ni = 0; ni < 4; ni++) {
                int col = warp_n * 32 + ni * 8 + qq * 2;
                float z0 = acc[mi][ni][rh * 2]     * inv;
                float z1 = acc[mi][ni][rh * 2 + 1] * inv;
                if (full) {
                    out[1 + (size_t)m * D_OUTF + col]     = z0;
                    out[1 + (size_t)m * D_OUTF + col + 1] = z1;
                } else {
                    float2 zz = {z0, z1};
                    *(float2*)&g_Z[(size_t)m * D_OUTF + col] = zz;
                }
                *(__nv_bfloat162*)&g_Zh[(size_t)m * D_OUTF + col] =
                    __floats2bfloat162_rn(z0 * ZH_SCALE, z1 * ZH_SCALE);
            }
        }
}

// ---------------- paired tensor-core sim: 128x256 tile per CTA --------------
#define SIM_PITCH_B 272                        // 128 cols bf16 + 16B pad
#define SIM_TILE_BYTES (128 * SIM_PITCH_B)     // 34816
#define SIM_SMEM_SIZE (3 * SIM_TILE_BYTES + 3 * 128 * 4)

__device__ __forceinline__ int pair_off(int bi) {
    int h = bi >> 1, r = bi & 1;
    return 32 * bi - h * (h - 1 + r);
}

__global__ __launch_bounds__(256, 2) void k_simp() {
    extern __shared__ __align__(16) char smem[];
    char* sA  = smem;
    char* sB0 = smem + SIM_TILE_BYTES;
    char* sB1 = smem + 2 * SIM_TILE_BYTES;
    float* srow  = (float*)(smem + 3 * SIM_TILE_BYTES);
    float* scol0 = srow + 128;
    float* scol1 = srow + 256;

    const int t = threadIdx.x;
    const int wid = t >> 5, lane = t & 31;
    const int gr = lane >> 2, qq = lane & 3;
    const int sel = lane >> 3, li = lane & 7;
    const int warp_m = wid >> 2, warp_n = wid & 3;

    int tb = blockIdx.x;
    float disc = fmaxf(4096.f - 4.f * (float)tb, 0.f);
    int bi = (int)(64.f - sqrtf(disc));
    if (bi < 0) bi = 0; if (bi > 63) bi = 63;
    while (bi < 63 && pair_off(bi + 1) <= tb) ++bi;
    while (bi > 0 && pair_off(bi) > tb) --bi;
    int c = (bi >> 1) + (tb - pair_off(bi));
    const size_t i0  = (size_t)bi * 128;
    const int bj0 = 2 * c, bj1 = 2 * c + 1;
    const size_t j00 = (size_t)bj0 * 128;
    const size_t j01 = (size_t)bj1 * 128;
    const bool sub0  = (bj0 >= bi);
    const bool col0  = (bj0 > bi);
    const bool col1  = (bj1 > bi);

    const uint32_t sAu  = smem_u32(sA);
    const uint32_t sB0u = smem_u32(sB0);
    const uint32_t sB1u = smem_u32(sB1);
    const char* gA  = (const char*)(g_Zh + i0  * D_OUTF);
    const char* gB0 = (const char*)(g_Zh + j00 * D_OUTF);
    const char* gB1 = (const char*)(g_Zh + j01 * D_OUTF);
#pragma unroll
    for (int it = 0; it < 8; it++) {
        int q = t + it * 256;
        uint32_t so = (uint32_t)(q >> 4) * SIM_PITCH_B + (uint32_t)(q & 15) * 16u;
        cpa16(sAu + so,  gA  + q * 16);
        cpa16(sB0u + so, gB0 + q * 16);
        cpa16(sB1u + so, gB1 + q * 16);
    }
    if (t < 128) { srow[t] = 0.f; scol0[t] = 0.f; scol1[t] = 0.f; }
    cpa_wait_all();
    __syncthreads();

    uint32_t aBase[4], bB0[2], bB1[2];
#pragma unroll
    for (int mi = 0; mi < 4; mi++)
        aBase[mi] = sAu + (uint32_t)(warp_m * 64 + mi * 16 + (sel & 1) * 8 + li) * SIM_PITCH_B
                  + (uint32_t)(sel >> 1) * 16u;
#pragma unroll
    for (int nip = 0; nip < 2; nip++) {
        uint32_t ro = (uint32_t)(warp_n * 32 + nip * 16 + (sel >> 1) * 8 + li) * SIM_PITCH_B
                    + (uint32_t)(sel & 1) * 16u;
        bB0[nip] = sB0u + ro;
        bB1[nip] = sB1u + ro;
    }

    float rsum[8];
#pragma unroll
    for (int i = 0; i < 8; i++) rsum[i] = 0.f;

    for (int sub = 0; sub < 2; sub++) {
        if (sub == 0 && !sub0) continue;
        const uint32_t* bBase = sub ? bB1 : bB0;
        const bool colAdd = sub ? col1 : col0;
        float* scol = sub ? scol1 : scol0;

        float cc[4][4][4];
#pragma unroll
        for (int mi = 0; mi < 4; mi++)
#pragma unroll
            for (int ni = 0; ni < 4; ni++)
#pragma unroll
                for (int r = 0; r < 4; r++) cc[mi][ni][r] = 0.f;

#pragma unroll
        for (int ks = 0; ks < 8; ks++) {
            uint32_t koff = (uint32_t)ks * 32u;
            uint32_t a[4][4], b[4][2], tmp[4];
#pragma unroll
            for (int mi = 0; mi < 4; mi++) ldsm4(a[mi], aBase[mi] + koff);
            ldsm4(tmp, bBase[0] + koff);
            b[0][0]=tmp[0]; b[0][1]=tmp[1]; b[1][0]=tmp[2]; b[1][1]=tmp[3];
            ldsm4(tmp, bBase[1] + koff);
            b[2][0]=tmp[0]; b[2][1]=tmp[1]; b[3][0]=tmp[2]; b[3][1]=tmp[3];
#pragma unroll
            for (int mi = 0; mi < 4; mi++)
#pragma unroll
                for (int ni = 0; ni < 4; ni++)
                    mma16816(cc[mi][ni], a[mi], b[ni]);
        }

        float csum[8];
#pragma unroll
        for (int i = 0; i < 8; i++) csum[i] = 0.f;
#pragma unroll
        for (int mi = 0; mi < 4; mi++)
#pragma unroll
            for (int ni = 0; ni < 4; ni++) {
                float e0 = ex2(cc[mi][ni][0]);
                float e1 = ex2(cc[mi][ni][1]);
                float e2 = ex2(cc[mi][ni][2]);
                float e3 = ex2(cc[mi][ni][3]);
                rsum[mi * 2 + 0] += e0 + e1;
                rsum[mi * 2 + 1] += e2 + e3;
                csum[ni * 2 + 0] += e0 + e2;
                csum[ni * 2 + 1] += e1 + e3;
            }
        if (colAdd) {
#pragma unroll
            for (int i = 0; i < 8; i++) {
                csum[i] += __shfl_xor_sync(0xffffffffu, csum[i], 4);
                csum[i] += __shfl_xor_sync(0xffffffffu, csum[i], 8);
                csum[i] += __shfl_xor_sync(0xffffffffu, csum[i], 16);
            }
            if (gr == 0) {
#pragma unroll
                for (int ni = 0; ni < 4; ni++) {
                    atomicAdd(&scol[warp_n * 32 + ni * 8 + qq * 2],     csum[ni * 2 + 0]);
                    atomicAdd(&scol[warp_n * 32 + ni * 8 + qq * 2 + 1], csum[ni * 2 + 1]);
                }
            }
        }
    }

#pragma unroll
    for (int i = 0; i < 8; i++) {
        rsum[i] += __shfl_xor_sync(0xffffffffu, rsum[i], 1);
        rsum[i] += __shfl_xor_sync(0xffffffffu, rsum[i], 2);
    }
    if (qq == 0) {
#pragma unroll
        for (int mi = 0; mi < 4; mi++) {
            atomicAdd(&srow[warp_m * 64 + mi * 16 + gr],     rsum[mi * 2 + 0]);
            atomicAdd(&srow[warp_m * 64 + mi * 16 + gr + 8], rsum[mi * 2 + 1]);
        }
    }
    __syncthreads();
    if (t < 128) {
        atomicAdd(&g_sumexp[i0 + t], srow[t]);
        if (col0) atomicAdd(&g_sumexp[j00 + t], scol0[t]);
        if (col1) atomicAdd(&g_sumexp[j01 + t], scol1[t]);
    }
}

// ---------------- finish: loss = mean(lse_i - pos_i); emits out[0] ----------
__global__ void k_finish(float* __restrict__ out, int out_size) {
    int w    = (blockIdx.x * blockDim.x + threadIdx.x) >> 5;
    int lane = threadIdx.x & 31;
    if (w >= B_ROWS) return;
    bool full = (out_size > M2 * D_OUTF);
    const float* zsrc = full ? (out + 1) : g_Z;
    const float* p1 = zsrc + (size_t)w * D_OUTF + lane * 4;
    const float* p2 = zsrc + (size_t)(w + B_ROWS) * D_OUTF + lane * 4;
    float dp = 0.f;
#pragma unroll
    for (int j = 0; j < 4; j++) dp = fmaf(p1[j], p2[j], dp);
    const __nv_bfloat16* z1 = g_Zh + (size_t)w * D_OUTF + lane * 4;
    const __nv_bfloat16* z2 = g_Zh + (size_t)(w + B_ROWS) * D_OUTF + lane * 4;
    float d1 = 0.f, d2 = 0.f;
#pragma unroll
    for (int j = 0; j < 4; j++) {
        float v1 = __bfloat162float(z1[j]);
        float v2 = __bfloat162float(z2[j]);
        d1 = fmaf(v1, v1, d1);
        d2 = fmaf(v2, v2, d2);
    }
#pragma unroll
    for (int o = 16; o; o >>= 1) {
        dp += __shfl_down_sync(0xffffffffu, dp, o);
        d1 += __shfl_down_sync(0xffffffffu, d1, o);
        d2 += __shfl_down_sync(0xffffffffu, d2, o);
    }
    if (lane == 0) {
        float pos  = dp * INV_T;
        float lse1 = logf(g_sumexp[w]          - ex2(d1));
        float lse2 = logf(g_sumexp[w + B_ROWS] - ex2(d2));
        atomicAdd(&g_loss[0], (lse1 + lse2 - 2.f * pos) * (1.f / M2));
        __threadfence();
        unsigned prev = atomicAdd(&g_done, 1u);
        if (prev == B_ROWS - 1) {
            if (out_size > 0) out[0] = g_loss[0];
            g_done = 0u;   // reset for next graph replay
        }
    }
}

// ---------------- launch -----------------------------------------------------
extern "C" void kernel_launch(void* const* d_in, const int* in_sizes, int n_in,
                              void* d_out, int out_size) {
    const float* h1    = (const float*)d_in[0];
    const float* h2    = (const float*)d_in[1];
    const float* W1    = (const float*)d_in[2];
    const float* b1    = (const float*)d_in[3];
    const float* gamma = (const float*)d_in[4];
    const float* beta  = (const float*)d_in[5];
    const float* W2    = (const float*)d_in[6];
    const float* b2    = (const float*)d_in[7];
    float* out = (float*)d_out;

    cudaFuncSetAttribute(k_gemm1t, cudaFuncAttributeMaxDynamicSharedMemorySize, GSM1_BYTES);
    cudaFuncSetAttribute(k_gemm2t, cudaFuncAttributeMaxDynamicSharedMemorySize, GSM2_BYTES);
    cudaFuncSetAttribute(k_simp,   cudaFuncAttributeMaxDynamicSharedMemorySize, SIM_SMEM_SIZE);

    k_prep   <<<160, 256>>>(W1, W2);
    k_gemm1t <<<dim3(4, 64), 256, GSM1_BYTES>>>(h1, h2, b1);
    k_gemm2t <<<128, 256, GSM2_BYTES>>>(b2, gamma, beta, out, out_size);
    k_simp   <<<1056, 256, SIM_SMEM_SIZE>>>();
    k_finish <<<512, 256>>>(out, out_size);
}

// round 16
// speedup vs baseline: 1.1957x; 1.0229x over previous
#include <cuda_runtime.h>
#include <cuda_bf16.h>
#include <math.h>
#include <stdint.h>

#define B_ROWS 4096
#define D_INF  192
#define D_HID  512
#define D_OUTF 128
#define M2     8192      // 2*B
#define INV_T  2.0f      // 1/TEMPERATURE
#define BN_EPS 1e-5f
#define L2_EPS 1e-12f
// zh = z * sqrt(2*log2(e)): zh_i.zh_j = 2*log2e*(z_i.z_j); exp((z.z)/T) = exp2(zh.zh)
#define ZH_SCALE 1.69864361f

// ---------------- scratch (static device globals; no allocation) ------------
__device__ __align__(128) float g_Y[(size_t)M2 * D_HID];     // 16 MB
__device__ __align__(128) float g_Z[(size_t)M2 * D_OUTF];    // fallback only
__device__ __align__(128) __nv_bfloat16 g_Zh[(size_t)M2 * D_OUTF]; // scaled bf16 z
__device__ __align__(128) __nv_bfloat16 g_W1h[D_HID * D_INF];
__device__ __align__(128) __nv_bfloat16 g_W1l[D_HID * D_INF];
__device__ __align__(128) __nv_bfloat16 g_W2h[D_OUTF * D_HID];
__device__ __align__(128) __nv_bfloat16 g_W2l[D_OUTF * D_HID];
__device__ float g_colsum[2][D_HID];
__device__ float g_colsq[2][D_HID];
__device__ float g_sumexp[M2];
__device__ float g_loss[1];
__device__ unsigned g_done;

// ---------------- helpers ----------------------------------------------------
__device__ __forceinline__ uint32_t smem_u32(const void* p) {
    uint32_t a;
    asm("{ .reg .u64 t; cvta.to.shared.u64 t, %1; cvt.u32.u64 %0, t; }" : "=r"(a) : "l"(p));
    return a;
}
__device__ __forceinline__ void ldsm4(uint32_t* r, uint32_t addr) {
    asm volatile("ldmatrix.sync.aligned.m8n8.x4.shared.b16 {%0,%1,%2,%3}, [%4];"
                 : "=r"(r[0]), "=r"(r[1]), "=r"(r[2]), "=r"(r[3]) : "r"(addr));
}
__device__ __forceinline__ void mma16816(float* c, const uint32_t* a, const uint32_t* b) {
    asm volatile(
        "mma.sync.aligned.m16n8k16.row.col.f32.bf16.bf16.f32 "
        "{%0,%1,%2,%3}, {%4,%5,%6,%7}, {%8,%9}, {%0,%1,%2,%3};"
        : "+f"(c[0]), "+f"(c[1]), "+f"(c[2]), "+f"(c[3])
        : "r"(a[0]), "r"(a[1]), "r"(a[2]), "r"(a[3]), "r"(b[0]), "r"(b[1]));
}
__device__ __forceinline__ float ex2(float x) {
    float y;
    asm("ex2.approx.f32 %0, %1;" : "=f"(y) : "f"(x));
    return y;
}
__device__ __forceinline__ void cpa16(uint32_t saddr, const void* gaddr) {
    asm volatile("cp.async.cg.shared.global [%0], [%1], 16;"
                 :: "r"(saddr), "l"(gaddr) : "memory");
}
__device__ __forceinline__ void cpa_wait_all() {
    asm volatile("cp.async.commit_group;\n\tcp.async.wait_group 0;" ::: "memory");
}
// split fp32 pair into bf16x2 hi + bf16x2 lo (x = hi + lo, err ~2^-18)
__device__ __forceinline__ void split2(float f0, float f1, uint32_t& hi, uint32_t& lo) {
    __nv_bfloat162 h = __floats2bfloat162_rn(f0, f1);
    __nv_bfloat162 l = __floats2bfloat162_rn(f0 - __bfloat162float(h.x),
                                             f1 - __bfloat162float(h.y));
    hi = *reinterpret_cast<uint32_t*>(&h);
    lo = *reinterpret_cast<uint32_t*>(&l);
}

// smem tile geometry (pitch 36 words = 72 bf16 = 144 bytes)
#define PW   36
#define SAW  (64 * PW)     // gemm2 A tile: 64 rows
#define SA1W (128 * PW)    // gemm1 A tile: 128 rows
#define SBW  (128 * PW)    // B tile: 128 rows
#define GSM1_BYTES (((2 * SA1W + 2 * SBW) * 4) + 1024)           // 74752
#define GSM2_BYTES (((2 * SAW + 2 * SBW) * 4) + 4096 + 1280)     // 60672

// ---------------- prep: init + split WEIGHTS to hi/lo bf16 (once) -----------
__global__ __launch_bounds__(256) void k_prep(const float* __restrict__ W1,
                                              const float* __restrict__ W2) {
    int i = blockIdx.x * blockDim.x + threadIdx.x;
    if (i < M2) g_sumexp[i] = 0.f;
    if (i < 2 * D_HID) {
        g_colsum[i >> 9][i & 511] = 0.f;
        g_colsq [i >> 9][i & 511] = 0.f;
    }
    if (i == 0) { g_loss[0] = 0.f; g_done = 0u; }

    const int NW14 = (D_HID * D_INF) / 4;
    const int NW24 = (D_OUTF * D_HID) / 4;
    const float* src;
    __nv_bfloat16 *dh, *dl;
    int off;
    if (i < NW14)             { src = W1; dh = g_W1h; dl = g_W1l; off = i; }
    else if (i < NW14 + NW24) { src = W2; dh = g_W2h; dl = g_W2l; off = i - NW14; }
    else return;
    float4 v = *(const float4*)(src + (size_t)off * 4);
    uint32_t a0, b0, a1, b1v;
    split2(v.x, v.y, a0, b0);
    split2(v.z, v.w, a1, b1v);
    uint2 hh = {a0, a1}, ll = {b0, b1v};
    *(uint2*)(dh + (size_t)off * 4) = hh;
    *(uint2*)(dl + (size_t)off * 4) = ll;
}

// ---------------- GEMM1 (tensor, split-bf16): Y = H @ W1^T + b1 + BN partials
// BM=128, BN=128, K=192 in 3 chunks of 64. 8 warps (2m x 4n), warp tile 64x32.
__global__ __launch_bounds__(256) void k_gemm1t(const float* __restrict__ h1,
                                                const float* __restrict__ h2,
                                                const float* __restrict__ b1) {
    extern __shared__ __align__(16) uint32_t sw[];
    uint32_t* sAhi = sw;
    uint32_t* sAlo = sw + SA1W;
    uint32_t* sBhi = sw + 2 * SA1W;
    uint32_t* sBlo = sw + 2 * SA1W + SBW;
    float* colS = (float*)(sw + 2 * SA1W + 2 * SBW);
    float* colQ = colS + 128;

    const int t = threadIdx.x;
    const int wid = t >> 5, lane = t & 31;
    const int gr = lane >> 2, qq = lane & 3;
    const int sel = lane >> 3, li = lane & 7;
    const int warp_m = wid >> 2, warp_n = wid & 3;
    const int n0 = blockIdx.x * 128;
    const int m0 = blockIdx.y * 128;
    const int half = (m0 >= B_ROWS);
    const float* H = half ? (h2 + (size_t)(m0 - B_ROWS) * D_INF)
                          : (h1 + (size_t)m0 * D_INF);

    if (t < 128) { colS[t] = 0.f; colQ[t] = 0.f; }

    float acc[4][4][4];
#pragma unroll
    for (int mi = 0; mi < 4; mi++)
#pragma unroll
        for (int ni = 0; ni < 4; ni++)
#pragma unroll
            for (int r = 0; r < 4; r++) acc[mi][ni][r] = 0.f;

    const int arow = t >> 1, acq = (t & 1) * 32;
    const int brow = t >> 1, bcq = (t & 1) * 32;
    const float* pAf = H + (size_t)arow * D_INF + acq;
    const __nv_bfloat16* pBh = g_W1h + (size_t)(n0 + brow) * D_INF + bcq;
    const __nv_bfloat16* pBl = g_W1l + (size_t)(n0 + brow) * D_INF + bcq;
    const int aw = arow * PW + (acq >> 1);
    const int bw = brow * PW + (bcq >> 1);

    const uint32_t sAhiU = smem_u32(sAhi), sAloU = smem_u32(sAlo);
    const uint32_t sBhiU = smem_u32(sBhi), sBloU = smem_u32(sBlo);
    uint32_t aoff[4], boff[2];
#pragma unroll
    for (int mi = 0; mi < 4; mi++)
        aoff[mi] = (uint32_t)(warp_m * 64 + mi * 16 + (sel & 1) * 8 + li) * 144u
                 + (uint32_t)(sel >> 1) * 16u;
#pragma unroll
    for (int nip = 0; nip < 2; nip++)
        boff[nip] = (uint32_t)(warp_n * 32 + nip * 16 + (sel >> 1) * 8 + li) * 144u
                  + (uint32_t)(sel & 1) * 16u;

    for (int kb = 0; kb < D_INF; kb += 64) {
        {
#pragma unroll
            for (int j = 0; j < 8; j++) {
                float4 v = *(const float4*)(pAf + kb + j * 4);
                uint32_t h0, l0, h1v, l1;
                split2(v.x, v.y, h0, l0);
                split2(v.z, v.w, h1v, l1);
                uint2 hh = {h0, h1v}, ll = {l0, l1};
                *(uint2*)(sAhi + aw + j * 2) = hh;
                *(uint2*)(sAlo + aw + j * 2) = ll;
            }
#pragma unroll
            for (int j = 0; j < 4; j++) {
                uint4 vh = *(const uint4*)(pBh + kb + j * 8);
                uint4 vl = *(const uint4*)(pBl + kb + j * 8);
                *(uint4*)(sBhi + bw + j * 4) = vh;
                *(uint4*)(sBlo + bw + j * 4) = vl;
            }
        }
        __syncthreads();
#pragma unroll
        for (int ks = 0; ks < 4; ks++) {
            uint32_t koff = (uint32_t)ks * 32u;
            uint32_t ah[4][4], al[4][4], bh[4][2], bl[4][2], tmp[4];
#pragma unroll
            for (int mi = 0; mi < 4; mi++) {
                ldsm4(ah[mi], sAhiU + aoff[mi] + koff);
                ldsm4(al[mi], sAloU + aoff[mi] + koff);
            }
            ldsm4(tmp, sBhiU + boff[0] + koff);
            bh[0][0]=tmp[0]; bh[0][1]=tmp[1]; bh[1][0]=tmp[2]; bh[1][1]=tmp[3];
            ldsm4(tmp, sBhiU + boff[1] + koff);
            bh[2][0]=tmp[0]; bh[2][1]=tmp[1]; bh[3][0]=tmp[2]; bh[3][1]=tmp[3];
            ldsm4(tmp, sBloU + boff[0] + koff);
            bl[0][0]=tmp[0]; bl[0][1]=tmp[1]; bl[1][0]=tmp[2]; bl[1][1]=tmp[3];
            ldsm4(tmp, sBloU + boff[1] + koff);
            bl[2][0]=tmp[0]; bl[2][1]=tmp[1]; bl[3][0]=tmp[2]; bl[3][1]=tmp[3];
#pragma unroll
            for (int mi = 0; mi < 4; mi++)
#pragma unroll
                for (int ni = 0; ni < 4; ni++) {
                    mma16816(acc[mi][ni], ah[mi], bh[ni]);
                    mma16816(acc[mi][ni], ah[mi], bl[ni]);
                    mma16816(acc[mi][ni], al[mi], bh[ni]);
                }
        }
        __syncthreads();
    }

    float ps[4][2], pq[4][2];
#pragma unroll
    for (int ni = 0; ni < 4; ni++) { ps[ni][0]=ps[ni][1]=pq[ni][0]=pq[ni][1]=0.f; }
#pragma unroll
    for (int ni = 0; ni < 4; ni++) {
        int col = warp_n * 32 + ni * 8 + qq * 2;
        float2 bb = *(const float2*)&b1[n0 + col];
#pragma unroll
        for (int mi = 0; mi < 4; mi++) {
            int r = warp_m * 64 + mi * 16 + gr;
            float y0 = acc[mi][ni][0] + bb.x;
            float y1 = acc[mi][ni][1] + bb.y;
            float y2 = acc[mi][ni][2] + bb.x;
            float y3 = acc[mi][ni][3] + bb.y;
            float2 p0 = {y0, y1}, p1 = {y2, y3};
            *(float2*)&g_Y[(size_t)(m0 + r)     * D_HID + n0 + col] = p0;
            *(float2*)&g_Y[(size_t)(m0 + r + 8) * D_HID + n0 + col] = p1;
            ps[ni][0] += y0 + y2;              ps[ni][1] += y1 + y3;
            pq[ni][0] += y0 * y0 + y2 * y2;    pq[ni][1] += y1 * y1 + y3 * y3;
        }
    }
#pragma unroll
    for (int ni = 0; ni < 4; ni++)
#pragma unroll
        for (int c2 = 0; c2 < 2; c2++) {
            float s = ps[ni][c2], q = pq[ni][c2];
            s += __shfl_xor_sync(~0u, s, 4);  q += __shfl_xor_sync(~0u, q, 4);
            s += __shfl_xor_sync(~0u, s, 8);  q += __shfl_xor_sync(~0u, q, 8);
            s += __shfl_xor_sync(~0u, s, 16); q += __shfl_xor_sync(~0u, q, 16);
            ps[ni][c2] = s; pq[ni][c2] = q;
        }
    if (gr == 0) {
#pragma unroll
        for (int ni = 0; ni < 4; ni++) {
            int col = warp_n * 32 + ni * 8 + qq * 2;
            atomicAdd(&colS[col],     ps[ni][0]);
            atomicAdd(&colS[col + 1], ps[ni][1]);
            atomicAdd(&colQ[col],     pq[ni][0]);
            atomicAdd(&colQ[col + 1], pq[ni][1]);
        }
    }
    __syncthreads();
    if (t < 128) {
        atomicAdd(&g_colsum[half][n0 + t], colS[t]);
        atomicAdd(&g_colsq [half][n0 + t], colQ[t]);
    }
}

// ---------------- GEMM2 (tensor, split-bf16): Z = relu(BN(Y)) @ W2^T + b2 ----
__global__ __launch_bounds__(256) void k_gemm2t(const float* __restrict__ b2,
                                                const float* __restrict__ gamma,
                                                const float* __restrict__ beta,
                                                float* __restrict__ out,
                                                int out_size) {
    extern __shared__ __align__(16) uint32_t sw[];
    uint32_t* sAhi = sw;
    uint32_t* sAlo = sw + SAW;
    uint32_t* sBhi = sw + 2 * SAW;
    uint32_t* sBlo = sw + 2 * SAW + SBW;
    float* ssc  = (float*)(sw + 2 * SAW + 2 * SBW);
    float* ssh  = ssc + D_HID;
    float* red  = ssh + D_HID;
    float* sInv = red + 256;

    const int t = threadIdx.x;
    const int wid = t >> 5, lane = t & 31;
    const int gr = lane >> 2, qq = lane & 3;
    const int sel = lane >> 3, li = lane & 7;
    const int warp_m = wid >> 2, warp_n = wid & 3;
    const int m0 = blockIdx.x * 64;
    const int half = (m0 >= B_ROWS);

    for (int c = t; c < D_HID; c += 256) {
        float mean = g_colsum[half][c] * (1.f / B_ROWS);
        float var  = g_colsq [half][c] * (1.f / B_ROWS) - mean * mean;
        float scv  = gamma[c] * rsqrtf(var + BN_EPS);
        ssc[c] = scv;
        ssh[c] = beta[c] - mean * scv;
    }
    __syncthreads();

    float acc[2][4][4];
#pragma unroll
    for (int mi = 0; mi < 2; mi++)
#pragma unroll
        for (int ni = 0; ni < 4; ni++)
#pragma unroll
            for (int r = 0; r < 4; r++) acc[mi][ni][r] = 0.f;

    const int arow = t >> 2, acq = (t & 3) * 16;
    const int brow = t >> 1, bcq = (t & 1) * 32;
    const float* pA = g_Y + (size_t)(m0 + arow) * D_HID + acq;
    const __nv_bfloat16* pBh = g_W2h + (size_t)brow * D_HID + bcq;
    const __nv_bfloat16* pBl = g_W2l + (size_t)brow * D_HID + bcq;
    const int aw = arow * PW + (acq >> 1);
    const int bw = brow * PW + (bcq >> 1);

    const uint32_t sAhiU = smem_u32(sAhi), sAloU = smem_u32(sAlo);
    const uint32_t sBhiU = smem_u32(sBhi), sBloU = smem_u32(sBlo);
    uint32_t aoff[2], boff[2];
#pragma unroll
    for (int mi = 0; mi < 2; mi++)
        aoff[mi] = (uint32_t)(warp_m * 32 + mi * 16 + (sel & 1) * 8 + li) * 144u
                 + (uint32_t)(sel >> 1) * 16u;
#pragma unroll
    for (int nip = 0; nip < 2; nip++)
        boff[nip] = (uint32_t)(warp_n * 32 + nip * 16 + (sel >> 1) * 8 + li) * 144u
                  + (uint32_t)(sel & 1) * 16u;

    float4 rA[4];
    uint4 rBh[4], rBl[4];
#pragma unroll
    for (int j = 0; j < 4; j++) {
        rA[j]  = *(const float4*)(pA + j * 4);
        rBh[j] = *(const uint4*)(pBh + j * 8);
        rBl[j] = *(const uint4*)(pBl + j * 8);
    }

    for (int it = 0; it < 8; it++) {
        const int kb = it * 64;
        {
#pragma unroll
            for (int j = 0; j < 4; j++) {
                int k = kb + acq + j * 4;
                float f0 = fmaxf(fmaf(rA[j].x, ssc[k],     ssh[k]),     0.f);
                float f1 = fmaxf(fmaf(rA[j].y, ssc[k + 1], ssh[k + 1]), 0.f);
                float f2 = fmaxf(fmaf(rA[j].z, ssc[k + 2], ssh[k + 2]), 0.f);
                float f3 = fmaxf(fmaf(rA[j].w, ssc[k + 3], ssh[k + 3]), 0.f);
                uint32_t h0, l0, h1v, l1;
                split2(f0, f1, h0, l0);
                split2(f2, f3, h1v, l1);
                uint2 hh = {h0, h1v}, ll = {l0, l1};
                *(uint2*)(sAhi + aw + j * 2) = hh;
                *(uint2*)(sAlo + aw + j * 2) = ll;
                *(uint4*)(sBhi + bw + j * 4) = rBh[j];
                *(uint4*)(sBlo + bw + j * 4) = rBl[j];
            }
        }
        __syncthreads();
        if (it < 7) {
            int kn = kb + 64;
#pragma unroll
            for (int j = 0; j < 4; j++) {
                rA[j]  = *(const float4*)(pA + kn + j * 4);
                rBh[j] = *(const uint4*)(pBh + kn + j * 8);
                rBl[j] = *(const uint4*)(pBl + kn + j * 8);
            }
        }
#pragma unroll
        for (int ks = 0; ks < 4; ks++) {
            uint32_t koff = (uint32_t)ks * 32u;
            uint32_t ah[2][4], al[2][4], bh[4][2], bl[4][2], tmp[4];
            ldsm4(ah[0], sAhiU + aoff[0] + koff);
            ldsm4(ah[1], sAhiU + aoff[1] + koff);
            ldsm4(al[0], sAloU + aoff[0] + koff);
            ldsm4(al[1], sAloU + aoff[1] + koff);
            ldsm4(tmp, sBhiU + boff[0] + koff);
            bh[0][0]=tmp[0]; bh[0][1]=tmp[1]; bh[1][0]=tmp[2]; bh[1][1]=tmp[3];
            ldsm4(tmp, sBhiU + boff[1] + koff);
            bh[2][0]=tmp[0]; bh[2][1]=tmp[1]; bh[3][0]=tmp[2]; bh[3][1]=tmp[3];
            ldsm4(tmp, sBloU + boff[0] + koff);
            bl[0][0]=tmp[0]; bl[0][1]=tmp[1]; bl[1][0]=tmp[2]; bl[1][1]=tmp[3];
            ldsm4(tmp, sBloU + boff[1] + koff);
            bl[2][0]=tmp[0]; bl[2][1]=tmp[1]; bl[3][0]=tmp[2]; bl[3][1]=tmp[3];
#pragma unroll
            for (int mi = 0; mi < 2; mi++)
#pragma unroll
                for (int ni = 0; ni < 4; ni++) {
                    mma16816(acc[mi][ni], ah[mi], bh[ni]);
                    mma16816(acc[mi][ni], ah[mi], bl[ni]);
                    mma16816(acc[mi][ni], al[mi], bh[ni]);
                }
        }
        __syncthreads();
    }

    float rp[2][2] = {{0.f, 0.f}, {0.f, 0.f}};
#pragma unroll
    for (int ni = 0; ni < 4; ni++) {
        int col = warp_n * 32 + ni * 8 + qq * 2;
        float2 bb = *(const float2*)&b2[col];
#pragma unroll
        for (int mi = 0; mi < 2; mi++) {
            acc[mi][ni][0] += bb.x; acc[mi][ni][1] += bb.y;
            acc[mi][ni][2] += bb.x; acc[mi][ni][3] += bb.y;
            rp[mi][0] = fmaf(acc[mi][ni][0], acc[mi][ni][0],
                        fmaf(acc[mi][ni][1], acc[mi][ni][1], rp[mi][0]));
            rp[mi][1] = fmaf(acc[mi][ni][2], acc[mi][ni][2],
                        fmaf(acc[mi][ni][3], acc[mi][ni][3], rp[mi][1]));
        }
    }
#pragma unroll
    for (int mi = 0; mi < 2; mi++)
#pragma unroll
        for (int rh = 0; rh < 2; rh++) {
            float s = rp[mi][rh];
            s += __shfl_xor_sync(~0u, s, 1);
            s += __shfl_xor_sync(~0u, s, 2);
            rp[mi][rh] = s;
        }
    if (qq == 0) {
#pragma unroll
        for (int mi = 0; mi < 2; mi++) {
            red[(warp_m * 32 + mi * 16 + gr)     * 4 + warp_n] = rp[mi][0];
            red[(warp_m * 32 + mi * 16 + gr + 8) * 4 + warp_n] = rp[mi][1];
        }
    }
    __syncthreads();
    if (t < 64) {
        float s = red[t * 4] + red[t * 4 + 1] + red[t * 4 + 2] + red[t * 4 + 3];
        sInv[t] = 1.f / fmaxf(sqrtf(s), L2_EPS);
    }
    __syncthreads();
    bool full = (out_size > M2 * D_OUTF);
#pragma unroll
    for (int mi = 0; mi < 2; mi++)
#pragma unroll
        for (int rh = 0; rh < 2; rh++) {
            int r = warp_m * 32 + mi * 16 + gr + rh * 8;
            float inv = sInv[r];
            int m = m0 + r;
#pragma unroll
            for (int ni = 0; ni < 4; ni++) {
                int col = warp_n * 32 + ni * 8 + qq * 2;
                float z0 = acc[mi][ni][rh * 2]     * inv;
                float z1 = acc[mi][ni][rh * 2 + 1] * inv;
                if (full) {
                    out[1 + (size_t)m * D_OUTF + col]     = z0;
                    out[1 + (size_t)m * D_OUTF + col + 1] = z1;
                } else {
                    float2 zz = {z0, z1};
                    *(float2*)&g_Z[(size_t)m * D_OUTF + col] = zz;
                }
                *(__nv_bfloat162*)&g_Zh[(size_t)m * D_OUTF + col] =
                    __floats2bfloat162_rn(z0 * ZH_SCALE, z1 * ZH_SCALE);
            }
        }
}

// ---------------- tensor-core sim: 128x128 tile, 3 CTAs/SM target -----------
// 8 warps, warp tile 32x32, 2 sequential m-passes. Small acc footprint (32
// regs/pass) + 69KB smem -> occ 3 CTAs/SM.
#define SIM_PITCH_B 272
#define SIM_TILE_BYTES (128 * SIM_PITCH_B)     // 34816
#define SIM_SMEM_SIZE (2 * SIM_TILE_BYTES + 2 * 128 * 4)

__device__ __forceinline__ int tri_off(int r) { return r * 64 - ((r * (r - 1)) >> 1); }

__global__ __launch_bounds__(256, 3) void k_sims() {
    extern __shared__ __align__(16) char smem[];
    char* sA = smem;
    char* sB = smem + SIM_TILE_BYTES;
    float* srow = (float*)(smem + 2 * SIM_TILE_BYTES);
    float* scol = srow + 128;

    const int t = threadIdx.x;
    const int wid = t >> 5, lane = t & 31;
    const int gr = lane >> 2, qq = lane & 3;
    const int sel = lane >> 3, li = lane & 7;
    const int warp_m2 = wid >> 2;      // 0..1
    const int warp_n  = wid & 3;       // 0..3

    int tb = blockIdx.x;
    int bi = (int)(64.5f - sqrtf(64.5f * 64.5f - 2.0f * (float)tb));
    if (bi < 0) bi = 0; if (bi > 63) bi = 63;
    while (tri_off(bi + 1) <= tb) ++bi;
    while (tri_off(bi) > tb) --bi;
    int bj = bi + (tb - tri_off(bi));
    const size_t i0 = (size_t)bi * 128;
    const size_t j0 = (size_t)bj * 128;
    const bool offdiag = (bi != bj);

    const uint32_t sAu = smem_u32(sA);
    const uint32_t sBu = smem_u32(sB);
    const char* gA = (const char*)(g_Zh + i0 * D_OUTF);
    const char* gB = (const char*)(g_Zh + j0 * D_OUTF);
#pragma unroll
    for (int it = 0; it < 8; it++) {
        int q = t + it * 256;
        uint32_t so = (uint32_t)(q >> 4) * SIM_PITCH_B + (uint32_t)(q & 15) * 16u;
        cpa16(sAu + so, gA + q * 16);
        cpa16(sBu + so, gB + q * 16);
    }
    if (t < 128) { srow[t] = 0.f; scol[t] = 0.f; }
    cpa_wait_all();
    __syncthreads();

    uint32_t boff[2];
#pragma unroll
    for (int nip = 0; nip < 2; nip++)
        boff[nip] = sBu + (uint32_t)(warp_n * 32 + nip * 16 + (sel >> 1) * 8 + li) * SIM_PITCH_B
                  + (uint32_t)(sel & 1) * 16u;

    float csum[8];
#pragma unroll
    for (int i = 0; i < 8; i++) csum[i] = 0.f;

#pragma unroll
    for (int pass = 0; pass < 2; pass++) {
        const int rbase = pass * 64 + warp_m2 * 32;
        uint32_t aoff[2];
#pragma unroll
        for (int mi = 0; mi < 2; mi++)
            aoff[mi] = sAu + (uint32_t)(rbase + mi * 16 + (sel & 1) * 8 + li) * SIM_PITCH_B
                     + (uint32_t)(sel >> 1) * 16u;

        float cc[2][4][4];
#pragma unroll
        for (int mi = 0; mi < 2; mi++)
#pragma unroll
            for (int ni = 0; ni < 4; ni++)
#pragma unroll
                for (int r = 0; r < 4; r++) cc[mi][ni][r] = 0.f;

#pragma unroll
        for (int ks = 0; ks < 8; ks++) {
            uint32_t koff = (uint32_t)ks * 32u;
            uint32_t a[2][4], b[4][2], tmp[4];
            ldsm4(a[0], aoff[0] + koff);
            ldsm4(a[1], aoff[1] + koff);
            ldsm4(tmp, boff[0] + koff);
            b[0][0]=tmp[0]; b[0][1]=tmp[1]; b[1][0]=tmp[2]; b[1][1]=tmp[3];
            ldsm4(tmp, boff[1] + koff);
            b[2][0]=tmp[0]; b[2][1]=tmp[1]; b[3][0]=tmp[2]; b[3][1]=tmp[3];
#pragma unroll
            for (int mi = 0; mi < 2; mi++)
#pragma unroll
                for (int ni = 0; ni < 4; ni++)
                    mma16816(cc[mi][ni], a[mi], b[ni]);
        }

        // exp2 + row sums (flushed per pass) + col sums (kept across passes)
        float rsum[4];
#pragma unroll
        for (int i = 0; i < 4; i++) rsum[i] = 0.f;
#pragma unroll
        for (int mi = 0; mi < 2; mi++)
#pragma unroll
            for (int ni = 0; ni < 4; ni++) {
                float e0 = ex2(cc[mi][ni][0]);
                float e1 = ex2(cc[mi][ni][1]);
                float e2 = ex2(cc[mi][ni][2]);
                float e3 = ex2(cc[mi][ni][3]);
                rsum[mi * 2 + 0] += e0 + e1;
                rsum[mi * 2 + 1] += e2 + e3;
                csum[ni * 2 + 0] += e0 + e2;
                csum[ni * 2 + 1] += e1 + e3;
            }
#pragma unroll
        for (int i = 0; i < 4; i++) {
            rsum[i] += __shfl_xor_sync(0xffffffffu, rsum[i], 1);
            rsum[i] += __shfl_xor_sync(0xffffffffu, rsum[i], 2);
        }
        if (qq == 0) {
#pragma unroll
            for (int mi = 0; mi < 2; mi++) {
                atomicAdd(&srow[rbase + mi * 16 + gr],     rsum[mi * 2 + 0]);
                atomicAdd(&srow[rbase + mi * 16 + gr + 8], rsum[mi * 2 + 1]);
            }
        }
    }

    if (offdiag) {
#pragma unroll
        for (int i = 0; i < 8; i++) {
            csum[i] += __shfl_xor_sync(0xffffffffu, csum[i], 4);
            csum[i] += __shfl_xor_sync(0xffffffffu, csum[i], 8);
            csum[i] += __shfl_xor_sync(0xffffffffu, csum[i], 16);
        }
        if (gr == 0) {
#pragma unroll
            for (int ni = 0; ni < 4; ni++) {
                atomicAdd(&scol[warp_n * 32 + ni * 8 + qq * 2],     csum[ni * 2 + 0]);
                atomicAdd(&scol[warp_n * 32 + ni * 8 + qq * 2 + 1], csum[ni * 2 + 1]);
            }
        }
    }
    __syncthreads();
    if (t < 128) {
        atomicAdd(&g_sumexp[i0 + t], srow[t]);
        if (offdiag) atomicAdd(&g_sumexp[j0 + t], scol[t]);
    }
}

// ---------------- finish: loss = mean(lse_i - pos_i); emits out[0] ----------
__global__ void k_finish(float* __restrict__ out, int out_size) {
    int w    = (blockIdx.x * blockDim.x + threadIdx.x) >> 5;
    int lane = threadIdx.x & 31;
    if (w >= B_ROWS) return;
    bool full = (out_size > M2 * D_OUTF);
    const float* zsrc = full ? (out + 1) : g_Z;
    const float* p1 = zsrc + (size_t)w * D_OUTF + lane * 4;
    const float* p2 = zsrc + (size_t)(w + B_ROWS) * D_OUTF + lane * 4;
    float dp = 0.f;
#pragma unroll
    for (int j = 0; j < 4; j++) dp = fmaf(p1[j], p2[j], dp);
    const __nv_bfloat16* z1 = g_Zh + (size_t)w * D_OUTF + lane * 4;
    const __nv_bfloat16* z2 = g_Zh + (size_t)(w + B_ROWS) * D_OUTF + lane * 4;
    float d1 = 0.f, d2 = 0.f;
#pragma unroll
    for (int j = 0; j < 4; j++) {
        float v1 = __bfloat162float(z1[j]);
        float v2 = __bfloat162float(z2[j]);
        d1 = fmaf(v1, v1, d1);
        d2 = fmaf(v2, v2, d2);
    }
#pragma unroll
    for (int o = 16; o; o >>= 1) {
        dp += __shfl_down_sync(0xffffffffu, dp, o);
        d1 += __shfl_down_sync(0xffffffffu, d1, o);
        d2 += __shfl_down_sync(0xffffffffu, d2, o);
    }
    if (lane == 0) {
        float pos  = dp * INV_T;
        float lse1 = logf(g_sumexp[w]          - ex2(d1));
        float lse2 = logf(g_sumexp[w + B_ROWS] - ex2(d2));
        atomicAdd(&g_loss[0], (lse1 + lse2 - 2.f * pos) * (1.f / M2));
        __threadfence();
        unsigned prev = atomicAdd(&g_done, 1u);
        if (prev == B_ROWS - 1) {
            if (out_size > 0) out[0] = g_loss[0];
            g_done = 0u;   // reset for next graph replay
        }
    }
}

// ---------------- launch -----------------------------------------------------
extern "C" void kernel_launch(void* const* d_in, const int* in_sizes, int n_in,
                              void* d_out, int out_size) {
    const float* h1    = (const float*)d_in[0];
    const float* h2    = (const float*)d_in[1];
    const float* W1    = (const float*)d_in[2];
    const float* b1    = (const float*)d_in[3];
    const float* gamma = (const float*)d_in[4];
    const float* beta  = (const float*)d_in[5];
    const float* W2    = (const float*)d_in[6];
    const float* b2    = (const float*)d_in[7];
    float* out = (float*)d_out;

    cudaFuncSetAttribute(k_gemm1t, cudaFuncAttributeMaxDynamicSharedMemorySize, GSM1_BYTES);
    cudaFuncSetAttribute(k_gemm2t, cudaFuncAttributeMaxDynamicSharedMemorySize, GSM2_BYTES);
    cudaFuncSetAttribute(k_sims,   cudaFuncAttributeMaxDynamicSharedMemorySize, SIM_SMEM_SIZE);

    k_prep   <<<160, 256>>>(W1, W2);
    k_gemm1t <<<dim3(4, 64), 256, GSM1_BYTES>>>(h1, h2, b1);
    k_gemm2t <<<128, 256, GSM2_BYTES>>>(b2, gamma, beta, out, out_size);
    k_sims   <<<2080, 256, SIM_SMEM_SIZE>>>();
    k_finish <<<512, 256>>>(out, out_size);
}

// round 17
// speedup vs baseline: 1.2053x; 1.0080x over previous
#include <cuda_runtime.h>
#include <cuda_bf16.h>
#include <math.h>
#include <stdint.h>

#define B_ROWS 4096
#define D_INF  192
#define D_HID  512
#define D_OUTF 128
#define M2     8192      // 2*B
#define INV_T  2.0f      // 1/TEMPERATURE
#define BN_EPS 1e-5f
#define L2_EPS 1e-12f
// zh = z * sqrt(2*log2(e)): zh_i.zh_j = 2*log2e*(z_i.z_j); exp((z.z)/T) = exp2(zh.zh)
#define ZH_SCALE 1.69864361f

// ---------------- scratch (static device globals; no allocation) ------------
__device__ __align__(128) float g_Y[(size_t)M2 * D_HID];     // 16 MB
__device__ __align__(128) float g_Z[(size_t)M2 * D_OUTF];    // fallback only
__device__ __align__(128) __nv_bfloat16 g_Zh[(size_t)M2 * D_OUTF]; // scaled bf16 z
__device__ __align__(128) __nv_bfloat16 g_W1h[D_HID * D_INF];
__device__ __align__(128) __nv_bfloat16 g_W1l[D_HID * D_INF];
__device__ __align__(128) __nv_bfloat16 g_W2h[D_OUTF * D_HID];
__device__ __align__(128) __nv_bfloat16 g_W2l[D_OUTF * D_HID];
__device__ float g_colsum[2][D_HID];
__device__ float g_colsq[2][D_HID];
__device__ float g_sumexp[M2];
__device__ float g_loss[1];
__device__ unsigned g_done;

// ---------------- helpers ----------------------------------------------------
__device__ __forceinline__ uint32_t smem_u32(const void* p) {
    uint32_t a;
    asm("{ .reg .u64 t; cvta.to.shared.u64 t, %1; cvt.u32.u64 %0, t; }" : "=r"(a) : "l"(p));
    return a;
}
__device__ __forceinline__ void ldsm4(uint32_t* r, uint32_t addr) {
    asm volatile("ldmatrix.sync.aligned.m8n8.x4.shared.b16 {%0,%1,%2,%3}, [%4];"
                 : "=r"(r[0]), "=r"(r[1]), "=r"(r[2]), "=r"(r[3]) : "r"(addr));
}
__device__ __forceinline__ void mma16816(float* c, const uint32_t* a, const uint32_t* b) {
    asm volatile(
        "mma.sync.aligned.m16n8k16.row.col.f32.bf16.bf16.f32 "
        "{%0,%1,%2,%3}, {%4,%5,%6,%7}, {%8,%9}, {%0,%1,%2,%3};"
        : "+f"(c[0]), "+f"(c[1]), "+f"(c[2]), "+f"(c[3])
        : "r"(a[0]), "r"(a[1]), "r"(a[2]), "r"(a[3]), "r"(b[0]), "r"(b[1]));
}
__device__ __forceinline__ float ex2(float x) {
    float y;
    asm("ex2.approx.f32 %0, %1;" : "=f"(y) : "f"(x));
    return y;
}
__device__ __forceinline__ void cpa16(uint32_t saddr, const void* gaddr) {
    asm volatile("cp.async.cg.shared.global [%0], [%1], 16;"
                 :: "r"(saddr), "l"(gaddr) : "memory");
}
__device__ __forceinline__ void cpa_wait_all() {
    asm volatile("cp.async.commit_group;\n\tcp.async.wait_group 0;" ::: "memory");
}
// split fp32 pair into bf16x2 hi + bf16x2 lo (x = hi + lo, err ~2^-18)
__device__ __forceinline__ void split2(float f0, float f1, uint32_t& hi, uint32_t& lo) {
    __nv_bfloat162 h = __floats2bfloat162_rn(f0, f1);
    __nv_bfloat162 l = __floats2bfloat162_rn(f0 - __bfloat162float(h.x),
                                             f1 - __bfloat162float(h.y));
    hi = *reinterpret_cast<uint32_t*>(&h);
    lo = *reinterpret_cast<uint32_t*>(&l);
}

// smem tile geometry (pitch 36 words = 72 bf16 = 144 bytes)
#define PW   36
#define SAW  (64 * PW)     // gemm2 A tile: 64 rows
#define SA1W (128 * PW)    // gemm1 A tile: 128 rows
#define SBW  (128 * PW)    // B tile: 128 rows
#define GSM1_BYTES (((2 * SA1W + 2 * SBW) * 4) + 1024)           // 74752
#define GSM2_BYTES (((2 * SAW + 2 * SBW) * 4) + 4096 + 1280)     // 60672

// ---------------- prep: init + split WEIGHTS to hi/lo bf16 (once) -----------
__global__ __launch_bounds__(256) void k_prep(const float* __restrict__ W1,
                                              const float* __restrict__ W2) {
    int i = blockIdx.x * blockDim.x + threadIdx.x;
    if (i < M2) g_sumexp[i] = 0.f;
    if (i < 2 * D_HID) {
        g_colsum[i >> 9][i & 511] = 0.f;
        g_colsq [i >> 9][i & 511] = 0.f;
    }
    if (i == 0) { g_loss[0] = 0.f; g_done = 0u; }

    const int NW14 = (D_HID * D_INF) / 4;
    const int NW24 = (D_OUTF * D_HID) / 4;
    const float* src;
    __nv_bfloat16 *dh, *dl;
    int off;
    if (i < NW14)             { src = W1; dh = g_W1h; dl = g_W1l; off = i; }
    else if (i < NW14 + NW24) { src = W2; dh = g_W2h; dl = g_W2l; off = i - NW14; }
    else return;
    float4 v = *(const float4*)(src + (size_t)off * 4);
    uint32_t a0, b0, a1, b1v;
    split2(v.x, v.y, a0, b0);
    split2(v.z, v.w, a1, b1v);
    uint2 hh = {a0, a1}, ll = {b0, b1v};
    *(uint2*)(dh + (size_t)off * 4) = hh;
    *(uint2*)(dl + (size_t)off * 4) = ll;
}

// ---------------- GEMM1 (tensor, split-bf16): Y = H @ W1^T + b1 + BN partials
// Per-half launch: grid (4, 32), mbase selects half. BM=128, BN=128.
__global__ __launch_bounds__(256) void k_gemm1t(const float* __restrict__ h1,
                                                const float* __restrict__ h2,
                                                const float* __restrict__ b1,
                                                int mbase) {
    extern __shared__ __align__(16) uint32_t sw[];
    uint32_t* sAhi = sw;
    uint32_t* sAlo = sw + SA1W;
    uint32_t* sBhi = sw + 2 * SA1W;
    uint32_t* sBlo = sw + 2 * SA1W + SBW;
    float* colS = (float*)(sw + 2 * SA1W + 2 * SBW);
    float* colQ = colS + 128;

    const int t = threadIdx.x;
    const int wid = t >> 5, lane = t & 31;
    const int gr = lane >> 2, qq = lane & 3;
    const int sel = lane >> 3, li = lane & 7;
    const int warp_m = wid >> 2, warp_n = wid & 3;
    const int n0 = blockIdx.x * 128;
    const int m0 = mbase + blockIdx.y * 128;
    const int half = (m0 >= B_ROWS);
    const float* H = half ? (h2 + (size_t)(m0 - B_ROWS) * D_INF)
                          : (h1 + (size_t)m0 * D_INF);

    if (t < 128) { colS[t] = 0.f; colQ[t] = 0.f; }

    float acc[4][4][4];
#pragma unroll
    for (int mi = 0; mi < 4; mi++)
#pragma unroll
        for (int ni = 0; ni < 4; ni++)
#pragma unroll
            for (int r = 0; r < 4; r++) acc[mi][ni][r] = 0.f;

    const int arow = t >> 1, acq = (t & 1) * 32;
    const int brow = t >> 1, bcq = (t & 1) * 32;
    const float* pAf = H + (size_t)arow * D_INF + acq;
    const __nv_bfloat16* pBh = g_W1h + (size_t)(n0 + brow) * D_INF + bcq;
    const __nv_bfloat16* pBl = g_W1l + (size_t)(n0 + brow) * D_INF + bcq;
    const int aw = arow * PW + (acq >> 1);
    const int bw = brow * PW + (bcq >> 1);

    const uint32_t sAhiU = smem_u32(sAhi), sAloU = smem_u32(sAlo);
    const uint32_t sBhiU = smem_u32(sBhi), sBloU = smem_u32(sBlo);
    uint32_t aoff[4], boff[2];
#pragma unroll
    for (int mi = 0; mi < 4; mi++)
        aoff[mi] = (uint32_t)(warp_m * 64 + mi * 16 + (sel & 1) * 8 + li) * 144u
                 + (uint32_t)(sel >> 1) * 16u;
#pragma unroll
    for (int nip = 0; nip < 2; nip++)
        boff[nip] = (uint32_t)(warp_n * 32 + nip * 16 + (sel >> 1) * 8 + li) * 144u
                  + (uint32_t)(sel & 1) * 16u;

    for (int kb = 0; kb < D_INF; kb += 64) {
        {
#pragma unroll
            for (int j = 0; j < 8; j++) {
                float4 v = *(const float4*)(pAf + kb + j * 4);
                uint32_t h0, l0, h1v, l1;
                split2(v.x, v.y, h0, l0);
                split2(v.z, v.w, h1v, l1);
                uint2 hh = {h0, h1v}, ll = {l0, l1};
                *(uint2*)(sAhi + aw + j * 2) = hh;
                *(uint2*)(sAlo + aw + j * 2) = ll;
            }
#pragma unroll
            for (int j = 0; j < 4; j++) {
                uint4 vh = *(const uint4*)(pBh + kb + j * 8);
                uint4 vl = *(const uint4*)(pBl + kb + j * 8);
                *(uint4*)(sBhi + bw + j * 4) = vh;
                *(uint4*)(sBlo + bw + j * 4) = vl;
            }
        }
        __syncthreads();
#pragma unroll
        for (int ks = 0; ks < 4; ks++) {
            uint32_t koff = (uint32_t)ks * 32u;
            uint32_t ah[4][4], al[4][4], bh[4][2], bl[4][2], tmp[4];
#pragma unroll
            for (int mi = 0; mi < 4; mi++) {
                ldsm4(ah[mi], sAhiU + aoff[mi] + koff);
                ldsm4(al[mi], sAloU + aoff[mi] + koff);
            }
            ldsm4(tmp, sBhiU + boff[0] + koff);
            bh[0][0]=tmp[0]; bh[0][1]=tmp[1]; bh[1][0]=tmp[2]; bh[1][1]=tmp[3];
            ldsm4(tmp, sBhiU + boff[1] + koff);
            bh[2][0]=tmp[0]; bh[2][1]=tmp[1]; bh[3][0]=tmp[2]; bh[3][1]=tmp[3];
            ldsm4(tmp, sBloU + boff[0] + koff);
            bl[0][0]=tmp[0]; bl[0][1]=tmp[1]; bl[1][0]=tmp[2]; bl[1][1]=tmp[3];
            ldsm4(tmp, sBloU + boff[1] + koff);
            bl[2][0]=tmp[0]; bl[2][1]=tmp[1]; bl[3][0]=tmp[2]; bl[3][1]=tmp[3];
#pragma unroll
            for (int mi = 0; mi < 4; mi++)
#pragma unroll
                for (int ni = 0; ni < 4; ni++) {
                    mma16816(acc[mi][ni], ah[mi], bh[ni]);
                    mma16816(acc[mi][ni], ah[mi], bl[ni]);
                    mma16816(acc[mi][ni], al[mi], bh[ni]);
                }
        }
        __syncthreads();
    }

    float ps[4][2], pq[4][2];
#pragma unroll
    for (int ni = 0; ni < 4; ni++) { ps[ni][0]=ps[ni][1]=pq[ni][0]=pq[ni][1]=0.f; }
#pragma unroll
    for (int ni = 0; ni < 4; ni++) {
        int col = warp_n * 32 + ni * 8 + qq * 2;
        float2 bb = *(const float2*)&b1[n0 + col];
#pragma unroll
        for (int mi = 0; mi < 4; mi++) {
            int r = warp_m * 64 + mi * 16 + gr;
            float y0 = acc[mi][ni][0] + bb.x;
            float y1 = acc[mi][ni][1] + bb.y;
            float y2 = acc[mi][ni][2] + bb.x;
            float y3 = acc[mi][ni][3] + bb.y;
            float2 p0 = {y0, y1}, p1 = {y2, y3};
            *(float2*)&g_Y[(size_t)(m0 + r)     * D_HID + n0 + col] = p0;
            *(float2*)&g_Y[(size_t)(m0 + r + 8) * D_HID + n0 + col] = p1;
            ps[ni][0] += y0 + y2;              ps[ni][1] += y1 + y3;
            pq[ni][0] += y0 * y0 + y2 * y2;    pq[ni][1] += y1 * y1 + y3 * y3;
        }
    }
#pragma unroll
    for (int ni = 0; ni < 4; ni++)
#pragma unroll
        for (int c2 = 0; c2 < 2; c2++) {
            float s = ps[ni][c2], q = pq[ni][c2];
            s += __shfl_xor_sync(~0u, s, 4);  q += __shfl_xor_sync(~0u, q, 4);
            s += __shfl_xor_sync(~0u, s, 8);  q += __shfl_xor_sync(~0u, q, 8);
            s += __shfl_xor_sync(~0u, s, 16); q += __shfl_xor_sync(~0u, q, 16);
            ps[ni][c2] = s; pq[ni][c2] = q;
        }
    if (gr == 0) {
#pragma unroll
        for (int ni = 0; ni < 4; ni++) {
            int col = warp_n * 32 + ni * 8 + qq * 2;
            atomicAdd(&colS[col],     ps[ni][0]);
            atomicAdd(&colS[col + 1], ps[ni][1]);
            atomicAdd(&colQ[col],     pq[ni][0]);
            atomicAdd(&colQ[col + 1], pq[ni][1]);
        }
    }
    __syncthreads();
    if (t < 128) {
        atomicAdd(&g_colsum[half][n0 + t], colS[t]);
        atomicAdd(&g_colsq [half][n0 + t], colQ[t]);
    }
}

// ---------------- GEMM2 (tensor, split-bf16): Z = relu(BN(Y)) @ W2^T + b2 ----
// Per-half launch: grid 64, mbase selects half. BM=64, BN=128, prefetched.
__global__ __launch_bounds__(256) void k_gemm2t(const float* __restrict__ b2,
                                                const float* __restrict__ gamma,
                                                const float* __restrict__ beta,
                                                float* __restrict__ out,
                                                int out_size, int mbase) {
    extern __shared__ __align__(16) uint32_t sw[];
    uint32_t* sAhi = sw;
    uint32_t* sAlo = sw + SAW;
    uint32_t* sBhi = sw + 2 * SAW;
    uint32_t* sBlo = sw + 2 * SAW + SBW;
    float* ssc  = (float*)(sw + 2 * SAW + 2 * SBW);
    float* ssh  = ssc + D_HID;
    float* red  = ssh + D_HID;
    float* sInv = red + 256;

    const int t = threadIdx.x;
    const int wid = t >> 5, lane = t & 31;
    const int gr = lane >> 2, qq = lane & 3;
    const int sel = lane >> 3, li = lane & 7;
    const int warp_m = wid >> 2, warp_n = wid & 3;
    const int m0 = mbase + blockIdx.x * 64;
    const int half = (m0 >= B_ROWS);

    for (int c = t; c < D_HID; c += 256) {
        float mean = g_colsum[half][c] * (1.f / B_ROWS);
        float var  = g_colsq [half][c] * (1.f / B_ROWS) - mean * mean;
        float scv  = gamma[c] * rsqrtf(var + BN_EPS);
        ssc[c] = scv;
        ssh[c] = beta[c] - mean * scv;
    }
    __syncthreads();

    float acc[2][4][4];
#pragma unroll
    for (int mi = 0; mi < 2; mi++)
#pragma unroll
        for (int ni = 0; ni < 4; ni++)
#pragma unroll
            for (int r = 0; r < 4; r++) acc[mi][ni][r] = 0.f;

    const int arow = t >> 2, acq = (t & 3) * 16;
    const int brow = t >> 1, bcq = (t & 1) * 32;
    const float* pA = g_Y + (size_t)(m0 + arow) * D_HID + acq;
    const __nv_bfloat16* pBh = g_W2h + (size_t)brow * D_HID + bcq;
    const __nv_bfloat16* pBl = g_W2l + (size_t)brow * D_HID + bcq;
    const int aw = arow * PW + (acq >> 1);
    const int bw = brow * PW + (bcq >> 1);

    const uint32_t sAhiU = smem_u32(sAhi), sAloU = smem_u32(sAlo);
    const uint32_t sBhiU = smem_u32(sBhi), sBloU = smem_u32(sBlo);
    uint32_t aoff[2], boff[2];
#pragma unroll
    for (int mi = 0; mi < 2; mi++)
        aoff[mi] = (uint32_t)(warp_m * 32 + mi * 16 + (sel & 1) * 8 + li) * 144u
                 + (uint32_t)(sel >> 1) * 16u;
#pragma unroll
    for (int nip = 0; nip < 2; nip++)
        boff[nip] = (uint32_t)(warp_n * 32 + nip * 16 + (sel >> 1) * 8 + li) * 144u
                  + (uint32_t)(sel & 1) * 16u;

    float4 rA[4];
    uint4 rBh[4], rBl[4];
#pragma unroll
    for (int j = 0; j < 4; j++) {
        rA[j]  = *(const float4*)(pA + j * 4);
        rBh[j] = *(const uint4*)(pBh + j * 8);
        rBl[j] = *(const uint4*)(pBl + j * 8);
    }

    for (int it = 0; it < 8; it++) {
        const int kb = it * 64;
        {
#pragma unroll
            for (int j = 0; j < 4; j++) {
                int k = kb + acq + j * 4;
                float f0 = fmaxf(fmaf(rA[j].x, ssc[k],     ssh[k]),     0.f);
                float f1 = fmaxf(fmaf(rA[j].y, ssc[k + 1], ssh[k + 1]), 0.f);
                float f2 = fmaxf(fmaf(rA[j].z, ssc[k + 2], ssh[k + 2]), 0.f);
                float f3 = fmaxf(fmaf(rA[j].w, ssc[k + 3], ssh[k + 3]), 0.f);
                uint32_t h0, l0, h1v, l1;
                split2(f0, f1, h0, l0);
                split2(f2, f3, h1v, l1);
                uint2 hh = {h0, h1v}, ll = {l0, l1};
                *(uint2*)(sAhi + aw + j * 2) = hh;
                *(uint2*)(sAlo + aw + j * 2) = ll;
                *(uint4*)(sBhi + bw + j * 4) = rBh[j];
                *(uint4*)(sBlo + bw + j * 4) = rBl[j];
            }
        }
        __syncthreads();
        if (it < 7) {
            int kn = kb + 64;
#pragma unroll
            for (int j = 0; j < 4; j++) {
                rA[j]  = *(const float4*)(pA + kn + j * 4);
                rBh[j] = *(const uint4*)(pBh + kn + j * 8);
                rBl[j] = *(const uint4*)(pBl + kn + j * 8);
            }
        }
#pragma unroll
        for (int ks = 0; ks < 4; ks++) {
            uint32_t koff = (uint32_t)ks * 32u;
            uint32_t ah[2][4], al[2][4], bh[4][2], bl[4][2], tmp[4];
            ldsm4(ah[0], sAhiU + aoff[0] + koff);
            ldsm4(ah[1], sAhiU + aoff[1] + koff);
            ldsm4(al[0], sAloU + aoff[0] + koff);
            ldsm4(al[1], sAloU + aoff[1] + koff);
            ldsm4(tmp, sBhiU + boff[0] + koff);
            bh[0][0]=tmp[0]; bh[0][1]=tmp[1]; bh[1][0]=tmp[2]; bh[1][1]=tmp[3];
            ldsm4(tmp, sBhiU + boff[1] + koff);
            bh[2][0]=tmp[0]; bh[2][1]=tmp[1]; bh[3][0]=tmp[2]; bh[3][1]=tmp[3];
            ldsm4(tmp, sBloU + boff[0] + koff);
            bl[0][0]=tmp[0]; bl[0][1]=tmp[1]; bl[1][0]=tmp[2]; bl[1][1]=tmp[3];
            ldsm4(tmp, sBloU + boff[1] + koff);
            bl[2][0]=tmp[0]; bl[2][1]=tmp[1]; bl[3][0]=tmp[2]; bl[3][1]=tmp[3];
#pragma unroll
            for (int mi = 0; mi < 2; mi++)
#pragma unroll
                for (int ni = 0; ni < 4; ni++) {
                    mma16816(acc[mi][ni], ah[mi], bh[ni]);
                    mma16816(acc[mi][ni], ah[mi], bl[ni]);
                    mma16816(acc[mi][ni], al[mi], bh[ni]);
                }
        }
        __syncthreads();
    }

    float rp[2][2] = {{0.f, 0.f}, {0.f, 0.f}};
#pragma unroll
    for (int ni = 0; ni < 4; ni++) {
        int col = warp_n * 32 + ni * 8 + qq * 2;
        float2 bb = *(const float2*)&b2[col];
#pragma unroll
        for (int mi = 0; mi < 2; mi++) {
            acc[mi][ni][0] += bb.x; acc[mi][ni][1] += bb.y;
            acc[mi][ni][2] += bb.x; acc[mi][ni][3] += bb.y;
            rp[mi][0] = fmaf(acc[mi][ni][0], acc[mi][ni][0],
                        fmaf(acc[mi][ni][1], acc[mi][ni][1], rp[mi][0]));
            rp[mi][1] = fmaf(acc[mi][ni][2], acc[mi][ni][2],
                        fmaf(acc[mi][ni][3], acc[mi][ni][3], rp[mi][1]));
        }
    }
#pragma unroll
    for (int mi = 0; mi < 2; mi++)
#pragma unroll
        for (int rh = 0; rh < 2; rh++) {
            float s = rp[mi][rh];
            s += __shfl_xor_sync(~0u, s, 1);
            s += __shfl_xor_sync(~0u, s, 2);
            rp[mi][rh] = s;
        }
    if (qq == 0) {
#pragma unroll
        for (int mi = 0; mi < 2; mi++) {
            red[(warp_m * 32 + mi * 16 + gr)     * 4 + warp_n] = rp[mi][0];
            red[(warp_m * 32 + mi * 16 + gr + 8) * 4 + warp_n] = rp[mi][1];
        }
    }
    __syncthreads();
    if (t < 64) {
        float s = red[t * 4] + red[t * 4 + 1] + red[t * 4 + 2] + red[t * 4 + 3];
        sInv[t] = 1.f / fmaxf(sqrtf(s), L2_EPS);
    }
    __syncthreads();
    bool full = (out_size > M2 * D_OUTF);
#pragma unroll
    for (int mi = 0; mi < 2; mi++)
#pragma unroll
        for (int rh = 0; rh < 2; rh++) {
            int r = warp_m * 32 + mi * 16 + gr + rh * 8;
            float inv = sInv[r];
            int m = m0 + r;
#pragma unroll
            for (int ni = 0; ni < 4; ni++) {
                int col = warp_n * 32 + ni * 8 + qq * 2;
                float z0 = acc[mi][ni][rh * 2]     * inv;
                float z1 = acc[mi][ni][rh * 2 + 1] * inv;
                if (full) {
                    out[1 + (size_t)m * D_OUTF + col]     = z0;
                    out[1 + (size_t)m * D_OUTF + col + 1] = z1;
                } else {
                    float2 zz = {z0, z1};
                    *(float2*)&g_Z[(size_t)m * D_OUTF + col] = zz;
                }
                *(__nv_bfloat162*)&g_Zh[(size_t)m * D_OUTF + col] =
                    __floats2bfloat162_rn(z0 * ZH_SCALE, z1 * ZH_SCALE);
            }
        }
}

// ---------------- tensor-core sim: 128x128 tile, 3 CTAs/SM -------------------
#define SIM_PITCH_B 272
#define SIM_TILE_BYTES (128 * SIM_PITCH_B)
#define SIM_SMEM_SIZE (2 * SIM_TILE_BYTES + 2 * 128 * 4)

__device__ __forceinline__ int tri_off(int r) { return r * 64 - ((r * (r - 1)) >> 1); }

__global__ __launch_bounds__(256, 3) void k_sims() {
    extern __shared__ __align__(16) char smem[];
    char* sA = smem;
    char* sB = smem + SIM_TILE_BYTES;
    float* srow = (float*)(smem + 2 * SIM_TILE_BYTES);
    float* scol = srow + 128;

    const int t = threadIdx.x;
    const int wid = t >> 5, lane = t & 31;
    const int gr = lane >> 2, qq = lane & 3;
    const int sel = lane >> 3, li = lane & 7;
    const int warp_m2 = wid >> 2;
    const int warp_n  = wid & 3;

    int tb = blockIdx.x;
    int bi = (int)(64.5f - sqrtf(64.5f * 64.5f - 2.0f * (float)tb));
    if (bi < 0) bi = 0; if (bi > 63) bi = 63;
    while (tri_off(bi + 1) <= tb) ++bi;
    while (tri_off(bi) > tb) --bi;
    int bj = bi + (tb - tri_off(bi));
    const size_t i0 = (size_t)bi * 128;
    const size_t j0 = (size_t)bj * 128;
    const bool offdiag = (bi != bj);

    const uint32_t sAu = smem_u32(sA);
    const uint32_t sBu = smem_u32(sB);
    const char* gA = (const char*)(g_Zh + i0 * D_OUTF);
    const char* gB = (const char*)(g_Zh + j0 * D_OUTF);
#pragma unroll
    for (int it = 0; it < 8; it++) {
        int q = t + it * 256;
        uint32_t so = (uint32_t)(q >> 4) * SIM_PITCH_B + (uint32_t)(q & 15) * 16u;
        cpa16(sAu + so, gA + q * 16);
        cpa16(sBu + so, gB + q * 16);
    }
    if (t < 128) { srow[t] = 0.f; scol[t] = 0.f; }
    cpa_wait_all();
    __syncthreads();

    uint32_t boff[2];
#pragma unroll
    for (int nip = 0; nip < 2; nip++)
        boff[nip] = sBu + (uint32_t)(warp_n * 32 + nip * 16 + (sel >> 1) * 8 + li) * SIM_PITCH_B
                  + (uint32_t)(sel & 1) * 16u;

    float csum[8];
#pragma unroll
    for (int i = 0; i < 8; i++) csum[i] = 0.f;

#pragma unroll
    for (int pass = 0; pass < 2; pass++) {
        const int rbase = pass * 64 + warp_m2 * 32;
        uint32_t aoff[2];
#pragma unroll
        for (int mi = 0; mi < 2; mi++)
            aoff[mi] = sAu + (uint32_t)(rbase + mi * 16 + (sel & 1) * 8 + li) * SIM_PITCH_B
                     + (uint32_t)(sel >> 1) * 16u;

        float cc[2][4][4];
#pragma unroll
        for (int mi = 0; mi < 2; mi++)
#pragma unroll
            for (int ni = 0; ni < 4; ni++)
#pragma unroll
                for (int r = 0; r < 4; r++) cc[mi][ni][r] = 0.f;

#pragma unroll
        for (int ks = 0; ks < 8; ks++) {
            uint32_t koff = (uint32_t)ks * 32u;
            uint32_t a[2][4], b[4][2], tmp[4];
            ldsm4(a[0], aoff[0] + koff);
            ldsm4(a[1], aoff[1] + koff);
            ldsm4(tmp, boff[0] + koff);
            b[0][0]=tmp[0]; b[0][1]=tmp[1]; b[1][0]=tmp[2]; b[1][1]=tmp[3];
            ldsm4(tmp, boff[1] + koff);
            b[2][0]=tmp[0]; b[2][1]=tmp[1]; b[3][0]=tmp[2]; b[3][1]=tmp[3];
#pragma unroll
            for (int mi = 0; mi < 2; mi++)
#pragma unroll
                for (int ni = 0; ni < 4; ni++)
                    mma16816(cc[mi][ni], a[mi], b[ni]);
        }

        float rsum[4];
#pragma unroll
        for (int i = 0; i < 4; i++) rsum[i] = 0.f;
#pragma unroll
        for (int mi = 0; mi < 2; mi++)
#pragma unroll
            for (int ni = 0; ni < 4; ni++) {
                float e0 = ex2(cc[mi][ni][0]);
                float e1 = ex2(cc[mi][ni][1]);
                float e2 = ex2(cc[mi][ni][2]);
                float e3 = ex2(cc[mi][ni][3]);
                rsum[mi * 2 + 0] += e0 + e1;
                rsum[mi * 2 + 1] += e2 + e3;
                csum[ni * 2 + 0] += e0 + e2;
                csum[ni * 2 + 1] += e1 + e3;
            }
#pragma unroll
        for (int i = 0; i < 4; i++) {
            rsum[i] += __shfl_xor_sync(0xffffffffu, rsum[i], 1);
            rsum[i] += __shfl_xor_sync(0xffffffffu, rsum[i], 2);
        }
        if (qq == 0) {
#pragma unroll
            for (int mi = 0; mi < 2; mi++) {
                atomicAdd(&srow[rbase + mi * 16 + gr],     rsum[mi * 2 + 0]);
                atomicAdd(&srow[rbase + mi * 16 + gr + 8], rsum[mi * 2 + 1]);
            }
        }
    }

    if (offdiag) {
#pragma unroll
        for (int i = 0; i < 8; i++) {
            csum[i] += __shfl_xor_sync(0xffffffffu, csum[i], 4);
            csum[i] += __shfl_xor_sync(0xffffffffu, csum[i], 8);
            csum[i] += __shfl_xor_sync(0xffffffffu, csum[i], 16);
        }
        if (gr == 0) {
#pragma unroll
            for (int ni = 0; ni < 4; ni++) {
                atomicAdd(&scol[warp_n * 32 + ni * 8 + qq * 2],     csum[ni * 2 + 0]);
                atomicAdd(&scol[warp_n * 32 + ni * 8 + qq * 2 + 1], csum[ni * 2 + 1]);
            }
        }
    }
    __syncthreads();
    if (t < 128) {
        atomicAdd(&g_sumexp[i0 + t], srow[t]);
        if (offdiag) atomicAdd(&g_sumexp[j0 + t], scol[t]);
    }
}

// ---------------- finish: loss = mean(lse_i - pos_i); emits out[0] ----------
__global__ void k_finish(float* __restrict__ out, int out_size) {
    int w    = (blockIdx.x * blockDim.x + threadIdx.x) >> 5;
    int lane = threadIdx.x & 31;
    if (w >= B_ROWS) return;
    bool full = (out_size > M2 * D_OUTF);
    const float* zsrc = full ? (out + 1) : g_Z;
    const float* p1 = zsrc + (size_t)w * D_OUTF + lane * 4;
    const float* p2 = zsrc + (size_t)(w + B_ROWS) * D_OUTF + lane * 4;
    float dp = 0.f;
#pragma unroll
    for (int j = 0; j < 4; j++) dp = fmaf(p1[j], p2[j], dp);
    const __nv_bfloat16* z1 = g_Zh + (size_t)w * D_OUTF + lane * 4;
    const __nv_bfloat16* z2 = g_Zh + (size_t)(w + B_ROWS) * D_OUTF + lane * 4;
    float d1 = 0.f, d2 = 0.f;
#pragma unroll
    for (int j = 0; j < 4; j++) {
        float v1 = __bfloat162float(z1[j]);
        float v2 = __bfloat162float(z2[j]);
        d1 = fmaf(v1, v1, d1);
        d2 = fmaf(v2, v2, d2);
    }
#pragma unroll
    for (int o = 16; o; o >>= 1) {
        dp += __shfl_down_sync(0xffffffffu, dp, o);
        d1 += __shfl_down_sync(0xffffffffu, d1, o);
        d2 += __shfl_down_sync(0xffffffffu, d2, o);
    }
    if (lane == 0) {
        float pos  = dp * INV_T;
        float lse1 = logf(g_sumexp[w]          - ex2(d1));
        float lse2 = logf(g_sumexp[w + B_ROWS] - ex2(d2));
        atomicAdd(&g_loss[0], (lse1 + lse2 - 2.f * pos) * (1.f / M2));
        __threadfence();
        unsigned prev = atomicAdd(&g_done, 1u);
        if (prev == B_ROWS - 1) {
            if (out_size > 0) out[0] = g_loss[0];
            g_done = 0u;   // reset for next graph replay
        }
    }
}

// ---------------- side stream + events (created at load, before checkpoints) -
struct SideStream {
    cudaStream_t s = nullptr;
    cudaEvent_t  eP = nullptr, eB = nullptr;
    SideStream() {
        cudaStreamCreateWithFlags(&s, cudaStreamNonBlocking);
        cudaEventCreateWithFlags(&eP, cudaEventDisableTiming);
        cudaEventCreateWithFlags(&eB, cudaEventDisableTiming);
    }
};
static SideStream g_ss;

// ---------------- launch -----------------------------------------------------
extern "C" void kernel_launch(void* const* d_in, const int* in_sizes, int n_in,
                              void* d_out, int out_size) {
    const float* h1    = (const float*)d_in[0];
    const float* h2    = (const float*)d_in[1];
    const float* W1    = (const float*)d_in[2];
    const float* b1    = (const float*)d_in[3];
    const float* gamma = (const float*)d_in[4];
    const float* beta  = (const float*)d_in[5];
    const float* W2    = (const float*)d_in[6];
    const float* b2    = (const float*)d_in[7];
    float* out = (float*)d_out;

    cudaFuncSetAttribute(k_gemm1t, cudaFuncAttributeMaxDynamicSharedMemorySize, GSM1_BYTES);
    cudaFuncSetAttribute(k_gemm2t, cudaFuncAttributeMaxDynamicSharedMemorySize, GSM2_BYTES);
    cudaFuncSetAttribute(k_sims,   cudaFuncAttributeMaxDynamicSharedMemorySize, SIM_SMEM_SIZE);

    cudaStream_t s0 = 0, s1 = g_ss.s;

    k_prep <<<160, 256, 0, s0>>>(W1, W2);
    cudaEventRecord(g_ss.eP, s0);
    cudaStreamWaitEvent(s1, g_ss.eP, 0);

    // half 0 on s0, half 1 on s1 (BN stats + Y rows are per-half independent)
    k_gemm1t <<<dim3(4, 32), 256, GSM1_BYTES, s0>>>(h1, h2, b1, 0);
    k_gemm1t <<<dim3(4, 32), 256, GSM1_BYTES, s1>>>(h1, h2, b1, B_ROWS);
    k_gemm2t <<<64, 256, GSM2_BYTES, s0>>>(b2, gamma, beta, out, out_size, 0);
    k_gemm2t <<<64, 256, GSM2_BYTES, s1>>>(b2, gamma, beta, out, out_size, B_ROWS);
    cudaEventRecord(g_ss.eB, s1);
    cudaStreamWaitEvent(s0, g_ss.eB, 0);

    k_sims   <<<2080, 256, SIM_SMEM_SIZE, s0>>>();
    k_finish <<<512, 256, 0, s0>>>(out, out_size);
}